// round 1
// baseline (speedup 1.0000x reference)
#include <cuda_runtime.h>
#include <math.h>
#include <stdint.h>

#define EMB   1024
#define HEADS 16
#define HSZ   64
#define BATCH 4
#define SEQ   2048
#define MTOK  (BATCH * SEQ)   // 8192 token rows

// scratch: k, q, v, y (attention output) — 4 x 32MB fp32
__device__ float g_scratch[4ull * MTOK * EMB];

// ---------------------------------------------------------------------------
// SGEMM: C[M,N] = A[M,K] * B[N,K]^T (+ bias[N]), all row-major fp32.
// 128x128 block tile, BK=8, 8x8 per-thread micro-tile, 256 threads.
// ---------------------------------------------------------------------------
__global__ __launch_bounds__(256, 2)
void sgemm_nt(const float* __restrict__ A, const float* __restrict__ B,
              const float* __restrict__ bias, float* __restrict__ C,
              int M, int N, int K)
{
    __shared__ float As[8][128];
    __shared__ float Bs[8][128];

    const int tid  = threadIdx.x;
    const int bm   = blockIdx.y * 128;
    const int bn   = blockIdx.x * 128;
    const int lrow = tid >> 1;          // 0..127
    const int lcol = (tid & 1) * 4;     // 0 or 4
    const int tr   = (tid >> 4) * 8;    // 0..120
    const int tc   = (tid & 15) * 8;    // 0..120

    const float* Ap = A + (size_t)(bm + lrow) * K + lcol;
    const float* Bp = B + (size_t)(bn + lrow) * K + lcol;

    float acc[8][8];
    #pragma unroll
    for (int i = 0; i < 8; i++)
        #pragma unroll
        for (int j = 0; j < 8; j++) acc[i][j] = 0.0f;

    for (int k0 = 0; k0 < K; k0 += 8) {
        float4 av = *(const float4*)(Ap + k0);
        float4 bv = *(const float4*)(Bp + k0);
        As[lcol + 0][lrow] = av.x;
        As[lcol + 1][lrow] = av.y;
        As[lcol + 2][lrow] = av.z;
        As[lcol + 3][lrow] = av.w;
        Bs[lcol + 0][lrow] = bv.x;
        Bs[lcol + 1][lrow] = bv.y;
        Bs[lcol + 2][lrow] = bv.z;
        Bs[lcol + 3][lrow] = bv.w;
        __syncthreads();

        #pragma unroll
        for (int kk = 0; kk < 8; kk++) {
            float ar[8], br[8];
            *(float4*)&ar[0] = *(const float4*)&As[kk][tr];
            *(float4*)&ar[4] = *(const float4*)&As[kk][tr + 4];
            *(float4*)&br[0] = *(const float4*)&Bs[kk][tc];
            *(float4*)&br[4] = *(const float4*)&Bs[kk][tc + 4];
            #pragma unroll
            for (int i = 0; i < 8; i++)
                #pragma unroll
                for (int j = 0; j < 8; j++)
                    acc[i][j] += ar[i] * br[j];
        }
        __syncthreads();
    }

    float bb[8];
    #pragma unroll
    for (int j = 0; j < 8; j++) bb[j] = bias ? bias[bn + tc + j] : 0.0f;

    #pragma unroll
    for (int i = 0; i < 8; i++) {
        float4 o0, o1;
        o0.x = acc[i][0] + bb[0]; o0.y = acc[i][1] + bb[1];
        o0.z = acc[i][2] + bb[2]; o0.w = acc[i][3] + bb[3];
        o1.x = acc[i][4] + bb[4]; o1.y = acc[i][5] + bb[5];
        o1.z = acc[i][6] + bb[6]; o1.w = acc[i][7] + bb[7];
        float* crow = C + (size_t)(bm + tr + i) * N + bn + tc;
        *(float4*)(crow)     = o0;
        *(float4*)(crow + 4) = o1;
    }
}

// ---------------------------------------------------------------------------
// Per-head LayerNorm (+ fold in E^-0.25 scale). One warp per 64-elem segment.
// X layout: [MTOK, EMB] where segment = (row*HEADS + h), contiguous 64 floats.
// ---------------------------------------------------------------------------
__global__ __launch_bounds__(256)
void ln_head(float* __restrict__ X, const float* __restrict__ g,
             const float* __restrict__ b, float scale)
{
    const int seg  = blockIdx.x * 8 + (threadIdx.x >> 5);
    const int lane = threadIdx.x & 31;
    float2* p = (float2*)(X + (size_t)seg * HSZ) + lane;
    float2 v = *p;
    float sum = v.x + v.y;
    float sq  = v.x * v.x + v.y * v.y;
    #pragma unroll
    for (int o = 16; o; o >>= 1) {
        sum += __shfl_xor_sync(0xffffffffu, sum, o);
        sq  += __shfl_xor_sync(0xffffffffu, sq,  o);
    }
    const float mean = sum * (1.0f / 64.0f);
    const float var  = sq * (1.0f / 64.0f) - mean * mean;
    const float r    = rsqrtf(var + 1e-5f);
    const float gx = g[2 * lane], gy = g[2 * lane + 1];
    const float bx = b[2 * lane], by = b[2 * lane + 1];
    v.x = ((v.x - mean) * r * gx + bx) * scale;
    v.y = ((v.y - mean) * r * gy + by) * scale;
    *p = v;
}

// ---------------------------------------------------------------------------
// Causal flash attention, fp32. One thread per query row (BR=128 rows/block),
// K/V tiles (BC=64 x D=64) in SMEM read via warp-broadcast LDS.128.
// Online softmax with lazy rescale (rescale only when the max updates).
// ---------------------------------------------------------------------------
#define BR 128
#define BC 64

__global__ __launch_bounds__(BR)
void flash_attn(const float* __restrict__ Q, const float* __restrict__ K,
                const float* __restrict__ V, float* __restrict__ O)
{
    const int qt = blockIdx.x;   // query tile 0..15
    const int h  = blockIdx.y;   // head
    const int b  = blockIdx.z;   // batch
    const int row = qt * BR + threadIdx.x;

    __shared__ float4 Ks[BC * 16];
    __shared__ float4 Vs[BC * 16];

    const size_t base = (size_t)b * SEQ * EMB + (size_t)h * HSZ;

    float4 qv[16];
    const float4* qp = (const float4*)(Q + base + (size_t)row * EMB);
    #pragma unroll
    for (int i = 0; i < 16; i++) qv[i] = qp[i];

    float4 acc[16];
    #pragma unroll
    for (int i = 0; i < 16; i++) acc[i] = make_float4(0.f, 0.f, 0.f, 0.f);
    float m = -INFINITY, l = 0.0f;

    const int ntiles = (qt + 1) * (BR / BC);   // keys up to end of this q-tile
    const float4* kbase = (const float4*)(K + base);
    const float4* vbase = (const float4*)(V + base);

    for (int t0 = 0; t0 < ntiles; t0++) {
        const int k0 = t0 * BC;
        // cooperative tile load: 64 rows x 16 float4, coalesced per row
        for (int i = threadIdx.x; i < BC * 16; i += BR) {
            const int r = i >> 4, c = i & 15;
            const size_t gidx = (size_t)(k0 + r) * (EMB / 4) + c;
            Ks[i] = kbase[gidx];
            Vs[i] = vbase[gidx];
        }
        __syncthreads();

        const int jmax = min(BC, row - k0 + 1);  // causal bound for this row
        for (int j = 0; j < jmax; j++) {
            // score = q . k[j]   (Ks reads are warp-uniform -> broadcast)
            float s0 = 0.f, s1 = 0.f, s2 = 0.f, s3 = 0.f;
            #pragma unroll
            for (int i = 0; i < 16; i++) {
                float4 kk = Ks[j * 16 + i];
                s0 += qv[i].x * kk.x;
                s1 += qv[i].y * kk.y;
                s2 += qv[i].z * kk.z;
                s3 += qv[i].w * kk.w;
            }
            const float s = (s0 + s1) + (s2 + s3);

            float p;
            if (s <= m) {
                p = __expf(s - m);
            } else {
                const float corr = __expf(m - s);  // 0 when m == -inf
                l *= corr;
                #pragma unroll
                for (int i = 0; i < 16; i++) {
                    acc[i].x *= corr; acc[i].y *= corr;
                    acc[i].z *= corr; acc[i].w *= corr;
                }
                m = s;
                p = 1.0f;
            }
            l += p;
            #pragma unroll
            for (int i = 0; i < 16; i++) {
                float4 vvv = Vs[j * 16 + i];
                acc[i].x += p * vvv.x;
                acc[i].y += p * vvv.y;
                acc[i].z += p * vvv.z;
                acc[i].w += p * vvv.w;
            }
        }
        __syncthreads();
    }

    const float inv = 1.0f / l;
    float4* op = (float4*)(O + base + (size_t)row * EMB);
    #pragma unroll
    for (int i = 0; i < 16; i++) {
        float4 o;
        o.x = acc[i].x * inv; o.y = acc[i].y * inv;
        o.z = acc[i].z * inv; o.w = acc[i].w * inv;
        op[i] = o;
    }
}

// ---------------------------------------------------------------------------
extern "C" void kernel_launch(void* const* d_in, const int* in_sizes, int n_in,
                              void* d_out, int out_size)
{
    const float* x   = (const float*)d_in[0];
    const float* Wk  = (const float*)d_in[1];
    const float* Wq  = (const float*)d_in[2];
    const float* Wv  = (const float*)d_in[3];
    const float* Wo  = (const float*)d_in[4];
    const float* bo  = (const float*)d_in[5];
    const float* kg  = (const float*)d_in[6];
    const float* kb  = (const float*)d_in[7];
    const float* qg  = (const float*)d_in[8];
    const float* qb  = (const float*)d_in[9];
    float* out = (float*)d_out;

    float* sbase = nullptr;
    cudaGetSymbolAddress((void**)&sbase, g_scratch);
    float* gk = sbase;
    float* gq = sbase + 1ull * MTOK * EMB;
    float* gv = sbase + 2ull * MTOK * EMB;
    float* gy = sbase + 3ull * MTOK * EMB;

    const float SCALE = 0.17677669529663687f;  // 1024^(-1/4)

    dim3 gemmGrid(EMB / 128, MTOK / 128);      // (8, 64)
    sgemm_nt<<<gemmGrid, 256>>>(x, Wk, nullptr, gk, MTOK, EMB, EMB);
    sgemm_nt<<<gemmGrid, 256>>>(x, Wq, nullptr, gq, MTOK, EMB, EMB);
    sgemm_nt<<<gemmGrid, 256>>>(x, Wv, nullptr, gv, MTOK, EMB, EMB);

    const int nseg = MTOK * HEADS;             // 131072
    ln_head<<<nseg / 8, 256>>>(gk, kg, kb, SCALE);
    ln_head<<<nseg / 8, 256>>>(gq, qg, qb, SCALE);

    dim3 attnGrid(SEQ / BR, HEADS, BATCH);     // (16, 16, 4)
    flash_attn<<<attnGrid, BR>>>(gq, gk, gv, gy);

    sgemm_nt<<<gemmGrid, 256>>>(gy, Wo, bo, out, MTOK, EMB, EMB);
}

// round 2
// speedup vs baseline: 1.4804x; 1.4804x over previous
#include <cuda_runtime.h>
#include <math.h>
#include <stdint.h>

#define EMB   1024
#define HEADS 16
#define HSZ   64
#define BATCH 4
#define SEQ   2048
#define MTOK  (BATCH * SEQ)   // 8192 token rows

// scratch: k, q, v, y (attention output) — 4 x 32MB fp32
__device__ float g_scratch[4ull * MTOK * EMB];

// ---------------------------------------------------------------------------
// TF32 tensor-core GEMM: C[M,N] = A[M,K] * B[N,K]^T (+ bias[N]), fp32 in/out.
// 128x128 block tile, BK=16, 8 warps (2x4), warp tile 64x32, m16n8k8 TF32 mma.
// Double-buffered SMEM (stride 20 floats -> conflict-free fragment reads).
// ---------------------------------------------------------------------------
#define BK     16
#define SSTR   20      // smem row stride in floats (padding kills conflicts)
#define TILESZ (128 * SSTR)

__device__ __forceinline__ float f2tf32(float x) {
    uint32_t r;
    asm("cvt.rna.tf32.f32 %0, %1;" : "=r"(r) : "f"(x));
    return __uint_as_float(r);
}

__device__ __forceinline__ void mma_tf32(float* c, const uint32_t* a, const uint32_t* b) {
    asm volatile(
        "mma.sync.aligned.m16n8k8.row.col.f32.tf32.tf32.f32 "
        "{%0,%1,%2,%3}, {%4,%5,%6,%7}, {%8,%9}, {%0,%1,%2,%3};\n"
        : "+f"(c[0]), "+f"(c[1]), "+f"(c[2]), "+f"(c[3])
        : "r"(a[0]), "r"(a[1]), "r"(a[2]), "r"(a[3]), "r"(b[0]), "r"(b[1]));
}

__global__ __launch_bounds__(256, 2)
void gemm_tf32_nt(const float* __restrict__ A, const float* __restrict__ B,
                  const float* __restrict__ bias, float* __restrict__ C,
                  int M, int N, int K)
{
    __shared__ float As[2][TILESZ];
    __shared__ float Bs[2][TILESZ];

    const int tid  = threadIdx.x;
    const int bm   = blockIdx.y * 128;
    const int bn   = blockIdx.x * 128;
    const int lane = tid & 31;
    const int wid  = tid >> 5;
    const int wm   = (wid >> 2) * 64;   // warp M offset: 0 or 64
    const int wn   = (wid & 3) * 32;    // warp N offset: 0,32,64,96

    // global load assignment: each thread loads 8 floats (2 x float4) per tile
    const int grow  = tid >> 1;          // 0..127
    const int gcol  = (tid & 1) * 8;     // 0 or 8
    const float* Ap = A + (size_t)(bm + grow) * K + gcol;
    const float* Bp = B + (size_t)(bn + grow) * K + gcol;
    const int soff  = grow * SSTR + gcol;

    float acc[4][4][4];
    #pragma unroll
    for (int i = 0; i < 4; i++)
        #pragma unroll
        for (int j = 0; j < 4; j++)
            #pragma unroll
            for (int r = 0; r < 4; r++) acc[i][j][r] = 0.0f;

    // preload tile 0
    {
        float4 a0 = *(const float4*)(Ap);
        float4 a1 = *(const float4*)(Ap + 4);
        float4 b0 = *(const float4*)(Bp);
        float4 b1 = *(const float4*)(Bp + 4);
        As[0][soff + 0] = f2tf32(a0.x); As[0][soff + 1] = f2tf32(a0.y);
        As[0][soff + 2] = f2tf32(a0.z); As[0][soff + 3] = f2tf32(a0.w);
        As[0][soff + 4] = f2tf32(a1.x); As[0][soff + 5] = f2tf32(a1.y);
        As[0][soff + 6] = f2tf32(a1.z); As[0][soff + 7] = f2tf32(a1.w);
        Bs[0][soff + 0] = f2tf32(b0.x); Bs[0][soff + 1] = f2tf32(b0.y);
        Bs[0][soff + 2] = f2tf32(b0.z); Bs[0][soff + 3] = f2tf32(b0.w);
        Bs[0][soff + 4] = f2tf32(b1.x); Bs[0][soff + 5] = f2tf32(b1.y);
        Bs[0][soff + 6] = f2tf32(b1.z); Bs[0][soff + 7] = f2tf32(b1.w);
    }
    __syncthreads();

    const int niter = K / BK;
    int buf = 0;

    for (int it = 0; it < niter; it++) {
        float4 pa0, pa1, pb0, pb1;
        const bool has_next = (it + 1) < niter;
        if (has_next) {
            const int ko = (it + 1) * BK;
            pa0 = *(const float4*)(Ap + ko);
            pa1 = *(const float4*)(Ap + ko + 4);
            pb0 = *(const float4*)(Bp + ko);
            pb1 = *(const float4*)(Bp + ko + 4);
        }

        // compute on current buffer
        const float* as = As[buf];
        const float* bs = Bs[buf];
        #pragma unroll
        for (int ks = 0; ks < 2; ks++) {
            const int kb = ks * 8 + (lane & 3);
            uint32_t afr[4][4], bfr[4][2];
            #pragma unroll
            for (int mt = 0; mt < 4; mt++) {
                const int r0 = (wm + mt * 16 + (lane >> 2)) * SSTR;
                afr[mt][0] = __float_as_uint(as[r0 + kb]);
                afr[mt][1] = __float_as_uint(as[r0 + 8 * SSTR + kb]);
                afr[mt][2] = __float_as_uint(as[r0 + kb + 4]);
                afr[mt][3] = __float_as_uint(as[r0 + 8 * SSTR + kb + 4]);
            }
            #pragma unroll
            for (int nt = 0; nt < 4; nt++) {
                const int rn = (wn + nt * 8 + (lane >> 2)) * SSTR;
                bfr[nt][0] = __float_as_uint(bs[rn + kb]);
                bfr[nt][1] = __float_as_uint(bs[rn + kb + 4]);
            }
            #pragma unroll
            for (int mt = 0; mt < 4; mt++)
                #pragma unroll
                for (int nt = 0; nt < 4; nt++)
                    mma_tf32(acc[mt][nt], afr[mt], bfr[nt]);
        }

        if (has_next) {
            float* an = As[buf ^ 1];
            float* bn2 = Bs[buf ^ 1];
            an[soff + 0] = f2tf32(pa0.x); an[soff + 1] = f2tf32(pa0.y);
            an[soff + 2] = f2tf32(pa0.z); an[soff + 3] = f2tf32(pa0.w);
            an[soff + 4] = f2tf32(pa1.x); an[soff + 5] = f2tf32(pa1.y);
            an[soff + 6] = f2tf32(pa1.z); an[soff + 7] = f2tf32(pa1.w);
            bn2[soff + 0] = f2tf32(pb0.x); bn2[soff + 1] = f2tf32(pb0.y);
            bn2[soff + 2] = f2tf32(pb0.z); bn2[soff + 3] = f2tf32(pb0.w);
            bn2[soff + 4] = f2tf32(pb1.x); bn2[soff + 5] = f2tf32(pb1.y);
            bn2[soff + 6] = f2tf32(pb1.z); bn2[soff + 7] = f2tf32(pb1.w);
        }
        __syncthreads();
        buf ^= 1;
    }

    // epilogue: c0,c1 at (row, col), c2,c3 at (row+8, col); col = 2*(lane&3)
    #pragma unroll
    for (int mt = 0; mt < 4; mt++) {
        const int row = bm + wm + mt * 16 + (lane >> 2);
        #pragma unroll
        for (int nt = 0; nt < 4; nt++) {
            const int col = bn + wn + nt * 8 + (lane & 3) * 2;
            float b0 = 0.f, b1 = 0.f;
            if (bias) { b0 = bias[col]; b1 = bias[col + 1]; }
            float2 v0 = make_float2(acc[mt][nt][0] + b0, acc[mt][nt][1] + b1);
            float2 v1 = make_float2(acc[mt][nt][2] + b0, acc[mt][nt][3] + b1);
            *(float2*)(C + (size_t)row * N + col)       = v0;
            *(float2*)(C + (size_t)(row + 8) * N + col) = v1;
        }
    }
}

// ---------------------------------------------------------------------------
// Per-head LayerNorm (+ fold in E^-0.25 scale). One warp per 64-elem segment.
// ---------------------------------------------------------------------------
__global__ __launch_bounds__(256)
void ln_head(float* __restrict__ X, const float* __restrict__ g,
             const float* __restrict__ b, float scale)
{
    const int seg  = blockIdx.x * 8 + (threadIdx.x >> 5);
    const int lane = threadIdx.x & 31;
    float2* p = (float2*)(X + (size_t)seg * HSZ) + lane;
    float2 v = *p;
    float sum = v.x + v.y;
    float sq  = v.x * v.x + v.y * v.y;
    #pragma unroll
    for (int o = 16; o; o >>= 1) {
        sum += __shfl_xor_sync(0xffffffffu, sum, o);
        sq  += __shfl_xor_sync(0xffffffffu, sq,  o);
    }
    const float mean = sum * (1.0f / 64.0f);
    const float var  = sq * (1.0f / 64.0f) - mean * mean;
    const float r    = rsqrtf(var + 1e-5f);
    const float gx = g[2 * lane], gy = g[2 * lane + 1];
    const float bx = b[2 * lane], by = b[2 * lane + 1];
    v.x = ((v.x - mean) * r * gx + bx) * scale;
    v.y = ((v.y - mean) * r * gy + by) * scale;
    *p = v;
}

// ---------------------------------------------------------------------------
// Causal flash attention, fp32. One thread per query row (BR=128 rows/block),
// K/V tiles (BC=64 x D=64) in SMEM read via warp-broadcast LDS.128.
// ---------------------------------------------------------------------------
#define BR 128
#define BC 64

__global__ __launch_bounds__(BR)
void flash_attn(const float* __restrict__ Q, const float* __restrict__ K,
                const float* __restrict__ V, float* __restrict__ O)
{
    const int qt = blockIdx.x;
    const int h  = blockIdx.y;
    const int b  = blockIdx.z;
    const int row = qt * BR + threadIdx.x;

    __shared__ float4 Ks[BC * 16];
    __shared__ float4 Vs[BC * 16];

    const size_t base = (size_t)b * SEQ * EMB + (size_t)h * HSZ;

    float4 qv[16];
    const float4* qp = (const float4*)(Q + base + (size_t)row * EMB);
    #pragma unroll
    for (int i = 0; i < 16; i++) qv[i] = qp[i];

    float4 acc[16];
    #pragma unroll
    for (int i = 0; i < 16; i++) acc[i] = make_float4(0.f, 0.f, 0.f, 0.f);
    float m = -INFINITY, l = 0.0f;

    const int ntiles = (qt + 1) * (BR / BC);
    const float4* kbase = (const float4*)(K + base);
    const float4* vbase = (const float4*)(V + base);

    for (int t0 = 0; t0 < ntiles; t0++) {
        const int k0 = t0 * BC;
        for (int i = threadIdx.x; i < BC * 16; i += BR) {
            const int r = i >> 4, c = i & 15;
            const size_t gidx = (size_t)(k0 + r) * (EMB / 4) + c;
            Ks[i] = kbase[gidx];
            Vs[i] = vbase[gidx];
        }
        __syncthreads();

        const int jmax = min(BC, row - k0 + 1);
        for (int j = 0; j < jmax; j++) {
            float s0 = 0.f, s1 = 0.f, s2 = 0.f, s3 = 0.f;
            #pragma unroll
            for (int i = 0; i < 16; i++) {
                float4 kk = Ks[j * 16 + i];
                s0 += qv[i].x * kk.x;
                s1 += qv[i].y * kk.y;
                s2 += qv[i].z * kk.z;
                s3 += qv[i].w * kk.w;
            }
            const float s = (s0 + s1) + (s2 + s3);

            float p;
            if (s <= m) {
                p = __expf(s - m);
            } else {
                const float corr = __expf(m - s);
                l *= corr;
                #pragma unroll
                for (int i = 0; i < 16; i++) {
                    acc[i].x *= corr; acc[i].y *= corr;
                    acc[i].z *= corr; acc[i].w *= corr;
                }
                m = s;
                p = 1.0f;
            }
            l += p;
            #pragma unroll
            for (int i = 0; i < 16; i++) {
                float4 vvv = Vs[j * 16 + i];
                acc[i].x += p * vvv.x;
                acc[i].y += p * vvv.y;
                acc[i].z += p * vvv.z;
                acc[i].w += p * vvv.w;
            }
        }
        __syncthreads();
    }

    const float inv = 1.0f / l;
    float4* op = (float4*)(O + base + (size_t)row * EMB);
    #pragma unroll
    for (int i = 0; i < 16; i++) {
        float4 o;
        o.x = acc[i].x * inv; o.y = acc[i].y * inv;
        o.z = acc[i].z * inv; o.w = acc[i].w * inv;
        op[i] = o;
    }
}

// ---------------------------------------------------------------------------
extern "C" void kernel_launch(void* const* d_in, const int* in_sizes, int n_in,
                              void* d_out, int out_size)
{
    const float* x   = (const float*)d_in[0];
    const float* Wk  = (const float*)d_in[1];
    const float* Wq  = (const float*)d_in[2];
    const float* Wv  = (const float*)d_in[3];
    const float* Wo  = (const float*)d_in[4];
    const float* bo  = (const float*)d_in[5];
    const float* kg  = (const float*)d_in[6];
    const float* kb  = (const float*)d_in[7];
    const float* qg  = (const float*)d_in[8];
    const float* qb  = (const float*)d_in[9];
    float* out = (float*)d_out;

    float* sbase = nullptr;
    cudaGetSymbolAddress((void**)&sbase, g_scratch);
    float* gk = sbase;
    float* gq = sbase + 1ull * MTOK * EMB;
    float* gv = sbase + 2ull * MTOK * EMB;
    float* gy = sbase + 3ull * MTOK * EMB;

    const float SCALE = 0.17677669529663687f;  // 1024^(-1/4)

    dim3 gemmGrid(EMB / 128, MTOK / 128);      // (8, 64)
    gemm_tf32_nt<<<gemmGrid, 256>>>(x, Wk, nullptr, gk, MTOK, EMB, EMB);
    gemm_tf32_nt<<<gemmGrid, 256>>>(x, Wq, nullptr, gq, MTOK, EMB, EMB);
    gemm_tf32_nt<<<gemmGrid, 256>>>(x, Wv, nullptr, gv, MTOK, EMB, EMB);

    const int nseg = MTOK * HEADS;             // 131072
    ln_head<<<nseg / 8, 256>>>(gk, kg, kb, SCALE);
    ln_head<<<nseg / 8, 256>>>(gq, qg, qb, SCALE);

    dim3 attnGrid(SEQ / BR, HEADS, BATCH);     // (16, 16, 4)
    flash_attn<<<attnGrid, BR>>>(gq, gk, gv, gy);

    gemm_tf32_nt<<<gemmGrid, 256>>>(gy, Wo, bo, out, MTOK, EMB, EMB);
}

// round 3
// speedup vs baseline: 2.8505x; 1.9255x over previous
#include <cuda_runtime.h>
#include <math.h>
#include <stdint.h>

#define EMB   1024
#define HEADS 16
#define HSZ   64
#define BATCH 4
#define SEQ   2048
#define MTOK  (BATCH * SEQ)   // 8192 token rows

// scratch: k, q, v, y (attention output) — 4 x 32MB fp32
__device__ float g_scratch[4ull * MTOK * EMB];

__device__ __forceinline__ uint32_t f2tf32u(float x) {
    uint32_t r;
    asm("cvt.rna.tf32.f32 %0, %1;" : "=r"(r) : "f"(x));
    return r;
}
__device__ __forceinline__ float f2tf32(float x) {
    return __uint_as_float(f2tf32u(x));
}

__device__ __forceinline__ void mma_tf32(float* c, const uint32_t* a,
                                         uint32_t b0, uint32_t b1) {
    asm volatile(
        "mma.sync.aligned.m16n8k8.row.col.f32.tf32.tf32.f32 "
        "{%0,%1,%2,%3}, {%4,%5,%6,%7}, {%8,%9}, {%0,%1,%2,%3};\n"
        : "+f"(c[0]), "+f"(c[1]), "+f"(c[2]), "+f"(c[3])
        : "r"(a[0]), "r"(a[1]), "r"(a[2]), "r"(a[3]), "r"(b0), "r"(b1));
}

// ---------------------------------------------------------------------------
// TF32 tensor-core GEMM: C[M,N] = A[M,K] * B[N,K]^T (+ bias[N]), fp32 in/out.
// 128x128 block tile, BK=16, 8 warps (2x4), warp tile 64x32, m16n8k8 TF32 mma.
// ---------------------------------------------------------------------------
#define BK     16
#define SSTR   20
#define TILESZ (128 * SSTR)

__global__ __launch_bounds__(256, 2)
void gemm_tf32_nt(const float* __restrict__ A, const float* __restrict__ B,
                  const float* __restrict__ bias, float* __restrict__ C,
                  int M, int N, int K)
{
    __shared__ float As[2][TILESZ];
    __shared__ float Bs[2][TILESZ];

    const int tid  = threadIdx.x;
    const int bm   = blockIdx.y * 128;
    const int bn   = blockIdx.x * 128;
    const int lane = tid & 31;
    const int wid  = tid >> 5;
    const int wm   = (wid >> 2) * 64;
    const int wn   = (wid & 3) * 32;

    const int grow  = tid >> 1;
    const int gcol  = (tid & 1) * 8;
    const float* Ap = A + (size_t)(bm + grow) * K + gcol;
    const float* Bp = B + (size_t)(bn + grow) * K + gcol;
    const int soff  = grow * SSTR + gcol;

    float acc[4][4][4];
    #pragma unroll
    for (int i = 0; i < 4; i++)
        #pragma unroll
        for (int j = 0; j < 4; j++)
            #pragma unroll
            for (int r = 0; r < 4; r++) acc[i][j][r] = 0.0f;

    {
        float4 a0 = *(const float4*)(Ap);
        float4 a1 = *(const float4*)(Ap + 4);
        float4 b0 = *(const float4*)(Bp);
        float4 b1 = *(const float4*)(Bp + 4);
        As[0][soff + 0] = f2tf32(a0.x); As[0][soff + 1] = f2tf32(a0.y);
        As[0][soff + 2] = f2tf32(a0.z); As[0][soff + 3] = f2tf32(a0.w);
        As[0][soff + 4] = f2tf32(a1.x); As[0][soff + 5] = f2tf32(a1.y);
        As[0][soff + 6] = f2tf32(a1.z); As[0][soff + 7] = f2tf32(a1.w);
        Bs[0][soff + 0] = f2tf32(b0.x); Bs[0][soff + 1] = f2tf32(b0.y);
        Bs[0][soff + 2] = f2tf32(b0.z); Bs[0][soff + 3] = f2tf32(b0.w);
        Bs[0][soff + 4] = f2tf32(b1.x); Bs[0][soff + 5] = f2tf32(b1.y);
        Bs[0][soff + 6] = f2tf32(b1.z); Bs[0][soff + 7] = f2tf32(b1.w);
    }
    __syncthreads();

    const int niter = K / BK;
    int buf = 0;

    for (int it = 0; it < niter; it++) {
        float4 pa0, pa1, pb0, pb1;
        const bool has_next = (it + 1) < niter;
        if (has_next) {
            const int ko = (it + 1) * BK;
            pa0 = *(const float4*)(Ap + ko);
            pa1 = *(const float4*)(Ap + ko + 4);
            pb0 = *(const float4*)(Bp + ko);
            pb1 = *(const float4*)(Bp + ko + 4);
        }

        const float* as = As[buf];
        const float* bs = Bs[buf];
        #pragma unroll
        for (int ks = 0; ks < 2; ks++) {
            const int kb = ks * 8 + (lane & 3);
            uint32_t afr[4][4], bfr[4][2];
            #pragma unroll
            for (int mt = 0; mt < 4; mt++) {
                const int r0 = (wm + mt * 16 + (lane >> 2)) * SSTR;
                afr[mt][0] = __float_as_uint(as[r0 + kb]);
                afr[mt][1] = __float_as_uint(as[r0 + 8 * SSTR + kb]);
                afr[mt][2] = __float_as_uint(as[r0 + kb + 4]);
                afr[mt][3] = __float_as_uint(as[r0 + 8 * SSTR + kb + 4]);
            }
            #pragma unroll
            for (int nt = 0; nt < 4; nt++) {
                const int rn = (wn + nt * 8 + (lane >> 2)) * SSTR;
                bfr[nt][0] = __float_as_uint(bs[rn + kb]);
                bfr[nt][1] = __float_as_uint(bs[rn + kb + 4]);
            }
            #pragma unroll
            for (int mt = 0; mt < 4; mt++)
                #pragma unroll
                for (int nt = 0; nt < 4; nt++)
                    mma_tf32(acc[mt][nt], afr[mt], bfr[nt][0], bfr[nt][1]);
        }

        if (has_next) {
            float* an = As[buf ^ 1];
            float* bn2 = Bs[buf ^ 1];
            an[soff + 0] = f2tf32(pa0.x); an[soff + 1] = f2tf32(pa0.y);
            an[soff + 2] = f2tf32(pa0.z); an[soff + 3] = f2tf32(pa0.w);
            an[soff + 4] = f2tf32(pa1.x); an[soff + 5] = f2tf32(pa1.y);
            an[soff + 6] = f2tf32(pa1.z); an[soff + 7] = f2tf32(pa1.w);
            bn2[soff + 0] = f2tf32(pb0.x); bn2[soff + 1] = f2tf32(pb0.y);
            bn2[soff + 2] = f2tf32(pb0.z); bn2[soff + 3] = f2tf32(pb0.w);
            bn2[soff + 4] = f2tf32(pb1.x); bn2[soff + 5] = f2tf32(pb1.y);
            bn2[soff + 6] = f2tf32(pb1.z); bn2[soff + 7] = f2tf32(pb1.w);
        }
        __syncthreads();
        buf ^= 1;
    }

    #pragma unroll
    for (int mt = 0; mt < 4; mt++) {
        const int row = bm + wm + mt * 16 + (lane >> 2);
        #pragma unroll
        for (int nt = 0; nt < 4; nt++) {
            const int col = bn + wn + nt * 8 + (lane & 3) * 2;
            float b0 = 0.f, b1 = 0.f;
            if (bias) { b0 = bias[col]; b1 = bias[col + 1]; }
            float2 v0 = make_float2(acc[mt][nt][0] + b0, acc[mt][nt][1] + b1);
            float2 v1 = make_float2(acc[mt][nt][2] + b0, acc[mt][nt][3] + b1);
            *(float2*)(C + (size_t)row * N + col)       = v0;
            *(float2*)(C + (size_t)(row + 8) * N + col) = v1;
        }
    }
}

// ---------------------------------------------------------------------------
// Per-head LayerNorm (+ fold in E^-0.25 scale). One warp per 64-elem segment.
// ---------------------------------------------------------------------------
__global__ __launch_bounds__(256)
void ln_head(float* __restrict__ X, const float* __restrict__ g,
             const float* __restrict__ b, float scale)
{
    const int seg  = blockIdx.x * 8 + (threadIdx.x >> 5);
    const int lane = threadIdx.x & 31;
    float2* p = (float2*)(X + (size_t)seg * HSZ) + lane;
    float2 v = *p;
    float sum = v.x + v.y;
    float sq  = v.x * v.x + v.y * v.y;
    #pragma unroll
    for (int o = 16; o; o >>= 1) {
        sum += __shfl_xor_sync(0xffffffffu, sum, o);
        sq  += __shfl_xor_sync(0xffffffffu, sq,  o);
    }
    const float mean = sum * (1.0f / 64.0f);
    const float var  = sq * (1.0f / 64.0f) - mean * mean;
    const float r    = rsqrtf(var + 1e-5f);
    const float gx = g[2 * lane], gy = g[2 * lane + 1];
    const float bx = b[2 * lane], by = b[2 * lane + 1];
    v.x = ((v.x - mean) * r * gx + bx) * scale;
    v.y = ((v.y - mean) * r * gy + by) * scale;
    *p = v;
}

// ---------------------------------------------------------------------------
// Tensor-core causal flash attention (TF32 mma, fp32 accumulate).
// Block = 4 warps, BR=64 query rows (16/warp), BC=64 keys per tile, D=64.
// K in smem stride 68 (conflict-free for S B-frags), V stride 72 (PV B-frags).
// P overwrites K buffer after S-phase (K dead). Online softmax per row,
// row state shared by 4-lane shfl groups.
// ---------------------------------------------------------------------------
#define KSTR 68
#define VSTR 72

__global__ __launch_bounds__(128)
void flash_attn_tc(const float* __restrict__ Q, const float* __restrict__ K,
                   const float* __restrict__ V, float* __restrict__ O)
{
    const int qb = blockIdx.x;   // query tile (64 rows)
    const int h  = blockIdx.y;
    const int b  = blockIdx.z;
    const int tid  = threadIdx.x;
    const int lane = tid & 31;
    const int wid  = tid >> 5;
    const int wm   = wid * 16;       // warp's query-row offset in tile
    const int lr   = lane >> 2;      // fragment row 0..7
    const int lc   = lane & 3;       // fragment col group 0..3

    __shared__ float Ks[64 * KSTR];  // K tile, then P tile
    __shared__ float Vs[64 * VSTR];

    const size_t base = (size_t)b * SEQ * EMB + (size_t)h * HSZ;

    // ---- stage Q tile through Ks, build A-fragments in registers ----
    {
        const float4* qg = (const float4*)(Q + base + (size_t)(qb * 64) * EMB);
        for (int i = tid; i < 64 * 16; i += 128) {
            const int r = i >> 4, c = i & 15;
            float4 v = qg[(size_t)r * (EMB / 4) + c];
            float* d = &Ks[r * KSTR + c * 4];
            d[0] = v.x; d[1] = v.y; d[2] = v.z; d[3] = v.w;
        }
    }
    __syncthreads();

    uint32_t qa[8][4];
    #pragma unroll
    for (int kk = 0; kk < 8; kk++) {
        const int r0 = (wm + lr) * KSTR + kk * 8 + lc;
        qa[kk][0] = f2tf32u(Ks[r0]);
        qa[kk][1] = f2tf32u(Ks[r0 + 8 * KSTR]);
        qa[kk][2] = f2tf32u(Ks[r0 + 4]);
        qa[kk][3] = f2tf32u(Ks[r0 + 4 + 8 * KSTR]);
    }
    __syncthreads();

    float o[8][4];
    #pragma unroll
    for (int i = 0; i < 8; i++)
        #pragma unroll
        for (int j = 0; j < 4; j++) o[i][j] = 0.0f;
    float m0 = -INFINITY, m1 = -INFINITY, l0 = 0.0f, l1 = 0.0f;

    const float4* kg0 = (const float4*)(K + base);
    const float4* vg0 = (const float4*)(V + base);

    for (int kt = 0; kt <= qb; kt++) {
        // ---- cooperative K/V tile load with tf32 convert ----
        for (int i = tid; i < 64 * 16; i += 128) {
            const int r = i >> 4, c = i & 15;
            const size_t gidx = (size_t)(kt * 64 + r) * (EMB / 4) + c;
            float4 kv = kg0[gidx];
            float4 vv = vg0[gidx];
            float* dk = &Ks[r * KSTR + c * 4];
            dk[0] = f2tf32(kv.x); dk[1] = f2tf32(kv.y);
            dk[2] = f2tf32(kv.z); dk[3] = f2tf32(kv.w);
            float* dv = &Vs[r * VSTR + c * 4];
            dv[0] = f2tf32(vv.x); dv[1] = f2tf32(vv.y);
            dv[2] = f2tf32(vv.z); dv[3] = f2tf32(vv.w);
        }
        __syncthreads();

        // ---- S = Q K^T  (64 mmas/warp) ----
        float s[8][4];
        #pragma unroll
        for (int nt = 0; nt < 8; nt++)
            #pragma unroll
            for (int j = 0; j < 4; j++) s[nt][j] = 0.0f;

        #pragma unroll
        for (int kk = 0; kk < 8; kk++) {
            #pragma unroll
            for (int nt = 0; nt < 8; nt++) {
                const int rb = (nt * 8 + lr) * KSTR + kk * 8 + lc;
                mma_tf32(s[nt], qa[kk],
                         __float_as_uint(Ks[rb]),
                         __float_as_uint(Ks[rb + 4]));
            }
        }

        // ---- causal mask on diagonal tile ----
        if (kt == qb) {
            const int row0 = wm + lr;       // rows row0, row0+8 (within tile)
            #pragma unroll
            for (int nt = 0; nt < 8; nt++) {
                const int col = nt * 8 + 2 * lc;
                if (col     > row0)     s[nt][0] = -1e30f;
                if (col + 1 > row0)     s[nt][1] = -1e30f;
                if (col     > row0 + 8) s[nt][2] = -1e30f;
                if (col + 1 > row0 + 8) s[nt][3] = -1e30f;
            }
        }

        // ---- online softmax ----
        float mx0 = -INFINITY, mx1 = -INFINITY;
        #pragma unroll
        for (int nt = 0; nt < 8; nt++) {
            mx0 = fmaxf(mx0, fmaxf(s[nt][0], s[nt][1]));
            mx1 = fmaxf(mx1, fmaxf(s[nt][2], s[nt][3]));
        }
        mx0 = fmaxf(mx0, __shfl_xor_sync(0xffffffffu, mx0, 1));
        mx0 = fmaxf(mx0, __shfl_xor_sync(0xffffffffu, mx0, 2));
        mx1 = fmaxf(mx1, __shfl_xor_sync(0xffffffffu, mx1, 1));
        mx1 = fmaxf(mx1, __shfl_xor_sync(0xffffffffu, mx1, 2));

        const float m0n = fmaxf(m0, mx0);
        const float m1n = fmaxf(m1, mx1);
        const float c0 = __expf(m0 - m0n);
        const float c1 = __expf(m1 - m1n);
        m0 = m0n; m1 = m1n;
        l0 *= c0;  l1 *= c1;
        #pragma unroll
        for (int nt = 0; nt < 8; nt++) {
            o[nt][0] *= c0; o[nt][1] *= c0;
            o[nt][2] *= c1; o[nt][3] *= c1;
        }
        #pragma unroll
        for (int nt = 0; nt < 8; nt++) {
            float p0 = __expf(s[nt][0] - m0);
            float p1 = __expf(s[nt][1] - m0);
            float p2 = __expf(s[nt][2] - m1);
            float p3 = __expf(s[nt][3] - m1);
            l0 += p0 + p1;
            l1 += p2 + p3;
            s[nt][0] = f2tf32(p0); s[nt][1] = f2tf32(p1);
            s[nt][2] = f2tf32(p2); s[nt][3] = f2tf32(p3);
        }

        // ---- write P over K buffer (all warps done reading Ks) ----
        __syncthreads();
        {
            const int r0 = wm + lr;
            #pragma unroll
            for (int nt = 0; nt < 8; nt++) {
                const int col = nt * 8 + 2 * lc;
                *(float2*)&Ks[r0 * KSTR + col]       = make_float2(s[nt][0], s[nt][1]);
                *(float2*)&Ks[(r0 + 8) * KSTR + col] = make_float2(s[nt][2], s[nt][3]);
            }
        }
        __syncwarp();

        // ---- O += P V  (64 mmas/warp) ----
        #pragma unroll
        for (int kk = 0; kk < 8; kk++) {
            uint32_t pa[4];
            const int r0 = (wm + lr) * KSTR + kk * 8 + lc;
            pa[0] = __float_as_uint(Ks[r0]);
            pa[1] = __float_as_uint(Ks[r0 + 8 * KSTR]);
            pa[2] = __float_as_uint(Ks[r0 + 4]);
            pa[3] = __float_as_uint(Ks[r0 + 4 + 8 * KSTR]);
            #pragma unroll
            for (int ntd = 0; ntd < 8; ntd++) {
                const int vb = (kk * 8 + lc) * VSTR + ntd * 8 + lr;
                mma_tf32(o[ntd], pa,
                         __float_as_uint(Vs[vb]),
                         __float_as_uint(Vs[vb + 4 * VSTR]));
            }
        }
        __syncthreads();
    }

    // ---- finalize: reduce l across the 4-lane row group, normalize, store ----
    l0 += __shfl_xor_sync(0xffffffffu, l0, 1);
    l0 += __shfl_xor_sync(0xffffffffu, l0, 2);
    l1 += __shfl_xor_sync(0xffffffffu, l1, 1);
    l1 += __shfl_xor_sync(0xffffffffu, l1, 2);
    const float i0 = 1.0f / l0;
    const float i1 = 1.0f / l1;

    const int row0 = qb * 64 + wm + lr;
    float* op = O + base + (size_t)row0 * EMB;
    #pragma unroll
    for (int ntd = 0; ntd < 8; ntd++) {
        const int col = ntd * 8 + 2 * lc;
        *(float2*)(op + col) =
            make_float2(o[ntd][0] * i0, o[ntd][1] * i0);
        *(float2*)(op + (size_t)8 * EMB + col) =
            make_float2(o[ntd][2] * i1, o[ntd][3] * i1);
    }
}

// ---------------------------------------------------------------------------
extern "C" void kernel_launch(void* const* d_in, const int* in_sizes, int n_in,
                              void* d_out, int out_size)
{
    const float* x   = (const float*)d_in[0];
    const float* Wk  = (const float*)d_in[1];
    const float* Wq  = (const float*)d_in[2];
    const float* Wv  = (const float*)d_in[3];
    const float* Wo  = (const float*)d_in[4];
    const float* bo  = (const float*)d_in[5];
    const float* kg  = (const float*)d_in[6];
    const float* kb  = (const float*)d_in[7];
    const float* qg  = (const float*)d_in[8];
    const float* qb  = (const float*)d_in[9];
    float* out = (float*)d_out;

    float* sbase = nullptr;
    cudaGetSymbolAddress((void**)&sbase, g_scratch);
    float* gk = sbase;
    float* gq = sbase + 1ull * MTOK * EMB;
    float* gv = sbase + 2ull * MTOK * EMB;
    float* gy = sbase + 3ull * MTOK * EMB;

    const float SCALE = 0.17677669529663687f;  // 1024^(-1/4)

    dim3 gemmGrid(EMB / 128, MTOK / 128);      // (8, 64)
    gemm_tf32_nt<<<gemmGrid, 256>>>(x, Wk, nullptr, gk, MTOK, EMB, EMB);
    gemm_tf32_nt<<<gemmGrid, 256>>>(x, Wq, nullptr, gq, MTOK, EMB, EMB);
    gemm_tf32_nt<<<gemmGrid, 256>>>(x, Wv, nullptr, gv, MTOK, EMB, EMB);

    const int nseg = MTOK * HEADS;             // 131072
    ln_head<<<nseg / 8, 256>>>(gk, kg, kb, SCALE);
    ln_head<<<nseg / 8, 256>>>(gq, qg, qb, SCALE);

    dim3 attnGrid(SEQ / 64, HEADS, BATCH);     // (32, 16, 4)
    flash_attn_tc<<<attnGrid, 128>>>(gq, gk, gv, gy);

    gemm_tf32_nt<<<gemmGrid, 256>>>(gy, Wo, bo, out, MTOK, EMB, EMB);
}

// round 4
// speedup vs baseline: 3.3410x; 1.1721x over previous
#include <cuda_runtime.h>
#include <math.h>
#include <stdint.h>

#define EMB   1024
#define HEADS 16
#define HSZ   64
#define BATCH 4
#define SEQ   2048
#define MTOK  (BATCH * SEQ)   // 8192 token rows

__device__ float g_scratch[4ull * MTOK * EMB];

__device__ __forceinline__ uint32_t f2tf32u(float x) {
    uint32_t r;
    asm("cvt.rna.tf32.f32 %0, %1;" : "=r"(r) : "f"(x));
    return r;
}
__device__ __forceinline__ float f2tf32(float x) {
    return __uint_as_float(f2tf32u(x));
}

__device__ __forceinline__ void mma_tf32(float* c, const uint32_t* a,
                                         uint32_t b0, uint32_t b1) {
    asm volatile(
        "mma.sync.aligned.m16n8k8.row.col.f32.tf32.tf32.f32 "
        "{%0,%1,%2,%3}, {%4,%5,%6,%7}, {%8,%9}, {%0,%1,%2,%3};\n"
        : "+f"(c[0]), "+f"(c[1]), "+f"(c[2]), "+f"(c[3])
        : "r"(a[0]), "r"(a[1]), "r"(a[2]), "r"(a[3]), "r"(b0), "r"(b1));
}

__device__ __forceinline__ void cp_async16(uint32_t saddr, const void* gaddr) {
    asm volatile("cp.async.cg.shared.global [%0], [%1], 16;\n"
                 :: "r"(saddr), "l"(gaddr));
}
__device__ __forceinline__ void cp_commit() {
    asm volatile("cp.async.commit_group;\n");
}
template <int N>
__device__ __forceinline__ void cp_wait() {
    asm volatile("cp.async.wait_group %0;\n" :: "n"(N));
}

// ---------------------------------------------------------------------------
// TF32 GEMM, cp.async 4-stage pipeline: C[M,N] = A[M,K]*B[N,K]^T (+bias).
// 128x128 tile, BK=16, 8 warps (2x4), warp tile 64x32, m16n8k8.
// fp32 raw in smem (stride 20 -> conflict-free), cvt to tf32 after LDS.
// ---------------------------------------------------------------------------
#define STAGES 4
#define GBK    16
#define ASTR   20
#define STGF   (128 * ASTR)   // floats per stage per operand

__global__ __launch_bounds__(256, 2)
void gemm_tf32_pipe(const float* __restrict__ A, const float* __restrict__ B,
                    const float* __restrict__ bias, float* __restrict__ C,
                    int M, int N, int K)
{
    extern __shared__ float sm[];
    float* As = sm;                    // [STAGES][STGF]
    float* Bs = sm + STAGES * STGF;

    const int tid  = threadIdx.x;
    const int bm   = blockIdx.y * 128;
    const int bn   = blockIdx.x * 128;
    const int lane = tid & 31;
    const int wid  = tid >> 5;
    const int wm   = (wid >> 2) * 64;
    const int wn   = (wid & 3) * 32;
    const int lr   = lane >> 2;
    const int lc   = lane & 3;

    // cp.async assignment: 512 chunks (16B) per operand per stage, 2/thread
    const int ch0 = tid, ch1 = tid + 256;
    const int r0c = ch0 >> 2, c0c = (ch0 & 3) * 4;
    const int r1c = ch1 >> 2, c1c = (ch1 & 3) * 4;

    const float* Ag0 = A + (size_t)(bm + r0c) * K + c0c;
    const float* Ag1 = A + (size_t)(bm + r1c) * K + c1c;
    const float* Bg0 = B + (size_t)(bn + r0c) * K + c0c;
    const float* Bg1 = B + (size_t)(bn + r1c) * K + c1c;

    uint32_t sA0, sA1, sB0, sB1;
    {
        uint32_t base;
        asm("{ .reg .u64 t; cvta.to.shared.u64 t, %1; cvt.u32.u64 %0, t; }"
            : "=r"(base) : "l"(sm));
        sA0 = base + (r0c * ASTR + c0c) * 4;
        sA1 = base + (r1c * ASTR + c1c) * 4;
        sB0 = base + (STAGES * STGF + r0c * ASTR + c0c) * 4;
        sB1 = base + (STAGES * STGF + r1c * ASTR + c1c) * 4;
    }

    float acc[4][4][4];
    #pragma unroll
    for (int i = 0; i < 4; i++)
        #pragma unroll
        for (int j = 0; j < 4; j++)
            #pragma unroll
            for (int r = 0; r < 4; r++) acc[i][j][r] = 0.0f;

    const int niter = K / GBK;   // 64

    // prologue: stages 0..STAGES-2
    #pragma unroll
    for (int s = 0; s < STAGES - 1; s++) {
        const int ko = s * GBK;
        const uint32_t so = s * STGF * 4;
        cp_async16(sA0 + so, Ag0 + ko);
        cp_async16(sA1 + so, Ag1 + ko);
        cp_async16(sB0 + so, Bg0 + ko);
        cp_async16(sB1 + so, Bg1 + ko);
        cp_commit();
    }

    for (int it = 0; it < niter; it++) {
        cp_wait<STAGES - 2>();
        __syncthreads();

        // issue stage it+STAGES-1
        const int nxt = it + STAGES - 1;
        if (nxt < niter) {
            const int ko = nxt * GBK;
            const uint32_t so = (nxt % STAGES) * STGF * 4;
            cp_async16(sA0 + so, Ag0 + ko);
            cp_async16(sA1 + so, Ag1 + ko);
            cp_async16(sB0 + so, Bg0 + ko);
            cp_async16(sB1 + so, Bg1 + ko);
        }
        cp_commit();

        // compute stage it
        const float* as = As + (it % STAGES) * STGF;
        const float* bs = Bs + (it % STAGES) * STGF;
        #pragma unroll
        for (int ks = 0; ks < 2; ks++) {
            const int kb = ks * 8 + lc;
            uint32_t afr[4][4], bfr[4][2];
            #pragma unroll
            for (int mt = 0; mt < 4; mt++) {
                const int r0 = (wm + mt * 16 + lr) * ASTR;
                afr[mt][0] = f2tf32u(as[r0 + kb]);
                afr[mt][1] = f2tf32u(as[r0 + 8 * ASTR + kb]);
                afr[mt][2] = f2tf32u(as[r0 + kb + 4]);
                afr[mt][3] = f2tf32u(as[r0 + 8 * ASTR + kb + 4]);
            }
            #pragma unroll
            for (int nt = 0; nt < 4; nt++) {
                const int rn = (wn + nt * 8 + lr) * ASTR;
                bfr[nt][0] = f2tf32u(bs[rn + kb]);
                bfr[nt][1] = f2tf32u(bs[rn + kb + 4]);
            }
            #pragma unroll
            for (int mt = 0; mt < 4; mt++)
                #pragma unroll
                for (int nt = 0; nt < 4; nt++)
                    mma_tf32(acc[mt][nt], afr[mt], bfr[nt][0], bfr[nt][1]);
        }
    }

    #pragma unroll
    for (int mt = 0; mt < 4; mt++) {
        const int row = bm + wm + mt * 16 + lr;
        #pragma unroll
        for (int nt = 0; nt < 4; nt++) {
            const int col = bn + wn + nt * 8 + lc * 2;
            float b0 = 0.f, b1 = 0.f;
            if (bias) { b0 = bias[col]; b1 = bias[col + 1]; }
            float2 v0 = make_float2(acc[mt][nt][0] + b0, acc[mt][nt][1] + b1);
            float2 v1 = make_float2(acc[mt][nt][2] + b0, acc[mt][nt][3] + b1);
            *(float2*)(C + (size_t)row * N + col)       = v0;
            *(float2*)(C + (size_t)(row + 8) * N + col) = v1;
        }
    }
}

#define GEMM_SMEM (STAGES * 2 * STGF * 4)   // 81920 bytes

// ---------------------------------------------------------------------------
// Per-head LayerNorm (+ fold in E^-0.25 scale). One warp per 64-elem segment.
// ---------------------------------------------------------------------------
__global__ __launch_bounds__(256)
void ln_head(float* __restrict__ X, const float* __restrict__ g,
             const float* __restrict__ b, float scale)
{
    const int seg  = blockIdx.x * 8 + (threadIdx.x >> 5);
    const int lane = threadIdx.x & 31;
    float2* p = (float2*)(X + (size_t)seg * HSZ) + lane;
    float2 v = *p;
    float sum = v.x + v.y;
    float sq  = v.x * v.x + v.y * v.y;
    #pragma unroll
    for (int o = 16; o; o >>= 1) {
        sum += __shfl_xor_sync(0xffffffffu, sum, o);
        sq  += __shfl_xor_sync(0xffffffffu, sq,  o);
    }
    const float mean = sum * (1.0f / 64.0f);
    const float var  = sq * (1.0f / 64.0f) - mean * mean;
    const float r    = rsqrtf(var + 1e-5f);
    const float gx = g[2 * lane], gy = g[2 * lane + 1];
    const float bx = b[2 * lane], by = b[2 * lane + 1];
    v.x = ((v.x - mean) * r * gx + bx) * scale;
    v.y = ((v.y - mean) * r * gy + by) * scale;
    *p = v;
}

// ---------------------------------------------------------------------------
// Tensor-core causal flash attention (TF32 mma) — unchanged from R3.
// ---------------------------------------------------------------------------
#define KSTR 68
#define VSTR 72

__global__ __launch_bounds__(128)
void flash_attn_tc(const float* __restrict__ Q, const float* __restrict__ K,
                   const float* __restrict__ V, float* __restrict__ O)
{
    const int qb = blockIdx.x;
    const int h  = blockIdx.y;
    const int b  = blockIdx.z;
    const int tid  = threadIdx.x;
    const int lane = tid & 31;
    const int wid  = tid >> 5;
    const int wm   = wid * 16;
    const int lr   = lane >> 2;
    const int lc   = lane & 3;

    __shared__ float Ks[64 * KSTR];
    __shared__ float Vs[64 * VSTR];

    const size_t base = (size_t)b * SEQ * EMB + (size_t)h * HSZ;

    {
        const float4* qg = (const float4*)(Q + base + (size_t)(qb * 64) * EMB);
        for (int i = tid; i < 64 * 16; i += 128) {
            const int r = i >> 4, c = i & 15;
            float4 v = qg[(size_t)r * (EMB / 4) + c];
            float* d = &Ks[r * KSTR + c * 4];
            d[0] = v.x; d[1] = v.y; d[2] = v.z; d[3] = v.w;
        }
    }
    __syncthreads();

    uint32_t qa[8][4];
    #pragma unroll
    for (int kk = 0; kk < 8; kk++) {
        const int r0 = (wm + lr) * KSTR + kk * 8 + lc;
        qa[kk][0] = f2tf32u(Ks[r0]);
        qa[kk][1] = f2tf32u(Ks[r0 + 8 * KSTR]);
        qa[kk][2] = f2tf32u(Ks[r0 + 4]);
        qa[kk][3] = f2tf32u(Ks[r0 + 4 + 8 * KSTR]);
    }
    __syncthreads();

    float o[8][4];
    #pragma unroll
    for (int i = 0; i < 8; i++)
        #pragma unroll
        for (int j = 0; j < 4; j++) o[i][j] = 0.0f;
    float m0 = -INFINITY, m1 = -INFINITY, l0 = 0.0f, l1 = 0.0f;

    const float4* kg0 = (const float4*)(K + base);
    const float4* vg0 = (const float4*)(V + base);

    for (int kt = 0; kt <= qb; kt++) {
        for (int i = tid; i < 64 * 16; i += 128) {
            const int r = i >> 4, c = i & 15;
            const size_t gidx = (size_t)(kt * 64 + r) * (EMB / 4) + c;
            float4 kv = kg0[gidx];
            float4 vv = vg0[gidx];
            float* dk = &Ks[r * KSTR + c * 4];
            dk[0] = f2tf32(kv.x); dk[1] = f2tf32(kv.y);
            dk[2] = f2tf32(kv.z); dk[3] = f2tf32(kv.w);
            float* dv = &Vs[r * VSTR + c * 4];
            dv[0] = f2tf32(vv.x); dv[1] = f2tf32(vv.y);
            dv[2] = f2tf32(vv.z); dv[3] = f2tf32(vv.w);
        }
        __syncthreads();

        float s[8][4];
        #pragma unroll
        for (int nt = 0; nt < 8; nt++)
            #pragma unroll
            for (int j = 0; j < 4; j++) s[nt][j] = 0.0f;

        #pragma unroll
        for (int kk = 0; kk < 8; kk++) {
            #pragma unroll
            for (int nt = 0; nt < 8; nt++) {
                const int rb = (nt * 8 + lr) * KSTR + kk * 8 + lc;
                mma_tf32(s[nt], qa[kk],
                         __float_as_uint(Ks[rb]),
                         __float_as_uint(Ks[rb + 4]));
            }
        }

        if (kt == qb) {
            const int row0 = wm + lr;
            #pragma unroll
            for (int nt = 0; nt < 8; nt++) {
                const int col = nt * 8 + 2 * lc;
                if (col     > row0)     s[nt][0] = -1e30f;
                if (col + 1 > row0)     s[nt][1] = -1e30f;
                if (col     > row0 + 8) s[nt][2] = -1e30f;
                if (col + 1 > row0 + 8) s[nt][3] = -1e30f;
            }
        }

        float mx0 = -INFINITY, mx1 = -INFINITY;
        #pragma unroll
        for (int nt = 0; nt < 8; nt++) {
            mx0 = fmaxf(mx0, fmaxf(s[nt][0], s[nt][1]));
            mx1 = fmaxf(mx1, fmaxf(s[nt][2], s[nt][3]));
        }
        mx0 = fmaxf(mx0, __shfl_xor_sync(0xffffffffu, mx0, 1));
        mx0 = fmaxf(mx0, __shfl_xor_sync(0xffffffffu, mx0, 2));
        mx1 = fmaxf(mx1, __shfl_xor_sync(0xffffffffu, mx1, 1));
        mx1 = fmaxf(mx1, __shfl_xor_sync(0xffffffffu, mx1, 2));

        const float m0n = fmaxf(m0, mx0);
        const float m1n = fmaxf(m1, mx1);
        const float c0 = __expf(m0 - m0n);
        const float c1 = __expf(m1 - m1n);
        m0 = m0n; m1 = m1n;
        l0 *= c0;  l1 *= c1;
        #pragma unroll
        for (int nt = 0; nt < 8; nt++) {
            o[nt][0] *= c0; o[nt][1] *= c0;
            o[nt][2] *= c1; o[nt][3] *= c1;
        }
        #pragma unroll
        for (int nt = 0; nt < 8; nt++) {
            float p0 = __expf(s[nt][0] - m0);
            float p1 = __expf(s[nt][1] - m0);
            float p2 = __expf(s[nt][2] - m1);
            float p3 = __expf(s[nt][3] - m1);
            l0 += p0 + p1;
            l1 += p2 + p3;
            s[nt][0] = f2tf32(p0); s[nt][1] = f2tf32(p1);
            s[nt][2] = f2tf32(p2); s[nt][3] = f2tf32(p3);
        }

        __syncthreads();
        {
            const int r0 = wm + lr;
            #pragma unroll
            for (int nt = 0; nt < 8; nt++) {
                const int col = nt * 8 + 2 * lc;
                *(float2*)&Ks[r0 * KSTR + col]       = make_float2(s[nt][0], s[nt][1]);
                *(float2*)&Ks[(r0 + 8) * KSTR + col] = make_float2(s[nt][2], s[nt][3]);
            }
        }
        __syncwarp();

        #pragma unroll
        for (int kk = 0; kk < 8; kk++) {
            uint32_t pa[4];
            const int r0 = (wm + lr) * KSTR + kk * 8 + lc;
            pa[0] = __float_as_uint(Ks[r0]);
            pa[1] = __float_as_uint(Ks[r0 + 8 * KSTR]);
            pa[2] = __float_as_uint(Ks[r0 + 4]);
            pa[3] = __float_as_uint(Ks[r0 + 4 + 8 * KSTR]);
            #pragma unroll
            for (int ntd = 0; ntd < 8; ntd++) {
                const int vb = (kk * 8 + lc) * VSTR + ntd * 8 + lr;
                mma_tf32(o[ntd], pa,
                         __float_as_uint(Vs[vb]),
                         __float_as_uint(Vs[vb + 4 * VSTR]));
            }
        }
        __syncthreads();
    }

    l0 += __shfl_xor_sync(0xffffffffu, l0, 1);
    l0 += __shfl_xor_sync(0xffffffffu, l0, 2);
    l1 += __shfl_xor_sync(0xffffffffu, l1, 1);
    l1 += __shfl_xor_sync(0xffffffffu, l1, 2);
    const float i0 = 1.0f / l0;
    const float i1 = 1.0f / l1;

    const int row0 = qb * 64 + wm + lr;
    float* op = O + base + (size_t)row0 * EMB;
    #pragma unroll
    for (int ntd = 0; ntd < 8; ntd++) {
        const int col = ntd * 8 + 2 * lc;
        *(float2*)(op + col) =
            make_float2(o[ntd][0] * i0, o[ntd][1] * i0);
        *(float2*)(op + (size_t)8 * EMB + col) =
            make_float2(o[ntd][2] * i1, o[ntd][3] * i1);
    }
}

// ---------------------------------------------------------------------------
extern "C" void kernel_launch(void* const* d_in, const int* in_sizes, int n_in,
                              void* d_out, int out_size)
{
    const float* x   = (const float*)d_in[0];
    const float* Wk  = (const float*)d_in[1];
    const float* Wq  = (const float*)d_in[2];
    const float* Wv  = (const float*)d_in[3];
    const float* Wo  = (const float*)d_in[4];
    const float* bo  = (const float*)d_in[5];
    const float* kg  = (const float*)d_in[6];
    const float* kb  = (const float*)d_in[7];
    const float* qg  = (const float*)d_in[8];
    const float* qb  = (const float*)d_in[9];
    float* out = (float*)d_out;

    float* sbase = nullptr;
    cudaGetSymbolAddress((void**)&sbase, g_scratch);
    float* gk = sbase;
    float* gq = sbase + 1ull * MTOK * EMB;
    float* gv = sbase + 2ull * MTOK * EMB;
    float* gy = sbase + 3ull * MTOK * EMB;

    const float SCALE = 0.17677669529663687f;  // 1024^(-1/4)

    cudaFuncSetAttribute(gemm_tf32_pipe,
                         cudaFuncAttributeMaxDynamicSharedMemorySize, GEMM_SMEM);

    dim3 gemmGrid(EMB / 128, MTOK / 128);      // (8, 64)
    gemm_tf32_pipe<<<gemmGrid, 256, GEMM_SMEM>>>(x, Wk, nullptr, gk, MTOK, EMB, EMB);
    gemm_tf32_pipe<<<gemmGrid, 256, GEMM_SMEM>>>(x, Wq, nullptr, gq, MTOK, EMB, EMB);
    gemm_tf32_pipe<<<gemmGrid, 256, GEMM_SMEM>>>(x, Wv, nullptr, gv, MTOK, EMB, EMB);

    const int nseg = MTOK * HEADS;             // 131072
    ln_head<<<nseg / 8, 256>>>(gk, kg, kb, SCALE);
    ln_head<<<nseg / 8, 256>>>(gq, qg, qb, SCALE);

    dim3 attnGrid(SEQ / 64, HEADS, BATCH);     // (32, 16, 4)
    flash_attn_tc<<<attnGrid, 128>>>(gq, gk, gv, gy);

    gemm_tf32_pipe<<<gemmGrid, 256, GEMM_SMEM>>>(gy, Wo, bo, out, MTOK, EMB, EMB);
}

// round 6
// speedup vs baseline: 4.9810x; 1.4909x over previous
#include <cuda_runtime.h>
#include <cuda_fp16.h>
#include <math.h>
#include <stdint.h>

#define EMB   1024
#define HEADS 16
#define HSZ   64
#define BATCH 4
#define SEQ   2048
#define MTOK  (BATCH * SEQ)   // 8192 token rows

// scratch (floats): xh(4M) wk/wq/wv/wo h(4x0.5M) gk gq gv(3x8M) gyh(4M) = 34M
__device__ float g_scratch[34ull * 1024 * 1024];

__device__ __forceinline__ void mma_f16(float* c, const uint32_t* a,
                                        uint32_t b0, uint32_t b1) {
    asm volatile(
        "mma.sync.aligned.m16n8k16.row.col.f32.f16.f16.f32 "
        "{%0,%1,%2,%3}, {%4,%5,%6,%7}, {%8,%9}, {%0,%1,%2,%3};\n"
        : "+f"(c[0]), "+f"(c[1]), "+f"(c[2]), "+f"(c[3])
        : "r"(a[0]), "r"(a[1]), "r"(a[2]), "r"(a[3]), "r"(b0), "r"(b1));
}

__device__ __forceinline__ void cp_async16(uint32_t saddr, const void* gaddr) {
    asm volatile("cp.async.cg.shared.global [%0], [%1], 16;\n"
                 :: "r"(saddr), "l"(gaddr));
}
__device__ __forceinline__ void cp_commit() {
    asm volatile("cp.async.commit_group;\n");
}
template <int N>
__device__ __forceinline__ void cp_wait() {
    asm volatile("cp.async.wait_group %0;\n" :: "n"(N));
}
__device__ __forceinline__ uint32_t smem_u32(const void* p) {
    uint32_t a;
    asm("{ .reg .u64 t; cvta.to.shared.u64 t, %1; cvt.u32.u64 %0, t; }"
        : "=r"(a) : "l"(p));
    return a;
}
__device__ __forceinline__ uint32_t pack_h2(float a, float b) {
    __half2 h = __floats2half2_rn(a, b);
    return *(uint32_t*)&h;
}

// ---------------------------------------------------------------------------
// fp32 -> fp16 convert (RNE), grid-stride over float4 groups
// ---------------------------------------------------------------------------
__global__ __launch_bounds__(256)
void conv_f16(const float* __restrict__ in, __half* __restrict__ outp, int n4)
{
    int i = blockIdx.x * 256 + threadIdx.x;
    const int stride = gridDim.x * 256;
    for (; i < n4; i += stride) {
        float4 v = ((const float4*)in)[i];
        uint2 o;
        o.x = pack_h2(v.x, v.y);
        o.y = pack_h2(v.z, v.w);
        ((uint2*)outp)[i] = o;
    }
}

// ---------------------------------------------------------------------------
// FP16 GEMM (fp32 accumulate): C[M,N] = A[M,K]*B[N,K]^T (+bias), A,B half.
// 128x128 tile, BK=32, 8 warps (2x4), warp tile 64x32, m16n8k16.
// 4-stage cp.async; smem rows of 40 halves (32 data + 8 pad) -> conflict-free.
// ---------------------------------------------------------------------------
#define GSTAGES 4
#define BKH     32
#define ROWB    80                      // bytes per smem row (40 halves)
#define STG_B   (128 * ROWB)            // 10240 B per operand per stage
#define GEMM_SMEM (GSTAGES * 2 * STG_B) // 81920 B

__global__ __launch_bounds__(256, 2)
void gemm_f16(const __half* __restrict__ A, const __half* __restrict__ B,
              const float* __restrict__ bias, float* __restrict__ C,
              int M, int N, int K)
{
    extern __shared__ char dyn_smem[];
    const uint32_t data = smem_u32(dyn_smem);

    const int tid  = threadIdx.x;
    const int lane = tid & 31;
    const int wid  = tid >> 5;
    const int bm   = blockIdx.y * 128;
    const int bn   = blockIdx.x * 128;
    const int wm   = (wid >> 2) * 64;
    const int wn   = (wid & 3) * 32;
    const int lr   = lane >> 2;
    const int lc   = lane & 3;

    float acc[4][4][4];
    #pragma unroll
    for (int i = 0; i < 4; i++)
        #pragma unroll
        for (int j = 0; j < 4; j++)
            #pragma unroll
            for (int r = 0; r < 4; r++) acc[i][j][r] = 0.0f;

    // fill: per stage 1024 chunks of 16B (A 512 then B 512), 4 per thread
    #define GFILL(stg, kc) do {                                             \
        _Pragma("unroll")                                                   \
        for (int i_ = 0; i_ < 4; i_++) {                                    \
            const int idx_ = tid + i_ * 256;                                \
            const int op_  = idx_ >> 9;                                     \
            const int r_   = (idx_ & 511) >> 2;                             \
            const int q_   = idx_ & 3;                                      \
            const __half* g_ = (op_ ? B + (size_t)(bn + r_) * K             \
                                    : A + (size_t)(bm + r_) * K)            \
                               + (kc) * BKH + q_ * 8;                       \
            cp_async16(data + (stg) * 2 * STG_B + op_ * STG_B               \
                       + r_ * ROWB + q_ * 16, g_);                          \
        }                                                                   \
    } while (0)

    #pragma unroll
    for (int s = 0; s < GSTAGES - 1; s++) { GFILL(s, s); cp_commit(); }

    const int nchunk = K / BKH;   // 32
    const uint32_t* smw = (const uint32_t*)dyn_smem;

    for (int it = 0; it < nchunk; it++) {
        cp_wait<GSTAGES - 2>();
        __syncthreads();

        const int nxt = it + GSTAGES - 1;
        if (nxt < nchunk) GFILL(nxt % GSTAGES, nxt);
        cp_commit();

        const int st = it % GSTAGES;
        const uint32_t* as = smw + st * 2 * (STG_B / 4);
        const uint32_t* bs = as + STG_B / 4;

        #pragma unroll
        for (int ks = 0; ks < 2; ks++) {
            const int kw = ks * 8 + lc;             // word offset in row
            uint32_t afr[4][4], bfr[4][2];
            #pragma unroll
            for (int mt = 0; mt < 4; mt++) {
                const int r0 = (wm + mt * 16 + lr) * 20;
                afr[mt][0] = as[r0 + kw];
                afr[mt][1] = as[r0 + 160 + kw];       // row +8
                afr[mt][2] = as[r0 + kw + 4];         // col +8 halves
                afr[mt][3] = as[r0 + 160 + kw + 4];
            }
            #pragma unroll
            for (int nt = 0; nt < 4; nt++) {
                const int rn = (wn + nt * 8 + lr) * 20;
                bfr[nt][0] = bs[rn + kw];
                bfr[nt][1] = bs[rn + kw + 4];
            }
            #pragma unroll
            for (int mt = 0; mt < 4; mt++)
                #pragma unroll
                for (int nt = 0; nt < 4; nt++)
                    mma_f16(acc[mt][nt], afr[mt], bfr[nt][0], bfr[nt][1]);
        }
    }

    #pragma unroll
    for (int mt = 0; mt < 4; mt++) {
        const int row = bm + wm + mt * 16 + lr;
        #pragma unroll
        for (int nt = 0; nt < 4; nt++) {
            const int col = bn + wn + nt * 8 + lc * 2;
            float b0 = 0.f, b1 = 0.f;
            if (bias) { b0 = bias[col]; b1 = bias[col + 1]; }
            float2 v0 = make_float2(acc[mt][nt][0] + b0, acc[mt][nt][1] + b1);
            float2 v1 = make_float2(acc[mt][nt][2] + b0, acc[mt][nt][3] + b1);
            *(float2*)(C + (size_t)row * N + col)       = v0;
            *(float2*)(C + (size_t)(row + 8) * N + col) = v1;
        }
    }
}

// ---------------------------------------------------------------------------
// Per-head LayerNorm (+ fold in E^-0.25 scale). One warp per 64-elem segment.
// ---------------------------------------------------------------------------
__global__ __launch_bounds__(256)
void ln_head(float* __restrict__ X, const float* __restrict__ g,
             const float* __restrict__ b, float scale)
{
    const int seg  = blockIdx.x * 8 + (threadIdx.x >> 5);
    const int lane = threadIdx.x & 31;
    float2* p = (float2*)(X + (size_t)seg * HSZ) + lane;
    float2 v = *p;
    float sum = v.x + v.y;
    float sq  = v.x * v.x + v.y * v.y;
    #pragma unroll
    for (int o = 16; o; o >>= 1) {
        sum += __shfl_xor_sync(0xffffffffu, sum, o);
        sq  += __shfl_xor_sync(0xffffffffu, sq,  o);
    }
    const float mean = sum * (1.0f / 64.0f);
    const float var  = sq * (1.0f / 64.0f) - mean * mean;
    const float r    = rsqrtf(var + 1e-5f);
    const float gx = g[2 * lane], gy = g[2 * lane + 1];
    const float bx = b[2 * lane], by = b[2 * lane + 1];
    v.x = ((v.x - mean) * r * gx + bx) * scale;
    v.y = ((v.y - mean) * r * gy + by) * scale;
    *p = v;
}

// ---------------------------------------------------------------------------
// FP16 tensor-core causal flash attention. 4 warps, BR=64 (16 rows/warp),
// BC=64, D=64. Tiles in half: Ks rows=key 72-half stride, Vt TRANSPOSED
// (rows=dim). P (half) overwrites Ks. Softmax fp32. Output written as half.
// ---------------------------------------------------------------------------
#define FSTR 36   // row stride in 32-bit words (72 halves)

__global__ __launch_bounds__(128)
void flash_attn_f16(const float* __restrict__ Q, const float* __restrict__ K,
                    const float* __restrict__ V, __half* __restrict__ Oh)
{
    const int qb = blockIdx.x;
    const int h  = blockIdx.y;
    const int b  = blockIdx.z;
    const int tid  = threadIdx.x;
    const int lane = tid & 31;
    const int wid  = tid >> 5;
    const int wm   = wid * 16;
    const int lr   = lane >> 2;
    const int lc   = lane & 3;

    __shared__ uint32_t KsW[64 * FSTR];   // K tile / Q staging / P tile
    __shared__ uint32_t VtW[64 * FSTR];   // V transposed (rows = dim)

    const size_t base = (size_t)b * SEQ * EMB + (size_t)h * HSZ;

    // ---- stage Q tile (half) in KsW, build A-fragments ----
    {
        const float4* qg = (const float4*)(Q + base + (size_t)(qb * 64) * EMB);
        for (int i = tid; i < 64 * 16; i += 128) {
            const int r = i >> 4, c = i & 15;
            float4 v = qg[(size_t)r * (EMB / 4) + c];
            KsW[r * FSTR + c * 2]     = pack_h2(v.x, v.y);
            KsW[r * FSTR + c * 2 + 1] = pack_h2(v.z, v.w);
        }
    }
    __syncthreads();

    uint32_t qa[4][4];
    #pragma unroll
    for (int kk = 0; kk < 4; kk++) {
        const int r0 = (wm + lr) * FSTR + kk * 8 + lc;
        qa[kk][0] = KsW[r0];
        qa[kk][1] = KsW[r0 + 8 * FSTR];
        qa[kk][2] = KsW[r0 + 4];
        qa[kk][3] = KsW[r0 + 8 * FSTR + 4];
    }
    __syncthreads();

    float o[8][4];
    #pragma unroll
    for (int i = 0; i < 8; i++)
        #pragma unroll
        for (int j = 0; j < 4; j++) o[i][j] = 0.0f;
    float m0 = -INFINITY, m1 = -INFINITY, l0 = 0.0f, l1 = 0.0f;

    const float4* kg0 = (const float4*)(K + base);
    const float4* vg0 = (const float4*)(V + base);
    __half* Vth = (__half*)VtW;

    for (int kt = 0; kt <= qb; kt++) {
        // ---- load K tile (rows=key) and V tile transposed (rows=dim) ----
        for (int i = tid; i < 64 * 16; i += 128) {
            const int r = i >> 4, c = i & 15;        // key r, dim group c
            const size_t gidx = (size_t)(kt * 64 + r) * (EMB / 4) + c;
            float4 kv = kg0[gidx];
            KsW[r * FSTR + c * 2]     = pack_h2(kv.x, kv.y);
            KsW[r * FSTR + c * 2 + 1] = pack_h2(kv.z, kv.w);
            float4 vv = vg0[gidx];
            Vth[(c * 4 + 0) * 2 * FSTR + r] = __float2half_rn(vv.x);
            Vth[(c * 4 + 1) * 2 * FSTR + r] = __float2half_rn(vv.y);
            Vth[(c * 4 + 2) * 2 * FSTR + r] = __float2half_rn(vv.z);
            Vth[(c * 4 + 3) * 2 * FSTR + r] = __float2half_rn(vv.w);
        }
        __syncthreads();

        // ---- S = Q K^T  (32 mmas/warp) ----
        float s[8][4];
        #pragma unroll
        for (int nt = 0; nt < 8; nt++)
            #pragma unroll
            for (int j = 0; j < 4; j++) s[nt][j] = 0.0f;

        #pragma unroll
        for (int kk = 0; kk < 4; kk++) {
            #pragma unroll
            for (int nt = 0; nt < 8; nt++) {
                const int rb = (nt * 8 + lr) * FSTR + kk * 8 + lc;
                mma_f16(s[nt], qa[kk], KsW[rb], KsW[rb + 4]);
            }
        }

        // ---- causal mask on diagonal tile ----
        if (kt == qb) {
            const int row0 = wm + lr;
            #pragma unroll
            for (int nt = 0; nt < 8; nt++) {
                const int col = nt * 8 + 2 * lc;
                if (col     > row0)     s[nt][0] = -1e30f;
                if (col + 1 > row0)     s[nt][1] = -1e30f;
                if (col     > row0 + 8) s[nt][2] = -1e30f;
                if (col + 1 > row0 + 8) s[nt][3] = -1e30f;
            }
        }

        // ---- online softmax (fp32) ----
        float mx0 = -INFINITY, mx1 = -INFINITY;
        #pragma unroll
        for (int nt = 0; nt < 8; nt++) {
            mx0 = fmaxf(mx0, fmaxf(s[nt][0], s[nt][1]));
            mx1 = fmaxf(mx1, fmaxf(s[nt][2], s[nt][3]));
        }
        mx0 = fmaxf(mx0, __shfl_xor_sync(0xffffffffu, mx0, 1));
        mx0 = fmaxf(mx0, __shfl_xor_sync(0xffffffffu, mx0, 2));
        mx1 = fmaxf(mx1, __shfl_xor_sync(0xffffffffu, mx1, 1));
        mx1 = fmaxf(mx1, __shfl_xor_sync(0xffffffffu, mx1, 2));

        const float m0n = fmaxf(m0, mx0);
        const float m1n = fmaxf(m1, mx1);
        const float c0 = __expf(m0 - m0n);
        const float c1 = __expf(m1 - m1n);
        m0 = m0n; m1 = m1n;
        l0 *= c0;  l1 *= c1;
        #pragma unroll
        for (int nt = 0; nt < 8; nt++) {
            o[nt][0] *= c0; o[nt][1] *= c0;
            o[nt][2] *= c1; o[nt][3] *= c1;
        }

        uint32_t ph[8][2];
        #pragma unroll
        for (int nt = 0; nt < 8; nt++) {
            float p0 = __expf(s[nt][0] - m0);
            float p1 = __expf(s[nt][1] - m0);
            float p2 = __expf(s[nt][2] - m1);
            float p3 = __expf(s[nt][3] - m1);
            l0 += p0 + p1;
            l1 += p2 + p3;
            ph[nt][0] = pack_h2(p0, p1);
            ph[nt][1] = pack_h2(p2, p3);
        }

        // ---- write P (half) over K buffer ----
        __syncthreads();
        {
            const int r0 = wm + lr;
            #pragma unroll
            for (int nt = 0; nt < 8; nt++) {
                KsW[r0 * FSTR + nt * 4 + lc]       = ph[nt][0];
                KsW[(r0 + 8) * FSTR + nt * 4 + lc] = ph[nt][1];
            }
        }
        __syncwarp();

        // ---- O += P V  (32 mmas/warp) ----
        #pragma unroll
        for (int kk = 0; kk < 4; kk++) {
            uint32_t pa[4];
            const int r0 = (wm + lr) * FSTR + kk * 8 + lc;
            pa[0] = KsW[r0];
            pa[1] = KsW[r0 + 8 * FSTR];
            pa[2] = KsW[r0 + 4];
            pa[3] = KsW[r0 + 8 * FSTR + 4];
            #pragma unroll
            for (int ntd = 0; ntd < 8; ntd++) {
                const int vb = (ntd * 8 + lr) * FSTR + kk * 8 + lc;
                mma_f16(o[ntd], pa, VtW[vb], VtW[vb + 4]);
            }
        }
        __syncthreads();
    }

    // ---- finalize: reduce l, normalize, store as half ----
    l0 += __shfl_xor_sync(0xffffffffu, l0, 1);
    l0 += __shfl_xor_sync(0xffffffffu, l0, 2);
    l1 += __shfl_xor_sync(0xffffffffu, l1, 1);
    l1 += __shfl_xor_sync(0xffffffffu, l1, 2);
    const float i0 = 1.0f / l0;
    const float i1 = 1.0f / l1;

    const int row0 = qb * 64 + wm + lr;
    const size_t obase = (size_t)b * SEQ * EMB + (size_t)h * HSZ;
    uint32_t* op0 = (uint32_t*)(Oh + obase + (size_t)row0 * EMB);
    uint32_t* op1 = (uint32_t*)(Oh + obase + (size_t)(row0 + 8) * EMB);
    #pragma unroll
    for (int ntd = 0; ntd < 8; ntd++) {
        const int colw = ntd * 4 + lc;   // u32 index (2 halves)
        op0[colw] = pack_h2(o[ntd][0] * i0, o[ntd][1] * i0);
        op1[colw] = pack_h2(o[ntd][2] * i1, o[ntd][3] * i1);
    }
}

// ---------------------------------------------------------------------------
extern "C" void kernel_launch(void* const* d_in, const int* in_sizes, int n_in,
                              void* d_out, int out_size)
{
    const float* x   = (const float*)d_in[0];
    const float* Wk  = (const float*)d_in[1];
    const float* Wq  = (const float*)d_in[2];
    const float* Wv  = (const float*)d_in[3];
    const float* Wo  = (const float*)d_in[4];
    const float* bo  = (const float*)d_in[5];
    const float* kg  = (const float*)d_in[6];
    const float* kb  = (const float*)d_in[7];
    const float* qg  = (const float*)d_in[8];
    const float* qb  = (const float*)d_in[9];
    float* out = (float*)d_out;

    float* sbase = nullptr;
    cudaGetSymbolAddress((void**)&sbase, g_scratch);
    const size_t MB1 = 1024ull * 1024ull;
    __half* xh  = (__half*)(sbase);                 // 8M halves = 4M floats
    __half* wkh = (__half*)(sbase + 4 * MB1);       // 1M halves = .5M floats
    __half* wqh = (__half*)(sbase + 4 * MB1 + MB1 / 2);
    __half* wvh = (__half*)(sbase + 5 * MB1);
    __half* woh = (__half*)(sbase + 5 * MB1 + MB1 / 2);
    float*  gk  = sbase + 6 * MB1;                  // 8M floats each
    float*  gq  = sbase + 14 * MB1;
    float*  gv  = sbase + 22 * MB1;
    __half* gyh = (__half*)(sbase + 30 * MB1);      // 8M halves

    const float SCALE = 0.17677669529663687f;  // 1024^(-1/4)

    cudaFuncSetAttribute(gemm_f16,
                         cudaFuncAttributeMaxDynamicSharedMemorySize, GEMM_SMEM);

    // convert inputs to fp16 (RNE)
    conv_f16<<<512, 256>>>(x,  xh,  MTOK * EMB / 4);
    conv_f16<<<256, 256>>>(Wk, wkh, EMB * EMB / 4);
    conv_f16<<<256, 256>>>(Wq, wqh, EMB * EMB / 4);
    conv_f16<<<256, 256>>>(Wv, wvh, EMB * EMB / 4);
    conv_f16<<<256, 256>>>(Wo, woh, EMB * EMB / 4);

    dim3 gemmGrid(EMB / 128, MTOK / 128);      // (8, 64)
    gemm_f16<<<gemmGrid, 256, GEMM_SMEM>>>(xh, wkh, nullptr, gk, MTOK, EMB, EMB);
    gemm_f16<<<gemmGrid, 256, GEMM_SMEM>>>(xh, wqh, nullptr, gq, MTOK, EMB, EMB);
    gemm_f16<<<gemmGrid, 256, GEMM_SMEM>>>(xh, wvh, nullptr, gv, MTOK, EMB, EMB);

    const int nseg = MTOK * HEADS;             // 131072
    ln_head<<<nseg / 8, 256>>>(gk, kg, kb, SCALE);
    ln_head<<<nseg / 8, 256>>>(gq, qg, qb, SCALE);

    dim3 attnGrid(SEQ / 64, HEADS, BATCH);     // (32, 16, 4)
    flash_attn_f16<<<attnGrid, 128>>>(gq, gk, gv, gyh);

    gemm_f16<<<gemmGrid, 256, GEMM_SMEM>>>(gyh, woh, bo, out, MTOK, EMB, EMB);
}

// round 7
// speedup vs baseline: 6.9815x; 1.4016x over previous
#include <cuda_runtime.h>
#include <cuda_fp16.h>
#include <math.h>
#include <stdint.h>

#define EMB   1024
#define HEADS 16
#define HSZ   64
#define BATCH 4
#define SEQ   2048
#define MTOK  (BATCH * SEQ)   // 8192 token rows

// scratch floats: xh(4M) wk/wq/wv/wo(4x.5M) gkh gqh gvh gyh(4x4M) = 22M floats
__device__ float g_scratch[22ull * 1024 * 1024];

__device__ __forceinline__ void mma_f16(float* c, const uint32_t* a,
                                        uint32_t b0, uint32_t b1) {
    asm volatile(
        "mma.sync.aligned.m16n8k16.row.col.f32.f16.f16.f32 "
        "{%0,%1,%2,%3}, {%4,%5,%6,%7}, {%8,%9}, {%0,%1,%2,%3};\n"
        : "+f"(c[0]), "+f"(c[1]), "+f"(c[2]), "+f"(c[3])
        : "r"(a[0]), "r"(a[1]), "r"(a[2]), "r"(a[3]), "r"(b0), "r"(b1));
}
__device__ __forceinline__ void cp_async16(uint32_t saddr, const void* gaddr) {
    asm volatile("cp.async.cg.shared.global [%0], [%1], 16;\n"
                 :: "r"(saddr), "l"(gaddr));
}
__device__ __forceinline__ void cp_commit() {
    asm volatile("cp.async.commit_group;\n");
}
template <int N>
__device__ __forceinline__ void cp_wait() {
    asm volatile("cp.async.wait_group %0;\n" :: "n"(N));
}
__device__ __forceinline__ uint32_t smem_u32(const void* p) {
    uint32_t a;
    asm("{ .reg .u64 t; cvta.to.shared.u64 t, %1; cvt.u32.u64 %0, t; }"
        : "=r"(a) : "l"(p));
    return a;
}
__device__ __forceinline__ uint32_t pack_h2(float a, float b) {
    __half2 h = __floats2half2_rn(a, b);
    return *(uint32_t*)&h;
}
__device__ __forceinline__ void ldsm4(uint32_t& r0, uint32_t& r1,
                                      uint32_t& r2, uint32_t& r3, uint32_t a) {
    asm volatile("ldmatrix.sync.aligned.m8n8.x4.shared.b16 {%0,%1,%2,%3}, [%4];"
                 : "=r"(r0), "=r"(r1), "=r"(r2), "=r"(r3) : "r"(a));
}
__device__ __forceinline__ void ldsm4t(uint32_t& r0, uint32_t& r1,
                                       uint32_t& r2, uint32_t& r3, uint32_t a) {
    asm volatile("ldmatrix.sync.aligned.m8n8.x4.trans.shared.b16 {%0,%1,%2,%3}, [%4];"
                 : "=r"(r0), "=r"(r1), "=r"(r2), "=r"(r3) : "r"(a));
}

// ---------------------------------------------------------------------------
// fp32 -> fp16 convert (RNE)
// ---------------------------------------------------------------------------
__global__ __launch_bounds__(256)
void conv_f16(const float* __restrict__ in, __half* __restrict__ outp, int n4)
{
    int i = blockIdx.x * 256 + threadIdx.x;
    const int stride = gridDim.x * 256;
    for (; i < n4; i += stride) {
        float4 v = ((const float4*)in)[i];
        uint2 o;
        o.x = pack_h2(v.x, v.y);
        o.y = pack_h2(v.z, v.w);
        ((uint2*)outp)[i] = o;
    }
}

// ---------------------------------------------------------------------------
// FP16 GEMM core (fp32 accumulate): C = A[M,K]*B[N,K]^T. Two epilogues:
// gemm_f16  -> fp32 C + bias;  gemm_f16h -> fp16 C (no bias).
// 128x128 tile, BK=32, 8 warps, m16n8k16, 4-stage cp.async.
// ---------------------------------------------------------------------------
#define GSTAGES 4
#define BKH     32
#define ROWB    80
#define STG_B   (128 * ROWB)
#define GEMM_SMEM (GSTAGES * 2 * STG_B) // 81920 B

#define GEMM_BODY                                                             \
    extern __shared__ char dyn_smem[];                                        \
    const uint32_t data = smem_u32(dyn_smem);                                 \
    const int tid  = threadIdx.x;                                             \
    const int lane = tid & 31;                                                \
    const int wid  = tid >> 5;                                                \
    const int bm   = blockIdx.y * 128;                                        \
    const int bn   = blockIdx.x * 128;                                        \
    const int wm   = (wid >> 2) * 64;                                         \
    const int wn   = (wid & 3) * 32;                                          \
    const int lr   = lane >> 2;                                               \
    const int lc   = lane & 3;                                                \
    float acc[4][4][4];                                                       \
    _Pragma("unroll")                                                         \
    for (int i = 0; i < 4; i++)                                               \
        _Pragma("unroll")                                                     \
        for (int j = 0; j < 4; j++)                                           \
            _Pragma("unroll")                                                 \
            for (int r = 0; r < 4; r++) acc[i][j][r] = 0.0f;                  \
    _Pragma("unroll")                                                         \
    for (int s = 0; s < GSTAGES - 1; s++) { GFILL(s, s); cp_commit(); }       \
    const int nchunk = K / BKH;                                               \
    const uint32_t* smw = (const uint32_t*)dyn_smem;                          \
    for (int it = 0; it < nchunk; it++) {                                     \
        cp_wait<GSTAGES - 2>();                                               \
        __syncthreads();                                                      \
        const int nxt = it + GSTAGES - 1;                                     \
        if (nxt < nchunk) GFILL(nxt % GSTAGES, nxt);                          \
        cp_commit();                                                          \
        const int st = it % GSTAGES;                                          \
        const uint32_t* as = smw + st * 2 * (STG_B / 4);                      \
        const uint32_t* bs = as + STG_B / 4;                                  \
        _Pragma("unroll")                                                     \
        for (int ks = 0; ks < 2; ks++) {                                      \
            const int kw = ks * 8 + lc;                                       \
            uint32_t afr[4][4], bfr[4][2];                                    \
            _Pragma("unroll")                                                 \
            for (int mt = 0; mt < 4; mt++) {                                  \
                const int r0 = (wm + mt * 16 + lr) * 20;                      \
                afr[mt][0] = as[r0 + kw];                                     \
                afr[mt][1] = as[r0 + 160 + kw];                               \
                afr[mt][2] = as[r0 + kw + 4];                                 \
                afr[mt][3] = as[r0 + 160 + kw + 4];                           \
            }                                                                 \
            _Pragma("unroll")                                                 \
            for (int nt = 0; nt < 4; nt++) {                                  \
                const int rn = (wn + nt * 8 + lr) * 20;                       \
                bfr[nt][0] = bs[rn + kw];                                     \
                bfr[nt][1] = bs[rn + kw + 4];                                 \
            }                                                                 \
            _Pragma("unroll")                                                 \
            for (int mt = 0; mt < 4; mt++)                                    \
                _Pragma("unroll")                                             \
                for (int nt = 0; nt < 4; nt++)                                \
                    mma_f16(acc[mt][nt], afr[mt], bfr[nt][0], bfr[nt][1]);    \
        }                                                                     \
    }

#define GFILL(stg, kc) do {                                                  \
    _Pragma("unroll")                                                        \
    for (int i_ = 0; i_ < 4; i_++) {                                         \
        const int idx_ = tid + i_ * 256;                                     \
        const int op_  = idx_ >> 9;                                          \
        const int r_   = (idx_ & 511) >> 2;                                  \
        const int q_   = idx_ & 3;                                           \
        const __half* g_ = (op_ ? B + (size_t)(bn + r_) * K                  \
                                : A + (size_t)(bm + r_) * K)                 \
                           + (kc) * BKH + q_ * 8;                            \
        cp_async16(data + (stg) * 2 * STG_B + op_ * STG_B                    \
                   + r_ * ROWB + q_ * 16, g_);                               \
    }                                                                        \
} while (0)

__global__ __launch_bounds__(256, 2)
void gemm_f16(const __half* __restrict__ A, const __half* __restrict__ B,
              const float* __restrict__ bias, float* __restrict__ C,
              int M, int N, int K)
{
    GEMM_BODY
    #pragma unroll
    for (int mt = 0; mt < 4; mt++) {
        const int row = bm + wm + mt * 16 + lr;
        #pragma unroll
        for (int nt = 0; nt < 4; nt++) {
            const int col = bn + wn + nt * 8 + lc * 2;
            float b0 = 0.f, b1 = 0.f;
            if (bias) { b0 = bias[col]; b1 = bias[col + 1]; }
            *(float2*)(C + (size_t)row * N + col) =
                make_float2(acc[mt][nt][0] + b0, acc[mt][nt][1] + b1);
            *(float2*)(C + (size_t)(row + 8) * N + col) =
                make_float2(acc[mt][nt][2] + b0, acc[mt][nt][3] + b1);
        }
    }
}

__global__ __launch_bounds__(256, 2)
void gemm_f16h(const __half* __restrict__ A, const __half* __restrict__ B,
               __half* __restrict__ C, int M, int N, int K)
{
    GEMM_BODY
    #pragma unroll
    for (int mt = 0; mt < 4; mt++) {
        const int row = bm + wm + mt * 16 + lr;
        #pragma unroll
        for (int nt = 0; nt < 4; nt++) {
            const int col = bn + wn + nt * 8 + lc * 2;
            *(uint32_t*)(C + (size_t)row * N + col) =
                pack_h2(acc[mt][nt][0], acc[mt][nt][1]);
            *(uint32_t*)(C + (size_t)(row + 8) * N + col) =
                pack_h2(acc[mt][nt][2], acc[mt][nt][3]);
        }
    }
}

// ---------------------------------------------------------------------------
// Per-head LayerNorm on fp16 data (fp32 math), folds in E^-0.25 scale.
// ---------------------------------------------------------------------------
__global__ __launch_bounds__(256)
void ln_head_h(__half* __restrict__ X, const float* __restrict__ g,
               const float* __restrict__ b, float scale)
{
    const int seg  = blockIdx.x * 8 + (threadIdx.x >> 5);
    const int lane = threadIdx.x & 31;
    __half2* p = (__half2*)(X + (size_t)seg * HSZ) + lane;
    float2 v = __half22float2(*p);
    float sum = v.x + v.y;
    float sq  = v.x * v.x + v.y * v.y;
    #pragma unroll
    for (int o = 16; o; o >>= 1) {
        sum += __shfl_xor_sync(0xffffffffu, sum, o);
        sq  += __shfl_xor_sync(0xffffffffu, sq,  o);
    }
    const float mean = sum * (1.0f / 64.0f);
    const float var  = sq * (1.0f / 64.0f) - mean * mean;
    const float r    = rsqrtf(var + 1e-5f);
    const float gx = g[2 * lane], gy = g[2 * lane + 1];
    const float bx = b[2 * lane], by = b[2 * lane + 1];
    *p = __floats2half2_rn(((v.x - mean) * r * gx + bx) * scale,
                           ((v.y - mean) * r * gy + by) * scale);
}

// ---------------------------------------------------------------------------
// FP16 flash attention v2: all-half I/O, cp.async double-buffered K/V tiles,
// P in registers (S-fragment == A-fragment layout), V frags via ldmatrix.trans.
// 4 warps, BR=64 (16 rows/warp), BC=64, D=64. Softmax fp32.
// ---------------------------------------------------------------------------
#define FROWB 144   // smem row: 64 halves data + 8 pad

__global__ __launch_bounds__(128)
void flash_attn2(const __half* __restrict__ Q, const __half* __restrict__ K,
                 const __half* __restrict__ V, __half* __restrict__ Oh)
{
    __shared__ __align__(16) char kvbuf[2][2][64 * FROWB];  // [slot][K/V]

    const int qb = blockIdx.x;
    const int h  = blockIdx.y;
    const int b  = blockIdx.z;
    const int tid  = threadIdx.x;
    const int lane = tid & 31;
    const int wid  = tid >> 5;
    const int wm   = wid * 16;
    const int lr   = lane >> 2;
    const int lc   = lane & 3;

    const size_t base = (size_t)b * SEQ * EMB + (size_t)h * HSZ;
    const __half* Qg = Q + base + (size_t)(qb * 64) * EMB;
    const __half* Kg = K + base;
    const __half* Vg = V + base;

    uint32_t kb_[2], vb_[2];
    kb_[0] = smem_u32(kvbuf[0][0]); vb_[0] = smem_u32(kvbuf[0][1]);
    kb_[1] = smem_u32(kvbuf[1][0]); vb_[1] = smem_u32(kvbuf[1][1]);

    // ---- stage Q (half) through slot0-K, extract A-fragments via ldmatrix ----
    #pragma unroll
    for (int i = 0; i < 4; i++) {
        const int idx = tid + i * 128;
        const int r = idx >> 3, q = idx & 7;
        cp_async16(kb_[0] + r * FROWB + q * 16, Qg + (size_t)r * EMB + q * 8);
    }
    cp_commit();
    cp_wait<0>();
    __syncthreads();

    const uint32_t qrow = wm + ((lane >> 3) & 1) * 8 + (lane & 7);
    const uint32_t qoff = ((lane >> 4) ? 16u : 0u);
    uint32_t qa[4][4];
    #pragma unroll
    for (int kk = 0; kk < 4; kk++)
        ldsm4(qa[kk][0], qa[kk][1], qa[kk][2], qa[kk][3],
              kb_[0] + qrow * FROWB + kk * 32 + qoff);
    __syncthreads();

    // ---- prefetch K/V tiles 0 and 1 ----
    #define AFILL(kt_, slot_) do {                                           \
        _Pragma("unroll")                                                    \
        for (int i_ = 0; i_ < 8; i_++) {                                     \
            const int idx_ = tid + i_ * 128;                                 \
            const int op_  = idx_ >> 9;                                      \
            const int r_   = (idx_ >> 3) & 63;                               \
            const int q_   = idx_ & 7;                                       \
            const __half* g_ = (op_ ? Vg : Kg)                               \
                + (size_t)((kt_) * 64 + r_) * EMB + q_ * 8;                  \
            cp_async16((op_ ? vb_[slot_] : kb_[slot_]) + r_ * FROWB + q_ * 16, g_); \
        }                                                                    \
    } while (0)

    AFILL(0, 0);
    cp_commit();
    if (qb >= 1) AFILL(1, 1);
    cp_commit();

    float o[8][4];
    #pragma unroll
    for (int i = 0; i < 8; i++)
        #pragma unroll
        for (int j = 0; j < 4; j++) o[i][j] = 0.0f;
    float m0 = -INFINITY, m1 = -INFINITY, l0 = 0.0f, l1 = 0.0f;

    const uint32_t vrow = ((lane >> 3) & 1) * 8 + (lane & 7);
    const uint32_t voff = ((lane >> 4) ? 16u : 0u);

    for (int kt = 0; kt <= qb; kt++) {
        const int slot = kt & 1;
        cp_wait<1>();
        __syncthreads();

        // ---- S = Q K^T ----
        const uint32_t* ks = (const uint32_t*)kvbuf[slot][0];
        float s[8][4];
        #pragma unroll
        for (int nt = 0; nt < 8; nt++)
            #pragma unroll
            for (int j = 0; j < 4; j++) s[nt][j] = 0.0f;

        #pragma unroll
        for (int kk = 0; kk < 4; kk++) {
            #pragma unroll
            for (int nt = 0; nt < 8; nt++) {
                const int rb = (nt * 8 + lr) * 36 + kk * 8 + lc;
                mma_f16(s[nt], qa[kk], ks[rb], ks[rb + 4]);
            }
        }

        // ---- causal mask on diagonal tile ----
        if (kt == qb) {
            const int row0 = wm + lr;
            #pragma unroll
            for (int nt = 0; nt < 8; nt++) {
                const int col = nt * 8 + 2 * lc;
                if (col     > row0)     s[nt][0] = -1e30f;
                if (col + 1 > row0)     s[nt][1] = -1e30f;
                if (col     > row0 + 8) s[nt][2] = -1e30f;
                if (col + 1 > row0 + 8) s[nt][3] = -1e30f;
            }
        }

        // ---- online softmax (fp32), P stays in registers ----
        float mx0 = -INFINITY, mx1 = -INFINITY;
        #pragma unroll
        for (int nt = 0; nt < 8; nt++) {
            mx0 = fmaxf(mx0, fmaxf(s[nt][0], s[nt][1]));
            mx1 = fmaxf(mx1, fmaxf(s[nt][2], s[nt][3]));
        }
        mx0 = fmaxf(mx0, __shfl_xor_sync(0xffffffffu, mx0, 1));
        mx0 = fmaxf(mx0, __shfl_xor_sync(0xffffffffu, mx0, 2));
        mx1 = fmaxf(mx1, __shfl_xor_sync(0xffffffffu, mx1, 1));
        mx1 = fmaxf(mx1, __shfl_xor_sync(0xffffffffu, mx1, 2));

        const float m0n = fmaxf(m0, mx0);
        const float m1n = fmaxf(m1, mx1);
        const float c0 = __expf(m0 - m0n);
        const float c1 = __expf(m1 - m1n);
        m0 = m0n; m1 = m1n;
        l0 *= c0;  l1 *= c1;
        #pragma unroll
        for (int nt = 0; nt < 8; nt++) {
            o[nt][0] *= c0; o[nt][1] *= c0;
            o[nt][2] *= c1; o[nt][3] *= c1;
        }
        #pragma unroll
        for (int nt = 0; nt < 8; nt++) {
            s[nt][0] = __expf(s[nt][0] - m0);
            s[nt][1] = __expf(s[nt][1] - m0);
            s[nt][2] = __expf(s[nt][2] - m1);
            s[nt][3] = __expf(s[nt][3] - m1);
            l0 += s[nt][0] + s[nt][1];
            l1 += s[nt][2] + s[nt][3];
        }

        // ---- O += P V : P fragments packed from s, V via ldmatrix.trans ----
        const uint32_t vsl = vb_[slot];
        #pragma unroll
        for (int kk = 0; kk < 4; kk++) {
            uint32_t pa[4];
            pa[0] = pack_h2(s[2 * kk][0],     s[2 * kk][1]);
            pa[1] = pack_h2(s[2 * kk][2],     s[2 * kk][3]);
            pa[2] = pack_h2(s[2 * kk + 1][0], s[2 * kk + 1][1]);
            pa[3] = pack_h2(s[2 * kk + 1][2], s[2 * kk + 1][3]);
            const uint32_t vaddr0 = vsl + (kk * 16 + vrow) * FROWB + voff;
            #pragma unroll
            for (int j = 0; j < 4; j++) {
                uint32_t v0, v1, v2, v3;
                ldsm4t(v0, v1, v2, v3, vaddr0 + j * 32);
                mma_f16(o[2 * j],     pa, v0, v1);
                mma_f16(o[2 * j + 1], pa, v2, v3);
            }
        }

        __syncthreads();
        if (kt + 2 <= qb) AFILL(kt + 2, slot);
        cp_commit();
    }

    // ---- finalize ----
    l0 += __shfl_xor_sync(0xffffffffu, l0, 1);
    l0 += __shfl_xor_sync(0xffffffffu, l0, 2);
    l1 += __shfl_xor_sync(0xffffffffu, l1, 1);
    l1 += __shfl_xor_sync(0xffffffffu, l1, 2);
    const float i0 = 1.0f / l0;
    const float i1 = 1.0f / l1;

    const int row0 = qb * 64 + wm + lr;
    uint32_t* op0 = (uint32_t*)(Oh + base + (size_t)row0 * EMB);
    uint32_t* op1 = (uint32_t*)(Oh + base + (size_t)(row0 + 8) * EMB);
    #pragma unroll
    for (int ntd = 0; ntd < 8; ntd++) {
        const int colw = ntd * 4 + lc;
        op0[colw] = pack_h2(o[ntd][0] * i0, o[ntd][1] * i0);
        op1[colw] = pack_h2(o[ntd][2] * i1, o[ntd][3] * i1);
    }
}

// ---------------------------------------------------------------------------
extern "C" void kernel_launch(void* const* d_in, const int* in_sizes, int n_in,
                              void* d_out, int out_size)
{
    const float* x   = (const float*)d_in[0];
    const float* Wk  = (const float*)d_in[1];
    const float* Wq  = (const float*)d_in[2];
    const float* Wv  = (const float*)d_in[3];
    const float* Wo  = (const float*)d_in[4];
    const float* bo  = (const float*)d_in[5];
    const float* kg  = (const float*)d_in[6];
    const float* kb  = (const float*)d_in[7];
    const float* qg  = (const float*)d_in[8];
    const float* qb  = (const float*)d_in[9];
    float* out = (float*)d_out;

    float* sbase = nullptr;
    cudaGetSymbolAddress((void**)&sbase, g_scratch);
    const size_t MB1 = 1024ull * 1024ull;
    __half* xh  = (__half*)(sbase);                     // 8M halves
    __half* wkh = (__half*)(sbase + 4 * MB1);           // 1M halves
    __half* wqh = (__half*)(sbase + 4 * MB1 + MB1 / 2);
    __half* wvh = (__half*)(sbase + 5 * MB1);
    __half* woh = (__half*)(sbase + 5 * MB1 + MB1 / 2);
    __half* gkh = (__half*)(sbase + 6 * MB1);           // 8M halves each
    __half* gqh = (__half*)(sbase + 10 * MB1);
    __half* gvh = (__half*)(sbase + 14 * MB1);
    __half* gyh = (__half*)(sbase + 18 * MB1);

    const float SCALE = 0.17677669529663687f;  // 1024^(-1/4)

    cudaFuncSetAttribute(gemm_f16,
                         cudaFuncAttributeMaxDynamicSharedMemorySize, GEMM_SMEM);
    cudaFuncSetAttribute(gemm_f16h,
                         cudaFuncAttributeMaxDynamicSharedMemorySize, GEMM_SMEM);

    conv_f16<<<512, 256>>>(x,  xh,  MTOK * EMB / 4);
    conv_f16<<<256, 256>>>(Wk, wkh, EMB * EMB / 4);
    conv_f16<<<256, 256>>>(Wq, wqh, EMB * EMB / 4);
    conv_f16<<<256, 256>>>(Wv, wvh, EMB * EMB / 4);
    conv_f16<<<256, 256>>>(Wo, woh, EMB * EMB / 4);

    dim3 gemmGrid(EMB / 128, MTOK / 128);      // (8, 64)
    gemm_f16h<<<gemmGrid, 256, GEMM_SMEM>>>(xh, wkh, gkh, MTOK, EMB, EMB);
    gemm_f16h<<<gemmGrid, 256, GEMM_SMEM>>>(xh, wqh, gqh, MTOK, EMB, EMB);
    gemm_f16h<<<gemmGrid, 256, GEMM_SMEM>>>(xh, wvh, gvh, MTOK, EMB, EMB);

    const int nseg = MTOK * HEADS;             // 131072
    ln_head_h<<<nseg / 8, 256>>>(gkh, kg, kb, SCALE);
    ln_head_h<<<nseg / 8, 256>>>(gqh, qg, qb, SCALE);

    dim3 attnGrid(SEQ / 64, HEADS, BATCH);     // (32, 16, 4)
    flash_attn2<<<attnGrid, 128>>>(gqh, gkh, gvh, gyh);

    gemm_f16<<<gemmGrid, 256, GEMM_SMEM>>>(gyh, woh, bo, out, MTOK, EMB, EMB);
}

// round 8
// speedup vs baseline: 7.2528x; 1.0389x over previous
#include <cuda_runtime.h>
#include <cuda_fp16.h>
#include <math.h>
#include <stdint.h>

#define EMB   1024
#define HEADS 16
#define HSZ   64
#define BATCH 4
#define SEQ   2048
#define MTOK  (BATCH * SEQ)   // 8192 token rows

// scratch floats: xh(4M) wk/wq/wv/wo(4x.5M) gkh gqh gvh gyh(4x4M) = 22M floats
__device__ float g_scratch[22ull * 1024 * 1024];

__device__ __forceinline__ void mma_f16(float* c, const uint32_t* a,
                                        uint32_t b0, uint32_t b1) {
    asm volatile(
        "mma.sync.aligned.m16n8k16.row.col.f32.f16.f16.f32 "
        "{%0,%1,%2,%3}, {%4,%5,%6,%7}, {%8,%9}, {%0,%1,%2,%3};\n"
        : "+f"(c[0]), "+f"(c[1]), "+f"(c[2]), "+f"(c[3])
        : "r"(a[0]), "r"(a[1]), "r"(a[2]), "r"(a[3]), "r"(b0), "r"(b1));
}
__device__ __forceinline__ void cp_async16(uint32_t saddr, const void* gaddr) {
    asm volatile("cp.async.cg.shared.global [%0], [%1], 16;\n"
                 :: "r"(saddr), "l"(gaddr));
}
__device__ __forceinline__ void cp_commit() {
    asm volatile("cp.async.commit_group;\n");
}
template <int N>
__device__ __forceinline__ void cp_wait() {
    asm volatile("cp.async.wait_group %0;\n" :: "n"(N));
}
__device__ __forceinline__ uint32_t smem_u32(const void* p) {
    uint32_t a;
    asm("{ .reg .u64 t; cvta.to.shared.u64 t, %1; cvt.u32.u64 %0, t; }"
        : "=r"(a) : "l"(p));
    return a;
}
__device__ __forceinline__ uint32_t pack_h2(float a, float b) {
    __half2 h = __floats2half2_rn(a, b);
    return *(uint32_t*)&h;
}
__device__ __forceinline__ void ldsm4(uint32_t& r0, uint32_t& r1,
                                      uint32_t& r2, uint32_t& r3, uint32_t a) {
    asm volatile("ldmatrix.sync.aligned.m8n8.x4.shared.b16 {%0,%1,%2,%3}, [%4];"
                 : "=r"(r0), "=r"(r1), "=r"(r2), "=r"(r3) : "r"(a));
}
__device__ __forceinline__ void ldsm4t(uint32_t& r0, uint32_t& r1,
                                       uint32_t& r2, uint32_t& r3, uint32_t a) {
    asm volatile("ldmatrix.sync.aligned.m8n8.x4.trans.shared.b16 {%0,%1,%2,%3}, [%4];"
                 : "=r"(r0), "=r"(r1), "=r"(r2), "=r"(r3) : "r"(a));
}

// ---------------------------------------------------------------------------
// One-shot fp32 -> fp16 convert of x + all 4 weights (single launch).
// x: 2M float4;  each W: 256K float4.  total 3M float4.
// ---------------------------------------------------------------------------
#define X4  (MTOK * EMB / 4)          // 2097152
#define W4  (EMB * EMB / 4)           // 262144

__global__ __launch_bounds__(256)
void conv_all(const float* __restrict__ x,  const float* __restrict__ Wk,
              const float* __restrict__ Wq, const float* __restrict__ Wv,
              const float* __restrict__ Wo,
              __half* __restrict__ xh,  __half* __restrict__ wkh,
              __half* __restrict__ wqh, __half* __restrict__ wvh,
              __half* __restrict__ woh)
{
    const int total = X4 + 4 * W4;
    int i = blockIdx.x * 256 + threadIdx.x;
    const int stride = gridDim.x * 256;
    for (; i < total; i += stride) {
        const float* src; __half* dst; int off;
        if (i < X4) { src = x; dst = xh; off = i; }
        else {
            const int j = i - X4;
            const int w = j >> 18;            // /W4
            off = j & (W4 - 1);
            src = (w == 0) ? Wk : (w == 1) ? Wq : (w == 2) ? Wv : Wo;
            dst = (w == 0) ? wkh : (w == 1) ? wqh : (w == 2) ? wvh : woh;
        }
        float4 v = ((const float4*)src)[off];
        uint2 o;
        o.x = pack_h2(v.x, v.y);
        o.y = pack_h2(v.z, v.w);
        ((uint2*)dst)[off] = o;
    }
}

// ---------------------------------------------------------------------------
// FP16 GEMM core (fp32 accumulate). Variables A, B, bm, bn, K, N must be in
// scope. 128x128 tile, BK=32, 8 warps, m16n8k16, 4-stage cp.async.
// ---------------------------------------------------------------------------
#define GSTAGES 4
#define BKH     32
#define ROWB    80
#define STG_B   (128 * ROWB)
#define GEMM_SMEM (GSTAGES * 2 * STG_B) // 81920 B

#define GFILL(stg, kc) do {                                                  \
    _Pragma("unroll")                                                        \
    for (int i_ = 0; i_ < 4; i_++) {                                         \
        const int idx_ = tid + i_ * 256;                                     \
        const int op_  = idx_ >> 9;                                          \
        const int r_   = (idx_ & 511) >> 2;                                  \
        const int q_   = idx_ & 3;                                           \
        const __half* g_ = (op_ ? B + (size_t)(bn + r_) * K                  \
                                : A + (size_t)(bm + r_) * K)                 \
                           + (kc) * BKH + q_ * 8;                            \
        cp_async16(data + (stg) * 2 * STG_B + op_ * STG_B                    \
                   + r_ * ROWB + q_ * 16, g_);                               \
    }                                                                        \
} while (0)

#define GEMM_BODY                                                             \
    extern __shared__ char dyn_smem[];                                        \
    const uint32_t data = smem_u32(dyn_smem);                                 \
    const int lane = tid & 31;                                                \
    const int wid  = tid >> 5;                                                \
    const int wm   = (wid >> 2) * 64;                                         \
    const int wn   = (wid & 3) * 32;                                          \
    const int lr   = lane >> 2;                                               \
    const int lc   = lane & 3;                                                \
    float acc[4][4][4];                                                       \
    _Pragma("unroll")                                                         \
    for (int i = 0; i < 4; i++)                                               \
        _Pragma("unroll")                                                     \
        for (int j = 0; j < 4; j++)                                           \
            _Pragma("unroll")                                                 \
            for (int r = 0; r < 4; r++) acc[i][j][r] = 0.0f;                  \
    _Pragma("unroll")                                                         \
    for (int s = 0; s < GSTAGES - 1; s++) { GFILL(s, s); cp_commit(); }       \
    const int nchunk = K / BKH;                                               \
    const uint32_t* smw = (const uint32_t*)dyn_smem;                          \
    for (int it = 0; it < nchunk; it++) {                                     \
        cp_wait<GSTAGES - 2>();                                               \
        __syncthreads();                                                      \
        const int nxt = it + GSTAGES - 1;                                     \
        if (nxt < nchunk) GFILL(nxt % GSTAGES, nxt);                          \
        cp_commit();                                                          \
        const int st = it % GSTAGES;                                          \
        const uint32_t* as = smw + st * 2 * (STG_B / 4);                      \
        const uint32_t* bs = as + STG_B / 4;                                  \
        _Pragma("unroll")                                                     \
        for (int ks = 0; ks < 2; ks++) {                                      \
            const int kw = ks * 8 + lc;                                       \
            uint32_t afr[4][4], bfr[4][2];                                    \
            _Pragma("unroll")                                                 \
            for (int mt = 0; mt < 4; mt++) {                                  \
                const int r0 = (wm + mt * 16 + lr) * 20;                      \
                afr[mt][0] = as[r0 + kw];                                     \
                afr[mt][1] = as[r0 + 160 + kw];                               \
                afr[mt][2] = as[r0 + kw + 4];                                 \
                afr[mt][3] = as[r0 + 160 + kw + 4];                           \
            }                                                                 \
            _Pragma("unroll")                                                 \
            for (int nt = 0; nt < 4; nt++) {                                  \
                const int rn = (wn + nt * 8 + lr) * 20;                       \
                bfr[nt][0] = bs[rn + kw];                                     \
                bfr[nt][1] = bs[rn + kw + 4];                                 \
            }                                                                 \
            _Pragma("unroll")                                                 \
            for (int mt = 0; mt < 4; mt++)                                    \
                _Pragma("unroll")                                             \
                for (int nt = 0; nt < 4; nt++)                                \
                    mma_f16(acc[mt][nt], afr[mt], bfr[nt][0], bfr[nt][1]);    \
        }                                                                     \
    }

// ---- fused QKV: one launch, N=3072 via section switch, fp16 out ----
__global__ __launch_bounds__(256, 2)
void gemm_qkv(const __half* __restrict__ A,
              const __half* __restrict__ Wk2, const __half* __restrict__ Wq2,
              const __half* __restrict__ Wv2,
              __half* __restrict__ Ck, __half* __restrict__ Cq,
              __half* __restrict__ Cv)
{
    const int tid = threadIdx.x;
    const int K = EMB, N = EMB;
    const int bm = blockIdx.y * 128;
    const int bn_raw = blockIdx.x * 128;
    const int sec = bn_raw >> 10;
    const int bn  = bn_raw & 1023;
    const __half* B = (sec == 0) ? Wk2 : (sec == 1) ? Wq2 : Wv2;
    __half* C       = (sec == 0) ? Ck  : (sec == 1) ? Cq  : Cv;

    GEMM_BODY

    #pragma unroll
    for (int mt = 0; mt < 4; mt++) {
        const int row = bm + wm + mt * 16 + lr;
        #pragma unroll
        for (int nt = 0; nt < 4; nt++) {
            const int col = bn + wn + nt * 8 + lc * 2;
            *(uint32_t*)(C + (size_t)row * N + col) =
                pack_h2(acc[mt][nt][0], acc[mt][nt][1]);
            *(uint32_t*)(C + (size_t)(row + 8) * N + col) =
                pack_h2(acc[mt][nt][2], acc[mt][nt][3]);
        }
    }
}

// ---- output projection: fp32 out + bias ----
__global__ __launch_bounds__(256, 2)
void gemm_f16(const __half* __restrict__ A, const __half* __restrict__ B,
              const float* __restrict__ bias, float* __restrict__ C,
              int M, int N, int K)
{
    const int tid = threadIdx.x;
    const int bm  = blockIdx.y * 128;
    const int bn  = blockIdx.x * 128;

    GEMM_BODY

    #pragma unroll
    for (int mt = 0; mt < 4; mt++) {
        const int row = bm + wm + mt * 16 + lr;
        #pragma unroll
        for (int nt = 0; nt < 4; nt++) {
            const int col = bn + wn + nt * 8 + lc * 2;
            const float b0 = bias[col], b1 = bias[col + 1];
            *(float2*)(C + (size_t)row * N + col) =
                make_float2(acc[mt][nt][0] + b0, acc[mt][nt][1] + b1);
            *(float2*)(C + (size_t)(row + 8) * N + col) =
                make_float2(acc[mt][nt][2] + b0, acc[mt][nt][3] + b1);
        }
    }
}

// ---------------------------------------------------------------------------
// Fused per-head LayerNorm on K and Q (fp16 data, fp32 math), + E^-0.25 scale.
// First half of grid handles K segments, second half Q segments.
// ---------------------------------------------------------------------------
#define NSEG (MTOK * HEADS)   // 131072 segments per tensor

__global__ __launch_bounds__(256)
void ln_kq(__half* __restrict__ Kx, __half* __restrict__ Qx,
           const float* __restrict__ kgv, const float* __restrict__ kbv,
           const float* __restrict__ qgv, const float* __restrict__ qbv,
           float scale)
{
    int seg = blockIdx.x * 8 + (threadIdx.x >> 5);
    const int lane = threadIdx.x & 31;
    const bool isq = seg >= NSEG;
    if (isq) seg -= NSEG;
    __half* X = isq ? Qx : Kx;
    const float* g = isq ? qgv : kgv;
    const float* b = isq ? qbv : kbv;

    __half2* p = (__half2*)(X + (size_t)seg * HSZ) + lane;
    float2 v = __half22float2(*p);
    float sum = v.x + v.y;
    float sq  = v.x * v.x + v.y * v.y;
    #pragma unroll
    for (int o = 16; o; o >>= 1) {
        sum += __shfl_xor_sync(0xffffffffu, sum, o);
        sq  += __shfl_xor_sync(0xffffffffu, sq,  o);
    }
    const float mean = sum * (1.0f / 64.0f);
    const float var  = sq * (1.0f / 64.0f) - mean * mean;
    const float r    = rsqrtf(var + 1e-5f);
    const float gx = g[2 * lane], gy = g[2 * lane + 1];
    const float bx = b[2 * lane], by = b[2 * lane + 1];
    *p = __floats2half2_rn(((v.x - mean) * r * gx + bx) * scale,
                           ((v.y - mean) * r * gy + by) * scale);
}

// ---------------------------------------------------------------------------
// FP16 flash attention, BR=128 (8 warps x 16 rows), BC=64, D=64.
// cp.async double-buffered K/V, P in registers, V via ldmatrix.trans.
// ---------------------------------------------------------------------------
#define FROWB 144   // smem row: 64 halves data + 8 pad

__global__ __launch_bounds__(256)
void flash_attn2(const __half* __restrict__ Q, const __half* __restrict__ K,
                 const __half* __restrict__ V, __half* __restrict__ Oh)
{
    __shared__ __align__(16) char kvbuf[2][2][64 * FROWB];  // [slot][K/V]

    const int qb = blockIdx.x;          // 128-row query tile, 0..15
    const int h  = blockIdx.y;
    const int b  = blockIdx.z;
    const int tid  = threadIdx.x;
    const int lane = tid & 31;
    const int wid  = tid >> 5;          // 0..7
    const int wm   = wid * 16;          // query-row offset in tile
    const int lr   = lane >> 2;
    const int lc   = lane & 3;

    const size_t base = (size_t)b * SEQ * EMB + (size_t)h * HSZ;
    const __half* Qg = Q + base + (size_t)(qb * 128) * EMB;
    const __half* Kg = K + base;
    const __half* Vg = V + base;

    uint32_t kb_[2], vb_[2];
    kb_[0] = smem_u32(kvbuf[0][0]); vb_[0] = smem_u32(kvbuf[0][1]);
    kb_[1] = smem_u32(kvbuf[1][0]); vb_[1] = smem_u32(kvbuf[1][1]);

    // ---- stage Q (128 rows) through slot0 (K+V contiguous), extract frags ----
    #pragma unroll
    for (int i = 0; i < 4; i++) {
        const int idx = tid + i * 256;          // 0..1023
        const int r = idx >> 3, q = idx & 7;    // r 0..127
        cp_async16(kb_[0] + r * FROWB + q * 16, Qg + (size_t)r * EMB + q * 8);
    }
    cp_commit();
    cp_wait<0>();
    __syncthreads();

    const uint32_t qrow = wm + ((lane >> 3) & 1) * 8 + (lane & 7);
    const uint32_t qoff = ((lane >> 4) ? 16u : 0u);
    uint32_t qa[4][4];
    #pragma unroll
    for (int kk = 0; kk < 4; kk++)
        ldsm4(qa[kk][0], qa[kk][1], qa[kk][2], qa[kk][3],
              kb_[0] + qrow * FROWB + kk * 32 + qoff);
    __syncthreads();

    // ---- K/V tile fill (64 keys) ----
    #define AFILL(kt_, slot_) do {                                           \
        _Pragma("unroll")                                                    \
        for (int i_ = 0; i_ < 4; i_++) {                                     \
            const int idx_ = tid + i_ * 256;                                 \
            const int op_  = idx_ >> 9;                                      \
            const int r_   = (idx_ >> 3) & 63;                               \
            const int q_   = idx_ & 7;                                       \
            const __half* g_ = (op_ ? Vg : Kg)                               \
                + (size_t)((kt_) * 64 + r_) * EMB + q_ * 8;                  \
            cp_async16((op_ ? vb_[slot_] : kb_[slot_]) + r_ * FROWB + q_ * 16, g_); \
        }                                                                    \
    } while (0)

    AFILL(0, 0);
    cp_commit();
    AFILL(1, 1);          // tile 1 always exists (ntiles = 2*qb+2 >= 2)
    cp_commit();

    float o[8][4];
    #pragma unroll
    for (int i = 0; i < 8; i++)
        #pragma unroll
        for (int j = 0; j < 4; j++) o[i][j] = 0.0f;
    float m0 = -INFINITY, m1 = -INFINITY, l0 = 0.0f, l1 = 0.0f;

    const uint32_t vrow = ((lane >> 3) & 1) * 8 + (lane & 7);
    const uint32_t voff = ((lane >> 4) ? 16u : 0u);
    const int lastkt = 2 * qb + 1;

    for (int kt = 0; kt <= lastkt; kt++) {
        const int slot = kt & 1;
        cp_wait<1>();
        __syncthreads();

        // ---- S = Q K^T ----
        const uint32_t* ks = (const uint32_t*)kvbuf[slot][0];
        float s[8][4];
        #pragma unroll
        for (int nt = 0; nt < 8; nt++)
            #pragma unroll
            for (int j = 0; j < 4; j++) s[nt][j] = 0.0f;

        #pragma unroll
        for (int kk = 0; kk < 4; kk++) {
            #pragma unroll
            for (int nt = 0; nt < 8; nt++) {
                const int rb = (nt * 8 + lr) * 36 + kk * 8 + lc;
                mma_f16(s[nt], qa[kk], ks[rb], ks[rb + 4]);
            }
        }

        // ---- causal mask (last two tiles only) ----
        if (kt >= 2 * qb) {
            const int rg = qb * 128 + wm + lr;
            #pragma unroll
            for (int nt = 0; nt < 8; nt++) {
                const int cg = kt * 64 + nt * 8 + 2 * lc;
                if (cg     > rg)     s[nt][0] = -1e30f;
                if (cg + 1 > rg)     s[nt][1] = -1e30f;
                if (cg     > rg + 8) s[nt][2] = -1e30f;
                if (cg + 1 > rg + 8) s[nt][3] = -1e30f;
            }
        }

        // ---- online softmax (fp32), P stays in registers ----
        float mx0 = -INFINITY, mx1 = -INFINITY;
        #pragma unroll
        for (int nt = 0; nt < 8; nt++) {
            mx0 = fmaxf(mx0, fmaxf(s[nt][0], s[nt][1]));
            mx1 = fmaxf(mx1, fmaxf(s[nt][2], s[nt][3]));
        }
        mx0 = fmaxf(mx0, __shfl_xor_sync(0xffffffffu, mx0, 1));
        mx0 = fmaxf(mx0, __shfl_xor_sync(0xffffffffu, mx0, 2));
        mx1 = fmaxf(mx1, __shfl_xor_sync(0xffffffffu, mx1, 1));
        mx1 = fmaxf(mx1, __shfl_xor_sync(0xffffffffu, mx1, 2));

        const float m0n = fmaxf(m0, mx0);
        const float m1n = fmaxf(m1, mx1);
        const float c0 = __expf(m0 - m0n);
        const float c1 = __expf(m1 - m1n);
        m0 = m0n; m1 = m1n;
        l0 *= c0;  l1 *= c1;
        #pragma unroll
        for (int nt = 0; nt < 8; nt++) {
            o[nt][0] *= c0; o[nt][1] *= c0;
            o[nt][2] *= c1; o[nt][3] *= c1;
        }
        #pragma unroll
        for (int nt = 0; nt < 8; nt++) {
            s[nt][0] = __expf(s[nt][0] - m0);
            s[nt][1] = __expf(s[nt][1] - m0);
            s[nt][2] = __expf(s[nt][2] - m1);
            s[nt][3] = __expf(s[nt][3] - m1);
            l0 += s[nt][0] + s[nt][1];
            l1 += s[nt][2] + s[nt][3];
        }

        // ---- O += P V ----
        const uint32_t vsl = vb_[slot];
        #pragma unroll
        for (int kk = 0; kk < 4; kk++) {
            uint32_t pa[4];
            pa[0] = pack_h2(s[2 * kk][0],     s[2 * kk][1]);
            pa[1] = pack_h2(s[2 * kk][2],     s[2 * kk][3]);
            pa[2] = pack_h2(s[2 * kk + 1][0], s[2 * kk + 1][1]);
            pa[3] = pack_h2(s[2 * kk + 1][2], s[2 * kk + 1][3]);
            const uint32_t vaddr0 = vsl + (kk * 16 + vrow) * FROWB + voff;
            #pragma unroll
            for (int j = 0; j < 4; j++) {
                uint32_t v0, v1, v2, v3;
                ldsm4t(v0, v1, v2, v3, vaddr0 + j * 32);
                mma_f16(o[2 * j],     pa, v0, v1);
                mma_f16(o[2 * j + 1], pa, v2, v3);
            }
        }

        __syncthreads();
        if (kt + 2 <= lastkt) AFILL(kt + 2, slot);
        cp_commit();
    }

    // ---- finalize ----
    l0 += __shfl_xor_sync(0xffffffffu, l0, 1);
    l0 += __shfl_xor_sync(0xffffffffu, l0, 2);
    l1 += __shfl_xor_sync(0xffffffffu, l1, 1);
    l1 += __shfl_xor_sync(0xffffffffu, l1, 2);
    const float i0 = 1.0f / l0;
    const float i1 = 1.0f / l1;

    const int row0 = qb * 128 + wm + lr;
    uint32_t* op0 = (uint32_t*)(Oh + base + (size_t)row0 * EMB);
    uint32_t* op1 = (uint32_t*)(Oh + base + (size_t)(row0 + 8) * EMB);
    #pragma unroll
    for (int ntd = 0; ntd < 8; ntd++) {
        const int colw = ntd * 4 + lc;
        op0[colw] = pack_h2(o[ntd][0] * i0, o[ntd][1] * i0);
        op1[colw] = pack_h2(o[ntd][2] * i1, o[ntd][3] * i1);
    }
}

// ---------------------------------------------------------------------------
extern "C" void kernel_launch(void* const* d_in, const int* in_sizes, int n_in,
                              void* d_out, int out_size)
{
    const float* x   = (const float*)d_in[0];
    const float* Wk  = (const float*)d_in[1];
    const float* Wq  = (const float*)d_in[2];
    const float* Wv  = (const float*)d_in[3];
    const float* Wo  = (const float*)d_in[4];
    const float* bo  = (const float*)d_in[5];
    const float* kg  = (const float*)d_in[6];
    const float* kb  = (const float*)d_in[7];
    const float* qg  = (const float*)d_in[8];
    const float* qb  = (const float*)d_in[9];
    float* out = (float*)d_out;

    float* sbase = nullptr;
    cudaGetSymbolAddress((void**)&sbase, g_scratch);
    const size_t MB1 = 1024ull * 1024ull;
    __half* xh  = (__half*)(sbase);
    __half* wkh = (__half*)(sbase + 4 * MB1);
    __half* wqh = (__half*)(sbase + 4 * MB1 + MB1 / 2);
    __half* wvh = (__half*)(sbase + 5 * MB1);
    __half* woh = (__half*)(sbase + 5 * MB1 + MB1 / 2);
    __half* gkh = (__half*)(sbase + 6 * MB1);
    __half* gqh = (__half*)(sbase + 10 * MB1);
    __half* gvh = (__half*)(sbase + 14 * MB1);
    __half* gyh = (__half*)(sbase + 18 * MB1);

    const float SCALE = 0.17677669529663687f;  // 1024^(-1/4)

    cudaFuncSetAttribute(gemm_qkv,
                         cudaFuncAttributeMaxDynamicSharedMemorySize, GEMM_SMEM);
    cudaFuncSetAttribute(gemm_f16,
                         cudaFuncAttributeMaxDynamicSharedMemorySize, GEMM_SMEM);

    conv_all<<<768, 256>>>(x, Wk, Wq, Wv, Wo, xh, wkh, wqh, wvh, woh);

    dim3 qkvGrid(3 * EMB / 128, MTOK / 128);   // (24, 64)
    gemm_qkv<<<qkvGrid, 256, GEMM_SMEM>>>(xh, wkh, wqh, wvh, gkh, gqh, gvh);

    ln_kq<<<2 * NSEG / 8, 256>>>(gkh, gqh, kg, kb, qg, qb, SCALE);

    dim3 attnGrid(SEQ / 128, HEADS, BATCH);    // (16, 16, 4)
    flash_attn2<<<attnGrid, 256>>>(gqh, gkh, gvh, gyh);

    dim3 gemmGrid(EMB / 128, MTOK / 128);      // (8, 64)
    gemm_f16<<<gemmGrid, 256, GEMM_SMEM>>>(gyh, woh, bo, out, MTOK, EMB, EMB);
}

// round 9
// speedup vs baseline: 7.3944x; 1.0195x over previous
#include <cuda_runtime.h>
#include <cuda_fp16.h>
#include <math.h>
#include <stdint.h>

#define EMB   1024
#define HEADS 16
#define HSZ   64
#define BATCH 4
#define SEQ   2048
#define MTOK  (BATCH * SEQ)   // 8192 token rows

// scratch floats: xh(4M) wk/wq/wv/wo(4x.5M) gkh gqh gvh gyh(4x4M) = 22M floats
__device__ float g_scratch[22ull * 1024 * 1024];

__device__ __forceinline__ void mma_f16(float* c, const uint32_t* a,
                                        uint32_t b0, uint32_t b1) {
    asm volatile(
        "mma.sync.aligned.m16n8k16.row.col.f32.f16.f16.f32 "
        "{%0,%1,%2,%3}, {%4,%5,%6,%7}, {%8,%9}, {%0,%1,%2,%3};\n"
        : "+f"(c[0]), "+f"(c[1]), "+f"(c[2]), "+f"(c[3])
        : "r"(a[0]), "r"(a[1]), "r"(a[2]), "r"(a[3]), "r"(b0), "r"(b1));
}
__device__ __forceinline__ void cp_async16(uint32_t saddr, const void* gaddr) {
    asm volatile("cp.async.cg.shared.global [%0], [%1], 16;\n"
                 :: "r"(saddr), "l"(gaddr));
}
__device__ __forceinline__ void cp_commit() {
    asm volatile("cp.async.commit_group;\n");
}
template <int N>
__device__ __forceinline__ void cp_wait() {
    asm volatile("cp.async.wait_group %0;\n" :: "n"(N));
}
__device__ __forceinline__ uint32_t smem_u32(const void* p) {
    uint32_t a;
    asm("{ .reg .u64 t; cvta.to.shared.u64 t, %1; cvt.u32.u64 %0, t; }"
        : "=r"(a) : "l"(p));
    return a;
}
__device__ __forceinline__ uint32_t pack_h2(float a, float b) {
    __half2 h = __floats2half2_rn(a, b);
    return *(uint32_t*)&h;
}
__device__ __forceinline__ void ldsm4(uint32_t& r0, uint32_t& r1,
                                      uint32_t& r2, uint32_t& r3, uint32_t a) {
    asm volatile("ldmatrix.sync.aligned.m8n8.x4.shared.b16 {%0,%1,%2,%3}, [%4];"
                 : "=r"(r0), "=r"(r1), "=r"(r2), "=r"(r3) : "r"(a));
}
__device__ __forceinline__ void ldsm4t(uint32_t& r0, uint32_t& r1,
                                       uint32_t& r2, uint32_t& r3, uint32_t a) {
    asm volatile("ldmatrix.sync.aligned.m8n8.x4.trans.shared.b16 {%0,%1,%2,%3}, [%4];"
                 : "=r"(r0), "=r"(r1), "=r"(r2), "=r"(r3) : "r"(a));
}

// ---------------------------------------------------------------------------
// One-shot fp32 -> fp16 convert of x + all 4 weights (single launch).
// ---------------------------------------------------------------------------
#define X4  (MTOK * EMB / 4)          // 2097152
#define W4  (EMB * EMB / 4)           // 262144

__global__ __launch_bounds__(256)
void conv_all(const float* __restrict__ x,  const float* __restrict__ Wk,
              const float* __restrict__ Wq, const float* __restrict__ Wv,
              const float* __restrict__ Wo,
              __half* __restrict__ xh,  __half* __restrict__ wkh,
              __half* __restrict__ wqh, __half* __restrict__ wvh,
              __half* __restrict__ woh)
{
    const int total = X4 + 4 * W4;
    int i = blockIdx.x * 256 + threadIdx.x;
    const int stride = gridDim.x * 256;
    for (; i < total; i += stride) {
        const float* src; __half* dst; int off;
        if (i < X4) { src = x; dst = xh; off = i; }
        else {
            const int j = i - X4;
            const int w = j >> 18;
            off = j & (W4 - 1);
            src = (w == 0) ? Wk : (w == 1) ? Wq : (w == 2) ? Wv : Wo;
            dst = (w == 0) ? wkh : (w == 1) ? wqh : (w == 2) ? wvh : woh;
        }
        float4 v = ((const float4*)src)[off];
        uint2 o;
        o.x = pack_h2(v.x, v.y);
        o.y = pack_h2(v.z, v.w);
        ((uint2*)dst)[off] = o;
    }
}

// ---------------------------------------------------------------------------
// FP16 GEMM core (fp32 accumulate). 128x128 tile, BK=32, 8 warps, m16n8k16,
// 4-stage cp.async. (unchanged from R8)
// ---------------------------------------------------------------------------
#define GSTAGES 4
#define BKH     32
#define ROWB    80
#define STG_B   (128 * ROWB)
#define GEMM_SMEM (GSTAGES * 2 * STG_B) // 81920 B

#define GFILL(stg, kc) do {                                                  \
    _Pragma("unroll")                                                        \
    for (int i_ = 0; i_ < 4; i_++) {                                         \
        const int idx_ = tid + i_ * 256;                                     \
        const int op_  = idx_ >> 9;                                          \
        const int r_   = (idx_ & 511) >> 2;                                  \
        const int q_   = idx_ & 3;                                           \
        const __half* g_ = (op_ ? B + (size_t)(bn + r_) * K                  \
                                : A + (size_t)(bm + r_) * K)                 \
                           + (kc) * BKH + q_ * 8;                            \
        cp_async16(data + (stg) * 2 * STG_B + op_ * STG_B                    \
                   + r_ * ROWB + q_ * 16, g_);                               \
    }                                                                        \
} while (0)

#define GEMM_BODY                                                             \
    extern __shared__ char dyn_smem[];                                        \
    const uint32_t data = smem_u32(dyn_smem);                                 \
    const int lane = tid & 31;                                                \
    const int wid  = tid >> 5;                                                \
    const int wm   = (wid >> 2) * 64;                                         \
    const int wn   = (wid & 3) * 32;                                          \
    const int lr   = lane >> 2;                                               \
    const int lc   = lane & 3;                                                \
    float acc[4][4][4];                                                       \
    _Pragma("unroll")                                                         \
    for (int i = 0; i < 4; i++)                                               \
        _Pragma("unroll")                                                     \
        for (int j = 0; j < 4; j++)                                           \
            _Pragma("unroll")                                                 \
            for (int r = 0; r < 4; r++) acc[i][j][r] = 0.0f;                  \
    _Pragma("unroll")                                                         \
    for (int s = 0; s < GSTAGES - 1; s++) { GFILL(s, s); cp_commit(); }       \
    const int nchunk = K / BKH;                                               \
    const uint32_t* smw = (const uint32_t*)dyn_smem;                          \
    for (int it = 0; it < nchunk; it++) {                                     \
        cp_wait<GSTAGES - 2>();                                               \
        __syncthreads();                                                      \
        const int nxt = it + GSTAGES - 1;                                     \
        if (nxt < nchunk) GFILL(nxt % GSTAGES, nxt);                          \
        cp_commit();                                                          \
        const int st = it % GSTAGES;                                          \
        const uint32_t* as = smw + st * 2 * (STG_B / 4);                      \
        const uint32_t* bs = as + STG_B / 4;                                  \
        _Pragma("unroll")                                                     \
        for (int ks = 0; ks < 2; ks++) {                                      \
            const int kw = ks * 8 + lc;                                       \
            uint32_t afr[4][4], bfr[4][2];                                    \
            _Pragma("unroll")                                                 \
            for (int mt = 0; mt < 4; mt++) {                                  \
                const int r0 = (wm + mt * 16 + lr) * 20;                      \
                afr[mt][0] = as[r0 + kw];                                     \
                afr[mt][1] = as[r0 + 160 + kw];                               \
                afr[mt][2] = as[r0 + kw + 4];                                 \
                afr[mt][3] = as[r0 + 160 + kw + 4];                           \
            }                                                                 \
            _Pragma("unroll")                                                 \
            for (int nt = 0; nt < 4; nt++) {                                  \
                const int rn = (wn + nt * 8 + lr) * 20;                       \
                bfr[nt][0] = bs[rn + kw];                                     \
                bfr[nt][1] = bs[rn + kw + 4];                                 \
            }                                                                 \
            _Pragma("unroll")                                                 \
            for (int mt = 0; mt < 4; mt++)                                    \
                _Pragma("unroll")                                             \
                for (int nt = 0; nt < 4; nt++)                                \
                    mma_f16(acc[mt][nt], afr[mt], bfr[nt][0], bfr[nt][1]);    \
        }                                                                     \
    }

__global__ __launch_bounds__(256, 2)
void gemm_qkv(const __half* __restrict__ A,
              const __half* __restrict__ Wk2, const __half* __restrict__ Wq2,
              const __half* __restrict__ Wv2,
              __half* __restrict__ Ck, __half* __restrict__ Cq,
              __half* __restrict__ Cv)
{
    const int tid = threadIdx.x;
    const int K = EMB, N = EMB;
    const int bm = blockIdx.y * 128;
    const int bn_raw = blockIdx.x * 128;
    const int sec = bn_raw >> 10;
    const int bn  = bn_raw & 1023;
    const __half* B = (sec == 0) ? Wk2 : (sec == 1) ? Wq2 : Wv2;
    __half* C       = (sec == 0) ? Ck  : (sec == 1) ? Cq  : Cv;

    GEMM_BODY

    #pragma unroll
    for (int mt = 0; mt < 4; mt++) {
        const int row = bm + wm + mt * 16 + lr;
        #pragma unroll
        for (int nt = 0; nt < 4; nt++) {
            const int col = bn + wn + nt * 8 + lc * 2;
            *(uint32_t*)(C + (size_t)row * N + col) =
                pack_h2(acc[mt][nt][0], acc[mt][nt][1]);
            *(uint32_t*)(C + (size_t)(row + 8) * N + col) =
                pack_h2(acc[mt][nt][2], acc[mt][nt][3]);
        }
    }
}

__global__ __launch_bounds__(256, 2)
void gemm_f16(const __half* __restrict__ A, const __half* __restrict__ B,
              const float* __restrict__ bias, float* __restrict__ C,
              int M, int N, int K)
{
    const int tid = threadIdx.x;
    const int bm  = blockIdx.y * 128;
    const int bn  = blockIdx.x * 128;

    GEMM_BODY

    #pragma unroll
    for (int mt = 0; mt < 4; mt++) {
        const int row = bm + wm + mt * 16 + lr;
        #pragma unroll
        for (int nt = 0; nt < 4; nt++) {
            const int col = bn + wn + nt * 8 + lc * 2;
            const float b0 = bias[col], b1 = bias[col + 1];
            *(float2*)(C + (size_t)row * N + col) =
                make_float2(acc[mt][nt][0] + b0, acc[mt][nt][1] + b1);
            *(float2*)(C + (size_t)(row + 8) * N + col) =
                make_float2(acc[mt][nt][2] + b0, acc[mt][nt][3] + b1);
        }
    }
}

// ---------------------------------------------------------------------------
// Fused per-head LayerNorm on K and Q (fp16 data, fp32 math).
// K gets scale SCALE; Q gets SCALE*log2(e) (softmax runs in exp2 domain).
// ---------------------------------------------------------------------------
#define NSEG (MTOK * HEADS)   // 131072 segments per tensor

__global__ __launch_bounds__(256)
void ln_kq(__half* __restrict__ Kx, __half* __restrict__ Qx,
           const float* __restrict__ kgv, const float* __restrict__ kbv,
           const float* __restrict__ qgv, const float* __restrict__ qbv,
           float scaleK, float scaleQ)
{
    int seg = blockIdx.x * 8 + (threadIdx.x >> 5);
    const int lane = threadIdx.x & 31;
    const bool isq = seg >= NSEG;
    if (isq) seg -= NSEG;
    __half* X = isq ? Qx : Kx;
    const float* g = isq ? qgv : kgv;
    const float* b = isq ? qbv : kbv;
    const float scale = isq ? scaleQ : scaleK;

    __half2* p = (__half2*)(X + (size_t)seg * HSZ) + lane;
    float2 v = __half22float2(*p);
    float sum = v.x + v.y;
    float sq  = v.x * v.x + v.y * v.y;
    #pragma unroll
    for (int o = 16; o; o >>= 1) {
        sum += __shfl_xor_sync(0xffffffffu, sum, o);
        sq  += __shfl_xor_sync(0xffffffffu, sq,  o);
    }
    const float mean = sum * (1.0f / 64.0f);
    const float var  = sq * (1.0f / 64.0f) - mean * mean;
    const float r    = rsqrtf(var + 1e-5f);
    const float gx = g[2 * lane], gy = g[2 * lane + 1];
    const float bx = b[2 * lane], by = b[2 * lane + 1];
    *p = __floats2half2_rn(((v.x - mean) * r * gx + bx) * scale,
                           ((v.y - mean) * r * gy + by) * scale);
}

// ---------------------------------------------------------------------------
// FP16 flash attention, BR=128 (8 warps x 16 rows), BC=64, D=64.
// 3-slot K/V ring (ONE barrier/tile), K frags via ldmatrix, V via
// ldmatrix.trans, P in registers, softmax in exp2 domain.
// ---------------------------------------------------------------------------
#define FROWB 144                 // smem row: 64 halves + 8 pad
#define FTILE (64 * FROWB)        // 9216 B per operand tile

__global__ __launch_bounds__(256)
void flash_attn2(const __half* __restrict__ Q, const __half* __restrict__ K,
                 const __half* __restrict__ V, __half* __restrict__ Oh)
{
    __shared__ __align__(16) char kvbuf[3][2][FTILE];  // 55.3 KB

    const int qb = blockIdx.x;          // 128-row query tile
    const int h  = blockIdx.y;
    const int b  = blockIdx.z;
    const int tid  = threadIdx.x;
    const int lane = tid & 31;
    const int wid  = tid >> 5;
    const int wm   = wid * 16;
    const int lr   = lane >> 2;
    const int lc   = lane & 3;

    const size_t base = (size_t)b * SEQ * EMB + (size_t)h * HSZ;
    const __half* Qg = Q + base + (size_t)(qb * 128) * EMB;
    const __half* Kg = K + base;
    const __half* Vg = V + base;
    const uint32_t sbase = smem_u32(kvbuf);

    // ---- stage Q (128 rows) through slot0, extract A-frags via ldmatrix ----
    #pragma unroll
    for (int i = 0; i < 4; i++) {
        const int idx = tid + i * 256;
        const int r = idx >> 3, q = idx & 7;
        cp_async16(sbase + r * FROWB + q * 16, Qg + (size_t)r * EMB + q * 8);
    }
    cp_commit();
    cp_wait<0>();
    __syncthreads();

    const uint32_t qrow = wm + ((lane >> 3) & 1) * 8 + (lane & 7);
    const uint32_t qoff = ((lane >> 4) ? 16u : 0u);
    uint32_t qa[4][4];
    #pragma unroll
    for (int kk = 0; kk < 4; kk++)
        ldsm4(qa[kk][0], qa[kk][1], qa[kk][2], qa[kk][3],
              sbase + qrow * FROWB + kk * 32 + qoff);
    __syncthreads();

    // ---- K/V tile fill ----
    #define AFILL(kt_, slot_) do {                                           \
        const uint32_t so_ = sbase + (slot_) * 2 * FTILE;                    \
        _Pragma("unroll")                                                    \
        for (int i_ = 0; i_ < 4; i_++) {                                     \
            const int idx_ = tid + i_ * 256;                                 \
            const int op_  = idx_ >> 9;                                      \
            const int r_   = (idx_ >> 3) & 63;                               \
            const int q_   = idx_ & 7;                                       \
            const __half* g_ = (op_ ? Vg : Kg)                               \
                + (size_t)((kt_) * 64 + r_) * EMB + q_ * 8;                  \
            cp_async16(so_ + op_ * FTILE + r_ * FROWB + q_ * 16, g_);        \
        }                                                                    \
    } while (0)

    AFILL(0, 0);
    cp_commit();
    AFILL(1, 1);          // lastkt >= 1 always
    cp_commit();

    float o[8][4];
    #pragma unroll
    for (int i = 0; i < 8; i++)
        #pragma unroll
        for (int j = 0; j < 4; j++) o[i][j] = 0.0f;
    float m0 = -INFINITY, m1 = -INFINITY, l0 = 0.0f, l1 = 0.0f;

    // ldmatrix lane addressing (K: non-trans, V: trans)
    const uint32_t krow = (lane & 7);          // row within 8-key group
    const uint32_t ktil = (lane >> 3) * 16;    // 8-half column chunk
    const uint32_t vrow = ((lane >> 3) & 1) * 8 + (lane & 7);
    const uint32_t voff = ((lane >> 4) ? 16u : 0u);
    const int lastkt = 2 * qb + 1;

    for (int kt = 0; kt <= lastkt; kt++) {
        const int slot = kt % 3;
        cp_wait<1>();
        __syncthreads();

        // refill slot (kt-1)%3 with tile kt+2 (safe: all warps past kt-1)
        if (kt + 2 <= lastkt) AFILL(kt + 2, (kt + 2) % 3);
        cp_commit();

        // ---- S = Q K^T : B-frags via ldmatrix.x4 ----
        const uint32_t ksb = sbase + slot * 2 * FTILE;
        float s[8][4];
        #pragma unroll
        for (int nt = 0; nt < 8; nt++)
            #pragma unroll
            for (int j = 0; j < 4; j++) s[nt][j] = 0.0f;

        #pragma unroll
        for (int nt = 0; nt < 8; nt++) {
            const uint32_t abase = ksb + (nt * 8 + krow) * FROWB + ktil;
            #pragma unroll
            for (int hh = 0; hh < 2; hh++) {
                uint32_t b0, b1, b2, b3;
                ldsm4(b0, b1, b2, b3, abase + hh * 64);
                mma_f16(s[nt], qa[2 * hh],     b0, b1);
                mma_f16(s[nt], qa[2 * hh + 1], b2, b3);
            }
        }

        // ---- causal mask (last two tiles only) ----
        if (kt >= 2 * qb) {
            const int rg = qb * 128 + wm + lr;
            #pragma unroll
            for (int nt = 0; nt < 8; nt++) {
                const int cg = kt * 64 + nt * 8 + 2 * lc;
                if (cg     > rg)     s[nt][0] = -1e30f;
                if (cg + 1 > rg)     s[nt][1] = -1e30f;
                if (cg     > rg + 8) s[nt][2] = -1e30f;
                if (cg + 1 > rg + 8) s[nt][3] = -1e30f;
            }
        }

        // ---- online softmax in exp2 domain (s already scaled by log2e) ----
        float mx0 = -INFINITY, mx1 = -INFINITY;
        #pragma unroll
        for (int nt = 0; nt < 8; nt++) {
            mx0 = fmaxf(mx0, fmaxf(s[nt][0], s[nt][1]));
            mx1 = fmaxf(mx1, fmaxf(s[nt][2], s[nt][3]));
        }
        mx0 = fmaxf(mx0, __shfl_xor_sync(0xffffffffu, mx0, 1));
        mx0 = fmaxf(mx0, __shfl_xor_sync(0xffffffffu, mx0, 2));
        mx1 = fmaxf(mx1, __shfl_xor_sync(0xffffffffu, mx1, 1));
        mx1 = fmaxf(mx1, __shfl_xor_sync(0xffffffffu, mx1, 2));

        const float m0n = fmaxf(m0, mx0);
        const float m1n = fmaxf(m1, mx1);
        const float c0 = exp2f(m0 - m0n);
        const float c1 = exp2f(m1 - m1n);
        m0 = m0n; m1 = m1n;
        l0 *= c0;  l1 *= c1;
        #pragma unroll
        for (int nt = 0; nt < 8; nt++) {
            o[nt][0] *= c0; o[nt][1] *= c0;
            o[nt][2] *= c1; o[nt][3] *= c1;
        }
        #pragma unroll
        for (int nt = 0; nt < 8; nt++) {
            s[nt][0] = exp2f(s[nt][0] - m0);
            s[nt][1] = exp2f(s[nt][1] - m0);
            s[nt][2] = exp2f(s[nt][2] - m1);
            s[nt][3] = exp2f(s[nt][3] - m1);
            l0 += s[nt][0] + s[nt][1];
            l1 += s[nt][2] + s[nt][3];
        }

        // ---- O += P V ----
        const uint32_t vsl = ksb + FTILE;
        #pragma unroll
        for (int kk = 0; kk < 4; kk++) {
            uint32_t pa[4];
            pa[0] = pack_h2(s[2 * kk][0],     s[2 * kk][1]);
            pa[1] = pack_h2(s[2 * kk][2],     s[2 * kk][3]);
            pa[2] = pack_h2(s[2 * kk + 1][0], s[2 * kk + 1][1]);
            pa[3] = pack_h2(s[2 * kk + 1][2], s[2 * kk + 1][3]);
            const uint32_t vaddr0 = vsl + (kk * 16 + vrow) * FROWB + voff;
            #pragma unroll
            for (int j = 0; j < 4; j++) {
                uint32_t v0, v1, v2, v3;
                ldsm4t(v0, v1, v2, v3, vaddr0 + j * 32);
                mma_f16(o[2 * j],     pa, v0, v1);
                mma_f16(o[2 * j + 1], pa, v2, v3);
            }
        }
    }

    // ---- finalize ----
    l0 += __shfl_xor_sync(0xffffffffu, l0, 1);
    l0 += __shfl_xor_sync(0xffffffffu, l0, 2);
    l1 += __shfl_xor_sync(0xffffffffu, l1, 1);
    l1 += __shfl_xor_sync(0xffffffffu, l1, 2);
    const float i0 = 1.0f / l0;
    const float i1 = 1.0f / l1;

    const int row0 = qb * 128 + wm + lr;
    uint32_t* op0 = (uint32_t*)(Oh + base + (size_t)row0 * EMB);
    uint32_t* op1 = (uint32_t*)(Oh + base + (size_t)(row0 + 8) * EMB);
    #pragma unroll
    for (int ntd = 0; ntd < 8; ntd++) {
        const int colw = ntd * 4 + lc;
        op0[colw] = pack_h2(o[ntd][0] * i0, o[ntd][1] * i0);
        op1[colw] = pack_h2(o[ntd][2] * i1, o[ntd][3] * i1);
    }
}

// ---------------------------------------------------------------------------
extern "C" void kernel_launch(void* const* d_in, const int* in_sizes, int n_in,
                              void* d_out, int out_size)
{
    const float* x   = (const float*)d_in[0];
    const float* Wk  = (const float*)d_in[1];
    const float* Wq  = (const float*)d_in[2];
    const float* Wv  = (const float*)d_in[3];
    const float* Wo  = (const float*)d_in[4];
    const float* bo  = (const float*)d_in[5];
    const float* kg  = (const float*)d_in[6];
    const float* kb  = (const float*)d_in[7];
    const float* qg  = (const float*)d_in[8];
    const float* qb  = (const float*)d_in[9];
    float* out = (float*)d_out;

    float* sbase = nullptr;
    cudaGetSymbolAddress((void**)&sbase, g_scratch);
    const size_t MB1 = 1024ull * 1024ull;
    __half* xh  = (__half*)(sbase);
    __half* wkh = (__half*)(sbase + 4 * MB1);
    __half* wqh = (__half*)(sbase + 4 * MB1 + MB1 / 2);
    __half* wvh = (__half*)(sbase + 5 * MB1);
    __half* woh = (__half*)(sbase + 5 * MB1 + MB1 / 2);
    __half* gkh = (__half*)(sbase + 6 * MB1);
    __half* gqh = (__half*)(sbase + 10 * MB1);
    __half* gvh = (__half*)(sbase + 14 * MB1);
    __half* gyh = (__half*)(sbase + 18 * MB1);

    const float SCALE  = 0.17677669529663687f;           // 1024^(-1/4)
    const float SCALEQ = SCALE * 1.4426950408889634f;    // fold log2(e) into Q

    cudaFuncSetAttribute(gemm_qkv,
                         cudaFuncAttributeMaxDynamicSharedMemorySize, GEMM_SMEM);
    cudaFuncSetAttribute(gemm_f16,
                         cudaFuncAttributeMaxDynamicSharedMemorySize, GEMM_SMEM);

    conv_all<<<2048, 256>>>(x, Wk, Wq, Wv, Wo, xh, wkh, wqh, wvh, woh);

    dim3 qkvGrid(3 * EMB / 128, MTOK / 128);   // (24, 64)
    gemm_qkv<<<qkvGrid, 256, GEMM_SMEM>>>(xh, wkh, wqh, wvh, gkh, gqh, gvh);

    ln_kq<<<2 * NSEG / 8, 256>>>(gkh, gqh, kg, kb, qg, qb, SCALE, SCALEQ);

    dim3 attnGrid(SEQ / 128, HEADS, BATCH);    // (16, 16, 4)
    flash_attn2<<<attnGrid, 256>>>(gqh, gkh, gvh, gyh);

    dim3 gemmGrid(EMB / 128, MTOK / 128);      // (8, 64)
    gemm_f16<<<gemmGrid, 256, GEMM_SMEM>>>(gyh, woh, bo, out, MTOK, EMB, EMB);
}

// round 10
// speedup vs baseline: 7.8036x; 1.0553x over previous
#include <cuda_runtime.h>
#include <cuda_fp16.h>
#include <math.h>
#include <stdint.h>

#define EMB   1024
#define HEADS 16
#define HSZ   64
#define BATCH 4
#define SEQ   2048
#define MTOK  (BATCH * SEQ)   // 8192 token rows

// scratch floats: xh(4M) wk/wq/wv/wo(4x.5M) gkh gqh gvh gyh(4x4M) = 22M floats
__device__ float g_scratch[22ull * 1024 * 1024];

__device__ __forceinline__ void mma_f16(float* c, const uint32_t* a,
                                        uint32_t b0, uint32_t b1) {
    asm volatile(
        "mma.sync.aligned.m16n8k16.row.col.f32.f16.f16.f32 "
        "{%0,%1,%2,%3}, {%4,%5,%6,%7}, {%8,%9}, {%0,%1,%2,%3};\n"
        : "+f"(c[0]), "+f"(c[1]), "+f"(c[2]), "+f"(c[3])
        : "r"(a[0]), "r"(a[1]), "r"(a[2]), "r"(a[3]), "r"(b0), "r"(b1));
}
__device__ __forceinline__ void cp_async16(uint32_t saddr, const void* gaddr) {
    asm volatile("cp.async.cg.shared.global [%0], [%1], 16;\n"
                 :: "r"(saddr), "l"(gaddr));
}
__device__ __forceinline__ void cp_commit() {
    asm volatile("cp.async.commit_group;\n");
}
template <int N>
__device__ __forceinline__ void cp_wait() {
    asm volatile("cp.async.wait_group %0;\n" :: "n"(N));
}
__device__ __forceinline__ uint32_t smem_u32(const void* p) {
    uint32_t a;
    asm("{ .reg .u64 t; cvta.to.shared.u64 t, %1; cvt.u32.u64 %0, t; }"
        : "=r"(a) : "l"(p));
    return a;
}
__device__ __forceinline__ uint32_t pack_h2(float a, float b) {
    __half2 h = __floats2half2_rn(a, b);
    return *(uint32_t*)&h;
}
// packed fp16 exp2: 2 elements per MUFU op; output is a ready mma fragment
__device__ __forceinline__ uint32_t ex2_h2(float a, float b) {
    uint32_t h = pack_h2(a, b);
    uint32_t r;
    asm("ex2.approx.f16x2 %0, %1;" : "=r"(r) : "r"(h));
    return r;
}
__device__ __forceinline__ void ldsm4(uint32_t& r0, uint32_t& r1,
                                      uint32_t& r2, uint32_t& r3, uint32_t a) {
    asm volatile("ldmatrix.sync.aligned.m8n8.x4.shared.b16 {%0,%1,%2,%3}, [%4];"
                 : "=r"(r0), "=r"(r1), "=r"(r2), "=r"(r3) : "r"(a));
}
__device__ __forceinline__ void ldsm4t(uint32_t& r0, uint32_t& r1,
                                       uint32_t& r2, uint32_t& r3, uint32_t a) {
    asm volatile("ldmatrix.sync.aligned.m8n8.x4.trans.shared.b16 {%0,%1,%2,%3}, [%4];"
                 : "=r"(r0), "=r"(r1), "=r"(r2), "=r"(r3) : "r"(a));
}

// ---------------------------------------------------------------------------
// One-shot fp32 -> fp16 convert of x + all 4 weights (single launch).
// ---------------------------------------------------------------------------
#define X4  (MTOK * EMB / 4)          // 2097152
#define W4  (EMB * EMB / 4)           // 262144

__global__ __launch_bounds__(256)
void conv_all(const float* __restrict__ x,  const float* __restrict__ Wk,
              const float* __restrict__ Wq, const float* __restrict__ Wv,
              const float* __restrict__ Wo,
              __half* __restrict__ xh,  __half* __restrict__ wkh,
              __half* __restrict__ wqh, __half* __restrict__ wvh,
              __half* __restrict__ woh)
{
    const int total = X4 + 4 * W4;
    int i = blockIdx.x * 256 + threadIdx.x;
    const int stride = gridDim.x * 256;
    for (; i < total; i += stride) {
        const float* src; __half* dst; int off;
        if (i < X4) { src = x; dst = xh; off = i; }
        else {
            const int j = i - X4;
            const int w = j >> 18;
            off = j & (W4 - 1);
            src = (w == 0) ? Wk : (w == 1) ? Wq : (w == 2) ? Wv : Wo;
            dst = (w == 0) ? wkh : (w == 1) ? wqh : (w == 2) ? wvh : woh;
        }
        float4 v = ((const float4*)src)[off];
        uint2 o;
        o.x = pack_h2(v.x, v.y);
        o.y = pack_h2(v.z, v.w);
        ((uint2*)dst)[off] = o;
    }
}

// ---------------------------------------------------------------------------
// FP16 GEMM core (fp32 accumulate). 128x128 tile, BK=32, 8 warps, m16n8k16,
// 4-stage cp.async. Fragments via ldmatrix.x4 (12 LDSM/iter vs 96 LDS).
// ---------------------------------------------------------------------------
#define GSTAGES 4
#define BKH     32
#define ROWB    80
#define STG_B   (128 * ROWB)
#define GEMM_SMEM (GSTAGES * 2 * STG_B) // 81920 B

#define GFILL(stg, kc) do {                                                  \
    _Pragma("unroll")                                                        \
    for (int i_ = 0; i_ < 4; i_++) {                                         \
        const int idx_ = tid + i_ * 256;                                     \
        const int op_  = idx_ >> 9;                                          \
        const int r_   = (idx_ & 511) >> 2;                                  \
        const int q_   = idx_ & 3;                                           \
        const __half* g_ = (op_ ? B + (size_t)(bn + r_) * K                  \
                                : A + (size_t)(bm + r_) * K)                 \
                           + (kc) * BKH + q_ * 8;                            \
        cp_async16(data + (stg) * 2 * STG_B + op_ * STG_B                    \
                   + r_ * ROWB + q_ * 16, g_);                               \
    }                                                                        \
} while (0)

#define GEMM_BODY                                                             \
    extern __shared__ char dyn_smem[];                                        \
    const uint32_t data = smem_u32(dyn_smem);                                 \
    const int lane = tid & 31;                                                \
    const int wid  = tid >> 5;                                                \
    const int wm   = (wid >> 2) * 64;                                         \
    const int wn   = (wid & 3) * 32;                                          \
    const int lr   = lane >> 2;                                               \
    const int lc   = lane & 3;                                                \
    /* ldmatrix lane offsets (bytes, within a stage's A / B region) */        \
    const uint32_t arow = ((lane >> 3) & 1) * 8 + (lane & 7);                 \
    const uint32_t achk = (lane >> 4) * 16;                                   \
    uint32_t aoff[4], boff[4];                                                \
    _Pragma("unroll")                                                         \
    for (int mt = 0; mt < 4; mt++)                                            \
        aoff[mt] = (wm + mt * 16 + arow) * ROWB + achk;                       \
    _Pragma("unroll")                                                         \
    for (int nt = 0; nt < 4; nt++)                                            \
        boff[nt] = (wn + nt * 8 + (lane & 7)) * ROWB + (lane >> 3) * 16;      \
    float acc[4][4][4];                                                       \
    _Pragma("unroll")                                                         \
    for (int i = 0; i < 4; i++)                                               \
        _Pragma("unroll")                                                     \
        for (int j = 0; j < 4; j++)                                           \
            _Pragma("unroll")                                                 \
            for (int r = 0; r < 4; r++) acc[i][j][r] = 0.0f;                  \
    _Pragma("unroll")                                                         \
    for (int s = 0; s < GSTAGES - 1; s++) { GFILL(s, s); cp_commit(); }       \
    const int nchunk = K / BKH;                                               \
    for (int it = 0; it < nchunk; it++) {                                     \
        cp_wait<GSTAGES - 2>();                                               \
        __syncthreads();                                                      \
        const int nxt = it + GSTAGES - 1;                                     \
        if (nxt < nchunk) GFILL(nxt % GSTAGES, nxt);                          \
        cp_commit();                                                          \
        const uint32_t asb = data + (it % GSTAGES) * 2 * STG_B;               \
        const uint32_t bsb = asb + STG_B;                                     \
        uint32_t bfr[4][4];                                                   \
        _Pragma("unroll")                                                     \
        for (int nt = 0; nt < 4; nt++)                                        \
            ldsm4(bfr[nt][0], bfr[nt][1], bfr[nt][2], bfr[nt][3],             \
                  bsb + boff[nt]);                                            \
        _Pragma("unroll")                                                     \
        for (int ks = 0; ks < 2; ks++) {                                      \
            uint32_t afr[4][4];                                               \
            _Pragma("unroll")                                                 \
            for (int mt = 0; mt < 4; mt++)                                    \
                ldsm4(afr[mt][0], afr[mt][1], afr[mt][2], afr[mt][3],         \
                      asb + aoff[mt] + ks * 32);                              \
            _Pragma("unroll")                                                 \
            for (int mt = 0; mt < 4; mt++)                                    \
                _Pragma("unroll")                                             \
                for (int nt = 0; nt < 4; nt++)                                \
                    mma_f16(acc[mt][nt], afr[mt],                             \
                            bfr[nt][2 * ks], bfr[nt][2 * ks + 1]);            \
        }                                                                     \
    }

__global__ __launch_bounds__(256, 2)
void gemm_qkv(const __half* __restrict__ A,
              const __half* __restrict__ Wk2, const __half* __restrict__ Wq2,
              const __half* __restrict__ Wv2,
              __half* __restrict__ Ck, __half* __restrict__ Cq,
              __half* __restrict__ Cv)
{
    const int tid = threadIdx.x;
    const int K = EMB, N = EMB;
    const int bm = blockIdx.y * 128;
    const int bn_raw = blockIdx.x * 128;
    const int sec = bn_raw >> 10;
    const int bn  = bn_raw & 1023;
    const __half* B = (sec == 0) ? Wk2 : (sec == 1) ? Wq2 : Wv2;
    __half* C       = (sec == 0) ? Ck  : (sec == 1) ? Cq  : Cv;

    GEMM_BODY

    #pragma unroll
    for (int mt = 0; mt < 4; mt++) {
        const int row = bm + wm + mt * 16 + lr;
        #pragma unroll
        for (int nt = 0; nt < 4; nt++) {
            const int col = bn + wn + nt * 8 + lc * 2;
            *(uint32_t*)(C + (size_t)row * N + col) =
                pack_h2(acc[mt][nt][0], acc[mt][nt][1]);
            *(uint32_t*)(C + (size_t)(row + 8) * N + col) =
                pack_h2(acc[mt][nt][2], acc[mt][nt][3]);
        }
    }
}

__global__ __launch_bounds__(256, 2)
void gemm_f16(const __half* __restrict__ A, const __half* __restrict__ B,
              const float* __restrict__ bias, float* __restrict__ C,
              int M, int N, int K)
{
    const int tid = threadIdx.x;
    const int bm  = blockIdx.y * 128;
    const int bn  = blockIdx.x * 128;

    GEMM_BODY

    #pragma unroll
    for (int mt = 0; mt < 4; mt++) {
        const int row = bm + wm + mt * 16 + lr;
        #pragma unroll
        for (int nt = 0; nt < 4; nt++) {
            const int col = bn + wn + nt * 8 + lc * 2;
            const float b0 = bias[col], b1 = bias[col + 1];
            *(float2*)(C + (size_t)row * N + col) =
                make_float2(acc[mt][nt][0] + b0, acc[mt][nt][1] + b1);
            *(float2*)(C + (size_t)(row + 8) * N + col) =
                make_float2(acc[mt][nt][2] + b0, acc[mt][nt][3] + b1);
        }
    }
}

// ---------------------------------------------------------------------------
// Fused per-head LayerNorm on K and Q (fp16 data, fp32 math).
// K gets scale SCALE; Q gets SCALE*log2(e) (softmax runs in exp2 domain).
// ---------------------------------------------------------------------------
#define NSEG (MTOK * HEADS)   // 131072 segments per tensor

__global__ __launch_bounds__(256)
void ln_kq(__half* __restrict__ Kx, __half* __restrict__ Qx,
           const float* __restrict__ kgv, const float* __restrict__ kbv,
           const float* __restrict__ qgv, const float* __restrict__ qbv,
           float scaleK, float scaleQ)
{
    int seg = blockIdx.x * 8 + (threadIdx.x >> 5);
    const int lane = threadIdx.x & 31;
    const bool isq = seg >= NSEG;
    if (isq) seg -= NSEG;
    __half* X = isq ? Qx : Kx;
    const float* g = isq ? qgv : kgv;
    const float* b = isq ? qbv : kbv;
    const float scale = isq ? scaleQ : scaleK;

    __half2* p = (__half2*)(X + (size_t)seg * HSZ) + lane;
    float2 v = __half22float2(*p);
    float sum = v.x + v.y;
    float sq  = v.x * v.x + v.y * v.y;
    #pragma unroll
    for (int o = 16; o; o >>= 1) {
        sum += __shfl_xor_sync(0xffffffffu, sum, o);
        sq  += __shfl_xor_sync(0xffffffffu, sq,  o);
    }
    const float mean = sum * (1.0f / 64.0f);
    const float var  = sq * (1.0f / 64.0f) - mean * mean;
    const float r    = rsqrtf(var + 1e-5f);
    const float gx = g[2 * lane], gy = g[2 * lane + 1];
    const float bx = b[2 * lane], by = b[2 * lane + 1];
    *p = __floats2half2_rn(((v.x - mean) * r * gx + bx) * scale,
                           ((v.y - mean) * r * gy + by) * scale);
}

// ---------------------------------------------------------------------------
// FP16 flash attention, BR=128 (8 warps x 16 rows), BC=64, D=64.
// 3-slot K/V ring, ldmatrix fragments, P via ex2.approx.f16x2 (packed exp,
// output doubles as the PV A-fragment), softmax in exp2 domain.
// ---------------------------------------------------------------------------
#define FROWB 144                 // smem row: 64 halves + 8 pad
#define FTILE (64 * FROWB)        // 9216 B per operand tile

__global__ __launch_bounds__(256)
void flash_attn2(const __half* __restrict__ Q, const __half* __restrict__ K,
                 const __half* __restrict__ V, __half* __restrict__ Oh)
{
    __shared__ __align__(16) char kvbuf[3][2][FTILE];  // 55.3 KB

    const int qb = blockIdx.x;          // 128-row query tile
    const int h  = blockIdx.y;
    const int b  = blockIdx.z;
    const int tid  = threadIdx.x;
    const int lane = tid & 31;
    const int wid  = tid >> 5;
    const int wm   = wid * 16;
    const int lr   = lane >> 2;
    const int lc   = lane & 3;

    const size_t base = (size_t)b * SEQ * EMB + (size_t)h * HSZ;
    const __half* Qg = Q + base + (size_t)(qb * 128) * EMB;
    const __half* Kg = K + base;
    const __half* Vg = V + base;
    const uint32_t sbase = smem_u32(kvbuf);

    // ---- stage Q (128 rows) through slot0, extract A-frags via ldmatrix ----
    #pragma unroll
    for (int i = 0; i < 4; i++) {
        const int idx = tid + i * 256;
        const int r = idx >> 3, q = idx & 7;
        cp_async16(sbase + r * FROWB + q * 16, Qg + (size_t)r * EMB + q * 8);
    }
    cp_commit();
    cp_wait<0>();
    __syncthreads();

    const uint32_t qrow = wm + ((lane >> 3) & 1) * 8 + (lane & 7);
    const uint32_t qoff = ((lane >> 4) ? 16u : 0u);
    uint32_t qa[4][4];
    #pragma unroll
    for (int kk = 0; kk < 4; kk++)
        ldsm4(qa[kk][0], qa[kk][1], qa[kk][2], qa[kk][3],
              sbase + qrow * FROWB + kk * 32 + qoff);
    __syncthreads();

    // ---- K/V tile fill ----
    #define AFILL(kt_, slot_) do {                                           \
        const uint32_t so_ = sbase + (slot_) * 2 * FTILE;                    \
        _Pragma("unroll")                                                    \
        for (int i_ = 0; i_ < 4; i_++) {                                     \
            const int idx_ = tid + i_ * 256;                                 \
            const int op_  = idx_ >> 9;                                      \
            const int r_   = (idx_ >> 3) & 63;                               \
            const int q_   = idx_ & 7;                                       \
            const __half* g_ = (op_ ? Vg : Kg)                               \
                + (size_t)((kt_) * 64 + r_) * EMB + q_ * 8;                  \
            cp_async16(so_ + op_ * FTILE + r_ * FROWB + q_ * 16, g_);        \
        }                                                                    \
    } while (0)

    AFILL(0, 0);
    cp_commit();
    AFILL(1, 1);
    cp_commit();

    float o[8][4];
    #pragma unroll
    for (int i = 0; i < 8; i++)
        #pragma unroll
        for (int j = 0; j < 4; j++) o[i][j] = 0.0f;
    float m0 = -INFINITY, m1 = -INFINITY, l0 = 0.0f, l1 = 0.0f;

    const uint32_t krow = (lane & 7);
    const uint32_t ktil = (lane >> 3) * 16;
    const uint32_t vrow = ((lane >> 3) & 1) * 8 + (lane & 7);
    const uint32_t voff = ((lane >> 4) ? 16u : 0u);
    const int lastkt = 2 * qb + 1;

    for (int kt = 0; kt <= lastkt; kt++) {
        const int slot = kt % 3;
        cp_wait<1>();
        __syncthreads();

        if (kt + 2 <= lastkt) AFILL(kt + 2, (kt + 2) % 3);
        cp_commit();

        // ---- S = Q K^T ----
        const uint32_t ksb = sbase + slot * 2 * FTILE;
        float s[8][4];
        #pragma unroll
        for (int nt = 0; nt < 8; nt++)
            #pragma unroll
            for (int j = 0; j < 4; j++) s[nt][j] = 0.0f;

        #pragma unroll
        for (int nt = 0; nt < 8; nt++) {
            const uint32_t abase = ksb + (nt * 8 + krow) * FROWB + ktil;
            #pragma unroll
            for (int hh = 0; hh < 2; hh++) {
                uint32_t b0, b1, b2, b3;
                ldsm4(b0, b1, b2, b3, abase + hh * 64);
                mma_f16(s[nt], qa[2 * hh],     b0, b1);
                mma_f16(s[nt], qa[2 * hh + 1], b2, b3);
            }
        }

        // ---- causal mask (last two tiles only) ----
        if (kt >= 2 * qb) {
            const int rg = qb * 128 + wm + lr;
            #pragma unroll
            for (int nt = 0; nt < 8; nt++) {
                const int cg = kt * 64 + nt * 8 + 2 * lc;
                if (cg     > rg)     s[nt][0] = -1e30f;
                if (cg + 1 > rg)     s[nt][1] = -1e30f;
                if (cg     > rg + 8) s[nt][2] = -1e30f;
                if (cg + 1 > rg + 8) s[nt][3] = -1e30f;
            }
        }

        // ---- online softmax, exp2 domain, packed f16 exponentials ----
        float mx0 = -INFINITY, mx1 = -INFINITY;
        #pragma unroll
        for (int nt = 0; nt < 8; nt++) {
            mx0 = fmaxf(mx0, fmaxf(s[nt][0], s[nt][1]));
            mx1 = fmaxf(mx1, fmaxf(s[nt][2], s[nt][3]));
        }
        mx0 = fmaxf(mx0, __shfl_xor_sync(0xffffffffu, mx0, 1));
        mx0 = fmaxf(mx0, __shfl_xor_sync(0xffffffffu, mx0, 2));
        mx1 = fmaxf(mx1, __shfl_xor_sync(0xffffffffu, mx1, 1));
        mx1 = fmaxf(mx1, __shfl_xor_sync(0xffffffffu, mx1, 2));

        const float m0n = fmaxf(m0, mx0);
        const float m1n = fmaxf(m1, mx1);
        const float c0 = exp2f(m0 - m0n);
        const float c1 = exp2f(m1 - m1n);
        m0 = m0n; m1 = m1n;
        l0 *= c0;  l1 *= c1;
        #pragma unroll
        for (int nt = 0; nt < 8; nt++) {
            o[nt][0] *= c0; o[nt][1] *= c0;
            o[nt][2] *= c1; o[nt][3] *= c1;
        }

        uint32_t ph[8][2];
        #pragma unroll
        for (int nt = 0; nt < 8; nt++) {
            ph[nt][0] = ex2_h2(s[nt][0] - m0, s[nt][1] - m0);
            ph[nt][1] = ex2_h2(s[nt][2] - m1, s[nt][3] - m1);
            const float2 f0 = __half22float2(*(__half2*)&ph[nt][0]);
            const float2 f1 = __half22float2(*(__half2*)&ph[nt][1]);
            l0 += f0.x + f0.y;
            l1 += f1.x + f1.y;
        }

        // ---- O += P V (ph IS the A-fragment) ----
        const uint32_t vsl = ksb + FTILE;
        #pragma unroll
        for (int kk = 0; kk < 4; kk++) {
            uint32_t pa[4];
            pa[0] = ph[2 * kk][0];
            pa[1] = ph[2 * kk][1];
            pa[2] = ph[2 * kk + 1][0];
            pa[3] = ph[2 * kk + 1][1];
            const uint32_t vaddr0 = vsl + (kk * 16 + vrow) * FROWB + voff;
            #pragma unroll
            for (int j = 0; j < 4; j++) {
                uint32_t v0, v1, v2, v3;
                ldsm4t(v0, v1, v2, v3, vaddr0 + j * 32);
                mma_f16(o[2 * j],     pa, v0, v1);
                mma_f16(o[2 * j + 1], pa, v2, v3);
            }
        }
    }

    // ---- finalize ----
    l0 += __shfl_xor_sync(0xffffffffu, l0, 1);
    l0 += __shfl_xor_sync(0xffffffffu, l0, 2);
    l1 += __shfl_xor_sync(0xffffffffu, l1, 1);
    l1 += __shfl_xor_sync(0xffffffffu, l1, 2);
    const float i0 = 1.0f / l0;
    const float i1 = 1.0f / l1;

    const int row0 = qb * 128 + wm + lr;
    uint32_t* op0 = (uint32_t*)(Oh + base + (size_t)row0 * EMB);
    uint32_t* op1 = (uint32_t*)(Oh + base + (size_t)(row0 + 8) * EMB);
    #pragma unroll
    for (int ntd = 0; ntd < 8; ntd++) {
        const int colw = ntd * 4 + lc;
        op0[colw] = pack_h2(o[ntd][0] * i0, o[ntd][1] * i0);
        op1[colw] = pack_h2(o[ntd][2] * i1, o[ntd][3] * i1);
    }
}

// ---------------------------------------------------------------------------
extern "C" void kernel_launch(void* const* d_in, const int* in_sizes, int n_in,
                              void* d_out, int out_size)
{
    const float* x   = (const float*)d_in[0];
    const float* Wk  = (const float*)d_in[1];
    const float* Wq  = (const float*)d_in[2];
    const float* Wv  = (const float*)d_in[3];
    const float* Wo  = (const float*)d_in[4];
    const float* bo  = (const float*)d_in[5];
    const float* kg  = (const float*)d_in[6];
    const float* kb  = (const float*)d_in[7];
    const float* qg  = (const float*)d_in[8];
    const float* qb  = (const float*)d_in[9];
    float* out = (float*)d_out;

    float* sbase = nullptr;
    cudaGetSymbolAddress((void**)&sbase, g_scratch);
    const size_t MB1 = 1024ull * 1024ull;
    __half* xh  = (__half*)(sbase);
    __half* wkh = (__half*)(sbase + 4 * MB1);
    __half* wqh = (__half*)(sbase + 4 * MB1 + MB1 / 2);
    __half* wvh = (__half*)(sbase + 5 * MB1);
    __half* woh = (__half*)(sbase + 5 * MB1 + MB1 / 2);
    __half* gkh = (__half*)(sbase + 6 * MB1);
    __half* gqh = (__half*)(sbase + 10 * MB1);
    __half* gvh = (__half*)(sbase + 14 * MB1);
    __half* gyh = (__half*)(sbase + 18 * MB1);

    const float SCALE  = 0.17677669529663687f;           // 1024^(-1/4)
    const float SCALEQ = SCALE * 1.4426950408889634f;    // fold log2(e) into Q

    cudaFuncSetAttribute(gemm_qkv,
                         cudaFuncAttributeMaxDynamicSharedMemorySize, GEMM_SMEM);
    cudaFuncSetAttribute(gemm_f16,
                         cudaFuncAttributeMaxDynamicSharedMemorySize, GEMM_SMEM);

    conv_all<<<2048, 256>>>(x, Wk, Wq, Wv, Wo, xh, wkh, wqh, wvh, woh);

    dim3 qkvGrid(3 * EMB / 128, MTOK / 128);   // (24, 64)
    gemm_qkv<<<qkvGrid, 256, GEMM_SMEM>>>(xh, wkh, wqh, wvh, gkh, gqh, gvh);

    ln_kq<<<2 * NSEG / 8, 256>>>(gkh, gqh, kg, kb, qg, qb, SCALE, SCALEQ);

    dim3 attnGrid(SEQ / 128, HEADS, BATCH);    // (16, 16, 4)
    flash_attn2<<<attnGrid, 256>>>(gqh, gkh, gvh, gyh);

    dim3 gemmGrid(EMB / 128, MTOK / 128);      // (8, 64)
    gemm_f16<<<gemmGrid, 256, GEMM_SMEM>>>(gyh, woh, bo, out, MTOK, EMB, EMB);
}

// round 11
// speedup vs baseline: 8.4403x; 1.0816x over previous
#include <cuda_runtime.h>
#include <cuda_fp16.h>
#include <math.h>
#include <stdint.h>

#define EMB   1024
#define HEADS 16
#define HSZ   64
#define BATCH 4
#define SEQ   2048
#define MTOK  (BATCH * SEQ)   // 8192 token rows

// scratch floats: xh(4M) wk/wq/wv/wo(4x.5M) gkh gqh gvh gyh(4x4M) = 22M floats
__device__ float g_scratch[22ull * 1024 * 1024];

__device__ __forceinline__ void mma_f16(float* c, const uint32_t* a,
                                        uint32_t b0, uint32_t b1) {
    asm volatile(
        "mma.sync.aligned.m16n8k16.row.col.f32.f16.f16.f32 "
        "{%0,%1,%2,%3}, {%4,%5,%6,%7}, {%8,%9}, {%0,%1,%2,%3};\n"
        : "+f"(c[0]), "+f"(c[1]), "+f"(c[2]), "+f"(c[3])
        : "r"(a[0]), "r"(a[1]), "r"(a[2]), "r"(a[3]), "r"(b0), "r"(b1));
}
__device__ __forceinline__ void cp_async16(uint32_t saddr, const void* gaddr) {
    asm volatile("cp.async.cg.shared.global [%0], [%1], 16;\n"
                 :: "r"(saddr), "l"(gaddr));
}
__device__ __forceinline__ void cp_commit() {
    asm volatile("cp.async.commit_group;\n");
}
template <int N>
__device__ __forceinline__ void cp_wait() {
    asm volatile("cp.async.wait_group %0;\n" :: "n"(N));
}
__device__ __forceinline__ uint32_t smem_u32(const void* p) {
    uint32_t a;
    asm("{ .reg .u64 t; cvta.to.shared.u64 t, %1; cvt.u32.u64 %0, t; }"
        : "=r"(a) : "l"(p));
    return a;
}
__device__ __forceinline__ uint32_t pack_h2(float a, float b) {
    __half2 h = __floats2half2_rn(a, b);
    return *(uint32_t*)&h;
}
// packed fp16 exp2: 2 elements per MUFU op; output is a ready mma fragment
__device__ __forceinline__ uint32_t ex2_h2(float a, float b) {
    uint32_t h = pack_h2(a, b);
    uint32_t r;
    asm("ex2.approx.f16x2 %0, %1;" : "=r"(r) : "r"(h));
    return r;
}
__device__ __forceinline__ void ldsm4(uint32_t& r0, uint32_t& r1,
                                      uint32_t& r2, uint32_t& r3, uint32_t a) {
    asm volatile("ldmatrix.sync.aligned.m8n8.x4.shared.b16 {%0,%1,%2,%3}, [%4];"
                 : "=r"(r0), "=r"(r1), "=r"(r2), "=r"(r3) : "r"(a));
}
__device__ __forceinline__ void ldsm4t(uint32_t& r0, uint32_t& r1,
                                       uint32_t& r2, uint32_t& r3, uint32_t a) {
    asm volatile("ldmatrix.sync.aligned.m8n8.x4.trans.shared.b16 {%0,%1,%2,%3}, [%4];"
                 : "=r"(r0), "=r"(r1), "=r"(r2), "=r"(r3) : "r"(a));
}

// ---------------------------------------------------------------------------
// One-shot fp32 -> fp16 convert of x + all 4 weights (single launch).
// ---------------------------------------------------------------------------
#define X4  (MTOK * EMB / 4)          // 2097152
#define W4  (EMB * EMB / 4)           // 262144

__global__ __launch_bounds__(256)
void conv_all(const float* __restrict__ x,  const float* __restrict__ Wk,
              const float* __restrict__ Wq, const float* __restrict__ Wv,
              const float* __restrict__ Wo,
              __half* __restrict__ xh,  __half* __restrict__ wkh,
              __half* __restrict__ wqh, __half* __restrict__ wvh,
              __half* __restrict__ woh)
{
    const int total = X4 + 4 * W4;
    int i = blockIdx.x * 256 + threadIdx.x;
    const int stride = gridDim.x * 256;
    for (; i < total; i += stride) {
        const float* src; __half* dst; int off;
        if (i < X4) { src = x; dst = xh; off = i; }
        else {
            const int j = i - X4;
            const int w = j >> 18;
            off = j & (W4 - 1);
            src = (w == 0) ? Wk : (w == 1) ? Wq : (w == 2) ? Wv : Wo;
            dst = (w == 0) ? wkh : (w == 1) ? wqh : (w == 2) ? wvh : woh;
        }
        float4 v = ((const float4*)src)[off];
        uint2 o;
        o.x = pack_h2(v.x, v.y);
        o.y = pack_h2(v.z, v.w);
        ((uint2*)dst)[off] = o;
    }
}

// ---------------------------------------------------------------------------
// FP16 GEMM core (fp32 accumulate). 128x128 tile, BK=32, 8 warps, m16n8k16,
// 4-stage cp.async, fragments via ldmatrix.x4.
// ---------------------------------------------------------------------------
#define GSTAGES 4
#define BKH     32
#define ROWB    80
#define STG_B   (128 * ROWB)
#define GEMM_SMEM (GSTAGES * 2 * STG_B) // 81920 B

#define GFILL(stg, kc) do {                                                  \
    _Pragma("unroll")                                                        \
    for (int i_ = 0; i_ < 4; i_++) {                                         \
        const int idx_ = tid + i_ * 256;                                     \
        const int op_  = idx_ >> 9;                                          \
        const int r_   = (idx_ & 511) >> 2;                                  \
        const int q_   = idx_ & 3;                                           \
        const __half* g_ = (op_ ? B + (size_t)(bn + r_) * K                  \
                                : A + (size_t)(bm + r_) * K)                 \
                           + (kc) * BKH + q_ * 8;                            \
        cp_async16(data + (stg) * 2 * STG_B + op_ * STG_B                    \
                   + r_ * ROWB + q_ * 16, g_);                               \
    }                                                                        \
} while (0)

#define GEMM_BODY                                                             \
    extern __shared__ char dyn_smem[];                                        \
    const uint32_t data = smem_u32(dyn_smem);                                 \
    const int lane = tid & 31;                                                \
    const int wid  = tid >> 5;                                                \
    const int wm   = (wid >> 2) * 64;                                         \
    const int wn   = (wid & 3) * 32;                                          \
    const int lr   = lane >> 2;                                               \
    const int lc   = lane & 3;                                                \
    const uint32_t arow = ((lane >> 3) & 1) * 8 + (lane & 7);                 \
    const uint32_t achk = (lane >> 4) * 16;                                   \
    uint32_t aoff[4], boff[4];                                                \
    _Pragma("unroll")                                                         \
    for (int mt = 0; mt < 4; mt++)                                            \
        aoff[mt] = (wm + mt * 16 + arow) * ROWB + achk;                       \
    _Pragma("unroll")                                                         \
    for (int nt = 0; nt < 4; nt++)                                            \
        boff[nt] = (wn + nt * 8 + (lane & 7)) * ROWB + (lane >> 3) * 16;      \
    float acc[4][4][4];                                                       \
    _Pragma("unroll")                                                         \
    for (int i = 0; i < 4; i++)                                               \
        _Pragma("unroll")                                                     \
        for (int j = 0; j < 4; j++)                                           \
            _Pragma("unroll")                                                 \
            for (int r = 0; r < 4; r++) acc[i][j][r] = 0.0f;                  \
    _Pragma("unroll")                                                         \
    for (int s = 0; s < GSTAGES - 1; s++) { GFILL(s, s); cp_commit(); }       \
    const int nchunk = K / BKH;                                               \
    for (int it = 0; it < nchunk; it++) {                                     \
        cp_wait<GSTAGES - 2>();                                               \
        __syncthreads();                                                      \
        const int nxt = it + GSTAGES - 1;                                     \
        if (nxt < nchunk) GFILL(nxt % GSTAGES, nxt);                          \
        cp_commit();                                                          \
        const uint32_t asb = data + (it % GSTAGES) * 2 * STG_B;               \
        const uint32_t bsb = asb + STG_B;                                     \
        uint32_t bfr[4][4];                                                   \
        _Pragma("unroll")                                                     \
        for (int nt = 0; nt < 4; nt++)                                        \
            ldsm4(bfr[nt][0], bfr[nt][1], bfr[nt][2], bfr[nt][3],             \
                  bsb + boff[nt]);                                            \
        _Pragma("unroll")                                                     \
        for (int ks = 0; ks < 2; ks++) {                                      \
            uint32_t afr[4][4];                                               \
            _Pragma("unroll")                                                 \
            for (int mt = 0; mt < 4; mt++)                                    \
                ldsm4(afr[mt][0], afr[mt][1], afr[mt][2], afr[mt][3],         \
                      asb + aoff[mt] + ks * 32);                              \
            _Pragma("unroll")                                                 \
            for (int mt = 0; mt < 4; mt++)                                    \
                _Pragma("unroll")                                             \
                for (int nt = 0; nt < 4; nt++)                                \
                    mma_f16(acc[mt][nt], afr[mt],                             \
                            bfr[nt][2 * ks], bfr[nt][2 * ks + 1]);            \
        }                                                                     \
    }

// ---- fused QKV GEMM with per-head LayerNorm folded into the epilogue ----
// sec 0 = K (LN, scaleK), sec 1 = Q (LN, scaleQ incl log2e), sec 2 = V (plain).
__global__ __launch_bounds__(256, 2)
void gemm_qkv(const __half* __restrict__ A,
              const __half* __restrict__ Wk2, const __half* __restrict__ Wq2,
              const __half* __restrict__ Wv2,
              __half* __restrict__ Ck, __half* __restrict__ Cq,
              __half* __restrict__ Cv,
              const float* __restrict__ kgv, const float* __restrict__ kbv,
              const float* __restrict__ qgv, const float* __restrict__ qbv,
              float scaleK, float scaleQ)
{
    const int tid = threadIdx.x;
    const int K = EMB, N = EMB;
    const int bm = blockIdx.y * 128;
    const int bn_raw = blockIdx.x * 128;
    const int sec = bn_raw >> 10;
    const int bn  = bn_raw & 1023;
    const __half* B = (sec == 0) ? Wk2 : (sec == 1) ? Wq2 : Wv2;
    __half* C       = (sec == 0) ? Ck  : (sec == 1) ? Cq  : Cv;

    GEMM_BODY

    if (sec < 2) {
        // ---- per-head LayerNorm over the 64-dim segment, fused ----
        const float* g  = (sec == 0) ? kgv : qgv;
        const float* bb = (sec == 0) ? kbv : qbv;
        const float scale = (sec == 0) ? scaleK : scaleQ;

        cp_wait<0>();
        __syncthreads();                    // stage buffers now reusable
        float2* part = (float2*)dyn_smem;   // [8 warps][64 rows]

        float ss[4][2], qq[4][2];
        #pragma unroll
        for (int mt = 0; mt < 4; mt++) {
            #pragma unroll
            for (int hf = 0; hf < 2; hf++) {
                float s = 0.f, q = 0.f;
                #pragma unroll
                for (int nt = 0; nt < 4; nt++) {
                    const float a0 = acc[mt][nt][2 * hf];
                    const float a1 = acc[mt][nt][2 * hf + 1];
                    s += a0 + a1;
                    q += a0 * a0 + a1 * a1;
                }
                s += __shfl_xor_sync(0xffffffffu, s, 1);
                s += __shfl_xor_sync(0xffffffffu, s, 2);
                q += __shfl_xor_sync(0xffffffffu, q, 1);
                q += __shfl_xor_sync(0xffffffffu, q, 2);
                ss[mt][hf] = s;
                qq[mt][hf] = q;
                if (lc == 0)
                    part[wid * 64 + mt * 16 + hf * 8 + lr] = make_float2(s, q);
            }
        }
        __syncthreads();

        float mean[4][2], rstd[4][2];
        #pragma unroll
        for (int mt = 0; mt < 4; mt++) {
            #pragma unroll
            for (int hf = 0; hf < 2; hf++) {
                const float2 pr = part[(wid ^ 1) * 64 + mt * 16 + hf * 8 + lr];
                const float S  = ss[mt][hf] + pr.x;
                const float Q2 = qq[mt][hf] + pr.y;
                const float mn = S * (1.0f / 64.0f);
                const float vr = Q2 * (1.0f / 64.0f) - mn * mn;
                mean[mt][hf] = mn;
                rstd[mt][hf] = rsqrtf(vr + 1e-5f);
            }
        }

        #pragma unroll
        for (int mt = 0; mt < 4; mt++) {
            const int row = bm + wm + mt * 16 + lr;
            const float mA = mean[mt][0], rA = rstd[mt][0];
            const float mB = mean[mt][1], rB = rstd[mt][1];
            #pragma unroll
            for (int nt = 0; nt < 4; nt++) {
                const int col  = bn + wn + nt * 8 + lc * 2;
                const int gdim = (wn + nt * 8 + lc * 2) & 63;
                const float g0 = g[gdim],  g1 = g[gdim + 1];
                const float b0 = bb[gdim], b1 = bb[gdim + 1];
                const float oA0 = ((acc[mt][nt][0] - mA) * rA * g0 + b0) * scale;
                const float oA1 = ((acc[mt][nt][1] - mA) * rA * g1 + b1) * scale;
                const float oB0 = ((acc[mt][nt][2] - mB) * rB * g0 + b0) * scale;
                const float oB1 = ((acc[mt][nt][3] - mB) * rB * g1 + b1) * scale;
                *(uint32_t*)(C + (size_t)row * N + col)       = pack_h2(oA0, oA1);
                *(uint32_t*)(C + (size_t)(row + 8) * N + col) = pack_h2(oB0, oB1);
            }
        }
    } else {
        #pragma unroll
        for (int mt = 0; mt < 4; mt++) {
            const int row = bm + wm + mt * 16 + lr;
            #pragma unroll
            for (int nt = 0; nt < 4; nt++) {
                const int col = bn + wn + nt * 8 + lc * 2;
                *(uint32_t*)(C + (size_t)row * N + col) =
                    pack_h2(acc[mt][nt][0], acc[mt][nt][1]);
                *(uint32_t*)(C + (size_t)(row + 8) * N + col) =
                    pack_h2(acc[mt][nt][2], acc[mt][nt][3]);
            }
        }
    }
}

// ---- output projection: fp32 out + bias ----
__global__ __launch_bounds__(256, 2)
void gemm_f16(const __half* __restrict__ A, const __half* __restrict__ B,
              const float* __restrict__ bias, float* __restrict__ C,
              int M, int N, int K)
{
    const int tid = threadIdx.x;
    const int bm  = blockIdx.y * 128;
    const int bn  = blockIdx.x * 128;

    GEMM_BODY

    #pragma unroll
    for (int mt = 0; mt < 4; mt++) {
        const int row = bm + wm + mt * 16 + lr;
        #pragma unroll
        for (int nt = 0; nt < 4; nt++) {
            const int col = bn + wn + nt * 8 + lc * 2;
            const float b0 = bias[col], b1 = bias[col + 1];
            *(float2*)(C + (size_t)row * N + col) =
                make_float2(acc[mt][nt][0] + b0, acc[mt][nt][1] + b1);
            *(float2*)(C + (size_t)(row + 8) * N + col) =
                make_float2(acc[mt][nt][2] + b0, acc[mt][nt][3] + b1);
        }
    }
}

// ---------------------------------------------------------------------------
// FP16 flash attention, BR=128 (8 warps x 16 rows), BC=64, D=64.
// 3-slot K/V ring, ldmatrix fragments, packed f16 exp2, exp2-domain softmax.
// Prefetch issued after S-mmas (tensor work starts immediately post-barrier).
// ---------------------------------------------------------------------------
#define FROWB 144                 // smem row: 64 halves + 8 pad
#define FTILE (64 * FROWB)        // 9216 B per operand tile

__global__ __launch_bounds__(256)
void flash_attn2(const __half* __restrict__ Q, const __half* __restrict__ K,
                 const __half* __restrict__ V, __half* __restrict__ Oh)
{
    __shared__ __align__(16) char kvbuf[3][2][FTILE];  // 55.3 KB

    const int qb = blockIdx.x;          // 128-row query tile
    const int h  = blockIdx.y;
    const int b  = blockIdx.z;
    const int tid  = threadIdx.x;
    const int lane = tid & 31;
    const int wid  = tid >> 5;
    const int wm   = wid * 16;
    const int lr   = lane >> 2;
    const int lc   = lane & 3;

    const size_t base = (size_t)b * SEQ * EMB + (size_t)h * HSZ;
    const __half* Qg = Q + base + (size_t)(qb * 128) * EMB;
    const __half* Kg = K + base;
    const __half* Vg = V + base;
    const uint32_t sbase = smem_u32(kvbuf);

    // ---- stage Q through slot0, extract A-frags via ldmatrix ----
    #pragma unroll
    for (int i = 0; i < 4; i++) {
        const int idx = tid + i * 256;
        const int r = idx >> 3, q = idx & 7;
        cp_async16(sbase + r * FROWB + q * 16, Qg + (size_t)r * EMB + q * 8);
    }
    cp_commit();
    cp_wait<0>();
    __syncthreads();

    const uint32_t qrow = wm + ((lane >> 3) & 1) * 8 + (lane & 7);
    const uint32_t qoff = ((lane >> 4) ? 16u : 0u);
    uint32_t qa[4][4];
    #pragma unroll
    for (int kk = 0; kk < 4; kk++)
        ldsm4(qa[kk][0], qa[kk][1], qa[kk][2], qa[kk][3],
              sbase + qrow * FROWB + kk * 32 + qoff);
    __syncthreads();

    #define AFILL(kt_, slot_) do {                                           \
        const uint32_t so_ = sbase + (slot_) * 2 * FTILE;                    \
        _Pragma("unroll")                                                    \
        for (int i_ = 0; i_ < 4; i_++) {                                     \
            const int idx_ = tid + i_ * 256;                                 \
            const int op_  = idx_ >> 9;                                      \
            const int r_   = (idx_ >> 3) & 63;                               \
            const int q_   = idx_ & 7;                                       \
            const __half* g_ = (op_ ? Vg : Kg)                               \
                + (size_t)((kt_) * 64 + r_) * EMB + q_ * 8;                  \
            cp_async16(so_ + op_ * FTILE + r_ * FROWB + q_ * 16, g_);        \
        }                                                                    \
    } while (0)

    AFILL(0, 0);
    cp_commit();
    AFILL(1, 1);
    cp_commit();

    float o[8][4];
    #pragma unroll
    for (int i = 0; i < 8; i++)
        #pragma unroll
        for (int j = 0; j < 4; j++) o[i][j] = 0.0f;
    float m0 = -INFINITY, m1 = -INFINITY, l0 = 0.0f, l1 = 0.0f;

    const uint32_t krow = (lane & 7);
    const uint32_t ktil = (lane >> 3) * 16;
    const uint32_t vrow = ((lane >> 3) & 1) * 8 + (lane & 7);
    const uint32_t voff = ((lane >> 4) ? 16u : 0u);
    const int lastkt = 2 * qb + 1;

    for (int kt = 0; kt <= lastkt; kt++) {
        const int slot = kt % 3;
        cp_wait<1>();
        __syncthreads();

        // ---- S = Q K^T (issued first so tensor pipe starts immediately) ----
        const uint32_t ksb = sbase + slot * 2 * FTILE;
        float s[8][4];
        #pragma unroll
        for (int nt = 0; nt < 8; nt++)
            #pragma unroll
            for (int j = 0; j < 4; j++) s[nt][j] = 0.0f;

        #pragma unroll
        for (int nt = 0; nt < 8; nt++) {
            const uint32_t abase = ksb + (nt * 8 + krow) * FROWB + ktil;
            #pragma unroll
            for (int hh = 0; hh < 2; hh++) {
                uint32_t b0, b1, b2, b3;
                ldsm4(b0, b1, b2, b3, abase + hh * 64);
                mma_f16(s[nt], qa[2 * hh],     b0, b1);
                mma_f16(s[nt], qa[2 * hh + 1], b2, b3);
            }
        }

        // prefetch tile kt+2 into slot (kt+2)%3 (readers finished at barrier)
        if (kt + 2 <= lastkt) AFILL(kt + 2, (kt + 2) % 3);
        cp_commit();

        // ---- causal mask (last two tiles only) ----
        if (kt >= 2 * qb) {
            const int rg = qb * 128 + wm + lr;
            #pragma unroll
            for (int nt = 0; nt < 8; nt++) {
                const int cg = kt * 64 + nt * 8 + 2 * lc;
                if (cg     > rg)     s[nt][0] = -1e30f;
                if (cg + 1 > rg)     s[nt][1] = -1e30f;
                if (cg     > rg + 8) s[nt][2] = -1e30f;
                if (cg + 1 > rg + 8) s[nt][3] = -1e30f;
            }
        }

        // ---- online softmax, exp2 domain, packed f16 exponentials ----
        float mx0 = -INFINITY, mx1 = -INFINITY;
        #pragma unroll
        for (int nt = 0; nt < 8; nt++) {
            mx0 = fmaxf(mx0, fmaxf(s[nt][0], s[nt][1]));
            mx1 = fmaxf(mx1, fmaxf(s[nt][2], s[nt][3]));
        }
        mx0 = fmaxf(mx0, __shfl_xor_sync(0xffffffffu, mx0, 1));
        mx0 = fmaxf(mx0, __shfl_xor_sync(0xffffffffu, mx0, 2));
        mx1 = fmaxf(mx1, __shfl_xor_sync(0xffffffffu, mx1, 1));
        mx1 = fmaxf(mx1, __shfl_xor_sync(0xffffffffu, mx1, 2));

        const float m0n = fmaxf(m0, mx0);
        const float m1n = fmaxf(m1, mx1);
        const float c0 = exp2f(m0 - m0n);
        const float c1 = exp2f(m1 - m1n);
        m0 = m0n; m1 = m1n;
        #pragma unroll
        for (int nt = 0; nt < 8; nt++) {
            o[nt][0] *= c0; o[nt][1] *= c0;
            o[nt][2] *= c1; o[nt][3] *= c1;
        }

        uint32_t ph[8][2];
        // two independent accumulation chains per row-group, merged once
        float la0 = 0.f, lb0 = 0.f, la1 = 0.f, lb1 = 0.f;
        #pragma unroll
        for (int nt = 0; nt < 8; nt++) {
            ph[nt][0] = ex2_h2(s[nt][0] - m0, s[nt][1] - m0);
            ph[nt][1] = ex2_h2(s[nt][2] - m1, s[nt][3] - m1);
            const float2 f0 = __half22float2(*(__half2*)&ph[nt][0]);
            const float2 f1 = __half22float2(*(__half2*)&ph[nt][1]);
            if (nt & 1) { lb0 += f0.x + f0.y; lb1 += f1.x + f1.y; }
            else        { la0 += f0.x + f0.y; la1 += f1.x + f1.y; }
        }
        l0 = l0 * c0 + (la0 + lb0);
        l1 = l1 * c1 + (la1 + lb1);

        // ---- O += P V (ph IS the A-fragment) ----
        const uint32_t vsl = ksb + FTILE;
        #pragma unroll
        for (int kk = 0; kk < 4; kk++) {
            uint32_t pa[4];
            pa[0] = ph[2 * kk][0];
            pa[1] = ph[2 * kk][1];
            pa[2] = ph[2 * kk + 1][0];
            pa[3] = ph[2 * kk + 1][1];
            const uint32_t vaddr0 = vsl + (kk * 16 + vrow) * FROWB + voff;
            #pragma unroll
            for (int j = 0; j < 4; j++) {
                uint32_t v0, v1, v2, v3;
                ldsm4t(v0, v1, v2, v3, vaddr0 + j * 32);
                mma_f16(o[2 * j],     pa, v0, v1);
                mma_f16(o[2 * j + 1], pa, v2, v3);
            }
        }
    }

    // ---- finalize ----
    l0 += __shfl_xor_sync(0xffffffffu, l0, 1);
    l0 += __shfl_xor_sync(0xffffffffu, l0, 2);
    l1 += __shfl_xor_sync(0xffffffffu, l1, 1);
    l1 += __shfl_xor_sync(0xffffffffu, l1, 2);
    const float i0 = 1.0f / l0;
    const float i1 = 1.0f / l1;

    const int row0 = qb * 128 + wm + lr;
    uint32_t* op0 = (uint32_t*)(Oh + base + (size_t)row0 * EMB);
    uint32_t* op1 = (uint32_t*)(Oh + base + (size_t)(row0 + 8) * EMB);
    #pragma unroll
    for (int ntd = 0; ntd < 8; ntd++) {
        const int colw = ntd * 4 + lc;
        op0[colw] = pack_h2(o[ntd][0] * i0, o[ntd][1] * i0);
        op1[colw] = pack_h2(o[ntd][2] * i1, o[ntd][3] * i1);
    }
}

// ---------------------------------------------------------------------------
extern "C" void kernel_launch(void* const* d_in, const int* in_sizes, int n_in,
                              void* d_out, int out_size)
{
    const float* x   = (const float*)d_in[0];
    const float* Wk  = (const float*)d_in[1];
    const float* Wq  = (const float*)d_in[2];
    const float* Wv  = (const float*)d_in[3];
    const float* Wo  = (const float*)d_in[4];
    const float* bo  = (const float*)d_in[5];
    const float* kg  = (const float*)d_in[6];
    const float* kb  = (const float*)d_in[7];
    const float* qg  = (const float*)d_in[8];
    const float* qb  = (const float*)d_in[9];
    float* out = (float*)d_out;

    float* sbase = nullptr;
    cudaGetSymbolAddress((void**)&sbase, g_scratch);
    const size_t MB1 = 1024ull * 1024ull;
    __half* xh  = (__half*)(sbase);
    __half* wkh = (__half*)(sbase + 4 * MB1);
    __half* wqh = (__half*)(sbase + 4 * MB1 + MB1 / 2);
    __half* wvh = (__half*)(sbase + 5 * MB1);
    __half* woh = (__half*)(sbase + 5 * MB1 + MB1 / 2);
    __half* gkh = (__half*)(sbase + 6 * MB1);
    __half* gqh = (__half*)(sbase + 10 * MB1);
    __half* gvh = (__half*)(sbase + 14 * MB1);
    __half* gyh = (__half*)(sbase + 18 * MB1);

    const float SCALE  = 0.17677669529663687f;           // 1024^(-1/4)
    const float SCALEQ = SCALE * 1.4426950408889634f;    // fold log2(e) into Q

    cudaFuncSetAttribute(gemm_qkv,
                         cudaFuncAttributeMaxDynamicSharedMemorySize, GEMM_SMEM);
    cudaFuncSetAttribute(gemm_f16,
                         cudaFuncAttributeMaxDynamicSharedMemorySize, GEMM_SMEM);

    conv_all<<<2048, 256>>>(x, Wk, Wq, Wv, Wo, xh, wkh, wqh, wvh, woh);

    dim3 qkvGrid(3 * EMB / 128, MTOK / 128);   // (24, 64)
    gemm_qkv<<<qkvGrid, 256, GEMM_SMEM>>>(xh, wkh, wqh, wvh, gkh, gqh, gvh,
                                          kg, kb, qg, qb, SCALE, SCALEQ);

    dim3 attnGrid(SEQ / 128, HEADS, BATCH);    // (16, 16, 4)
    flash_attn2<<<attnGrid, 256>>>(gqh, gkh, gvh, gyh);

    dim3 gemmGrid(EMB / 128, MTOK / 128);      // (8, 64)
    gemm_f16<<<gemmGrid, 256, GEMM_SMEM>>>(gyh, woh, bo, out, MTOK, EMB, EMB);
}